// round 1
// baseline (speedup 1.0000x reference)
#include <cuda_runtime.h>
#include <math.h>

// Problem constants
#define T_SEQ  4096
#define D_MODEL 1024
#define NH     16
#define NKV    4
#define HD     64
#define D_FF   4096

// ---------------- scratch (device globals; no allocation allowed) ----------
__device__ float g_q[T_SEQ * D_MODEL];          // 16 MB
__device__ float g_k[T_SEQ * NKV * HD];         // 4 MB
__device__ float g_v[T_SEQ * NKV * HD];         // 4 MB
__device__ float g_attn[T_SEQ * D_MODEL];       // 16 MB
__device__ float g_h1[(size_t)T_SEQ * D_FF];    // 64 MB
__device__ float g_cos[T_SEQ * 32];
__device__ float g_sin[T_SEQ * 32];

// ---------------- RoPE table (replicates reference fp32 path) --------------
__global__ void rope_table_kernel() {
    int t = blockIdx.x, i = threadIdx.x;            // i in [0,32)
    float inv = 1.0f / powf(10000.0f, (float)(2 * i) / 64.0f);
    float ang = (float)t * inv;
    g_cos[t * 32 + i] = cosf(ang);
    g_sin[t * 32 + i] = sinf(ang);
}

__global__ void rope_apply_kernel(float* __restrict__ x, int nh) {
    int t = blockIdx.x;
    int h = threadIdx.x >> 5;
    int i = threadIdx.x & 31;
    float c = g_cos[t * 32 + i];
    float s = g_sin[t * 32 + i];
    float* p = x + (size_t)t * nh * HD + h * HD;
    float x1 = p[i], x2 = p[i + 32];
    p[i]      = x1 * c - x2 * s;
    p[i + 32] = x2 * c + x1 * s;
}

// ---------------- tiled fp32 GEMM: C[M,N] = A[M,K] @ B[K,N] ---------------
// BM=BN=128, BK=8, 256 threads, 8x8 register tile per thread.
template <int SILU>
__global__ void __launch_bounds__(256) sgemm_kernel(
    const float* __restrict__ A, const float* __restrict__ B,
    float* __restrict__ C, int M, int N, int K)
{
    __shared__ float As[8][128];
    __shared__ float Bs[8][128];

    int tid = threadIdx.x;
    int tx  = tid & 15;       // 0..15 -> output cols
    int ty  = tid >> 4;       // 0..15 -> output rows
    int rowBase = blockIdx.y * 128;
    int colBase = blockIdx.x * 128;

    float acc[8][8];
#pragma unroll
    for (int i = 0; i < 8; i++)
#pragma unroll
        for (int j = 0; j < 8; j++) acc[i][j] = 0.0f;

    int arow = tid >> 1;           // 0..127
    int acol = (tid & 1) * 4;      // 0 or 4
    int brow = tid >> 5;           // 0..7
    int bcol = (tid & 31) * 4;     // 0..124

    const float* Aptr = A + (size_t)(rowBase + arow) * K + acol;
    const float* Bptr = B + (size_t)brow * N + colBase + bcol;

    for (int k0 = 0; k0 < K; k0 += 8) {
        float4 av = *(const float4*)(Aptr + k0);
        float4 bv = *(const float4*)(Bptr + (size_t)k0 * N);
        As[acol + 0][arow] = av.x;
        As[acol + 1][arow] = av.y;
        As[acol + 2][arow] = av.z;
        As[acol + 3][arow] = av.w;
        *(float4*)&Bs[brow][bcol] = bv;
        __syncthreads();

#pragma unroll
        for (int kk = 0; kk < 8; kk++) {
            float a[8], b[8];
            *(float4*)(a)     = *(float4*)&As[kk][ty * 8];
            *(float4*)(a + 4) = *(float4*)&As[kk][ty * 8 + 4];
            *(float4*)(b)     = *(float4*)&Bs[kk][tx * 8];
            *(float4*)(b + 4) = *(float4*)&Bs[kk][tx * 8 + 4];
#pragma unroll
            for (int i = 0; i < 8; i++)
#pragma unroll
                for (int j = 0; j < 8; j++)
                    acc[i][j] += a[i] * b[j];
        }
        __syncthreads();
    }

#pragma unroll
    for (int i = 0; i < 8; i++) {
        size_t rowOff = (size_t)(rowBase + ty * 8 + i) * N + colBase + tx * 8;
#pragma unroll
        for (int j4 = 0; j4 < 8; j4 += 4) {
            float4 v;
            v.x = acc[i][j4 + 0];
            v.y = acc[i][j4 + 1];
            v.z = acc[i][j4 + 2];
            v.w = acc[i][j4 + 3];
            if (SILU) {
                v.x = v.x / (1.0f + expf(-v.x));
                v.y = v.y / (1.0f + expf(-v.y));
                v.z = v.z / (1.0f + expf(-v.z));
                v.w = v.w / (1.0f + expf(-v.w));
            }
            *(float4*)&C[rowOff + j4] = v;
        }
    }
}

// ---------------- flash attention (causal, GQA 16q/4kv, d=64) -------------
// BM=BN=64, 256 threads, 4x4 micro-tiles. smem: Qs,Ks,Vs,Ps (64x64 each).
// Ks is XOR-swizzled so the S-GEMM column reads are bank-conflict-free.
__global__ void __launch_bounds__(256) attn_kernel(
    const float* __restrict__ q, const float* __restrict__ k,
    const float* __restrict__ v, float* __restrict__ o)
{
    extern __shared__ float sm[];
    float* Qs = sm;
    float* Ks = sm + 4096;
    float* Vs = sm + 8192;
    float* Ps = sm + 12288;

    int qb  = gridDim.x - 1 - blockIdx.x;   // heavy blocks first
    int h   = blockIdx.y;
    int kvh = h >> 2;
    int tid = threadIdx.x;
    int tx  = tid & 15;
    int ty  = tid >> 4;

    // load Q tile (rows qb*64.., head h)
#pragma unroll
    for (int it = 0; it < 4; it++) {
        int idx = tid + 256 * it;
        int r = idx >> 4, d4 = (idx & 15) << 2;
        *(float4*)&Qs[r * 64 + d4] =
            *(const float4*)&q[(size_t)(qb * 64 + r) * D_MODEL + h * HD + d4];
    }

    float m[4], l[4], acc[4][4];
#pragma unroll
    for (int i = 0; i < 4; i++) {
        m[i] = -1e30f;
        l[i] = 0.0f;
#pragma unroll
        for (int j = 0; j < 4; j++) acc[i][j] = 0.0f;
    }

    for (int kb = 0; kb <= qb; kb++) {
        __syncthreads();   // prev-iter smem reads done
#pragma unroll
        for (int it = 0; it < 4; it++) {
            int idx = tid + 256 * it;
            int c = idx >> 4, d4 = (idx & 15) << 2;
            int sw = d4 ^ (((c >> 2) & 15) << 2);
            size_t goff = (size_t)(kb * 64 + c) * (NKV * HD) + kvh * HD + d4;
            *(float4*)&Ks[c * 64 + sw] = *(const float4*)&k[goff];
            *(float4*)&Vs[c * 64 + d4] = *(const float4*)&v[goff];
        }
        __syncthreads();

        // S = Q @ K^T  (4x4 per thread)
        float s[4][4];
#pragma unroll
        for (int i = 0; i < 4; i++)
#pragma unroll
            for (int j = 0; j < 4; j++) s[i][j] = 0.0f;

#pragma unroll
        for (int d4 = 0; d4 < 64; d4 += 4) {
            float4 qv[4], kv[4];
#pragma unroll
            for (int i = 0; i < 4; i++)
                qv[i] = *(float4*)&Qs[(ty * 4 + i) * 64 + d4];
#pragma unroll
            for (int j = 0; j < 4; j++)
                kv[j] = *(float4*)&Ks[(tx * 4 + j) * 64 + (d4 ^ (tx << 2))];
#pragma unroll
            for (int i = 0; i < 4; i++)
#pragma unroll
                for (int j = 0; j < 4; j++)
                    s[i][j] += qv[i].x * kv[j].x + qv[i].y * kv[j].y +
                               qv[i].z * kv[j].z + qv[i].w * kv[j].w;
        }

        // scale + causal mask (only diagonal block can mask)
#pragma unroll
        for (int i = 0; i < 4; i++)
#pragma unroll
            for (int j = 0; j < 4; j++) s[i][j] *= 0.125f;
        if (kb == qb) {
#pragma unroll
            for (int i = 0; i < 4; i++)
#pragma unroll
                for (int j = 0; j < 4; j++)
                    if (tx * 4 + j > ty * 4 + i) s[i][j] = -INFINITY;
        }

        // online softmax update (row groups = 16 lanes sharing ty)
#pragma unroll
        for (int i = 0; i < 4; i++) {
            float tm = s[i][0];
            tm = fmaxf(tm, s[i][1]);
            tm = fmaxf(tm, s[i][2]);
            tm = fmaxf(tm, s[i][3]);
#pragma unroll
            for (int off = 8; off >= 1; off >>= 1)
                tm = fmaxf(tm, __shfl_xor_sync(0xffffffffu, tm, off));
            float mn = fmaxf(m[i], tm);
            float corr = __expf(m[i] - mn);
            float rs = 0.0f;
#pragma unroll
            for (int j = 0; j < 4; j++) {
                float p = __expf(s[i][j] - mn);
                s[i][j] = p;
                rs += p;
            }
#pragma unroll
            for (int off = 8; off >= 1; off >>= 1)
                rs += __shfl_xor_sync(0xffffffffu, rs, off);
            l[i] = l[i] * corr + rs;
            m[i] = mn;
#pragma unroll
            for (int j = 0; j < 4; j++) acc[i][j] *= corr;
        }

        // store P
#pragma unroll
        for (int i = 0; i < 4; i++) {
            float4 pv;
            pv.x = s[i][0]; pv.y = s[i][1]; pv.z = s[i][2]; pv.w = s[i][3];
            *(float4*)&Ps[(ty * 4 + i) * 64 + tx * 4] = pv;
        }
        __syncthreads();

        // O += P @ V
#pragma unroll
        for (int k4 = 0; k4 < 64; k4 += 4) {
            float4 pv[4], vv[4];
#pragma unroll
            for (int i = 0; i < 4; i++)
                pv[i] = *(float4*)&Ps[(ty * 4 + i) * 64 + k4];
#pragma unroll
            for (int lsub = 0; lsub < 4; lsub++)
                vv[lsub] = *(float4*)&Vs[(k4 + lsub) * 64 + tx * 4];
#pragma unroll
            for (int i = 0; i < 4; i++) {
                acc[i][0] += pv[i].x * vv[0].x + pv[i].y * vv[1].x +
                             pv[i].z * vv[2].x + pv[i].w * vv[3].x;
                acc[i][1] += pv[i].x * vv[0].y + pv[i].y * vv[1].y +
                             pv[i].z * vv[2].y + pv[i].w * vv[3].y;
                acc[i][2] += pv[i].x * vv[0].z + pv[i].y * vv[1].z +
                             pv[i].z * vv[2].z + pv[i].w * vv[3].z;
                acc[i][3] += pv[i].x * vv[0].w + pv[i].y * vv[1].w +
                             pv[i].z * vv[2].w + pv[i].w * vv[3].w;
            }
        }
    }

    // finalize: divide by l and write [t, h*64+e]
#pragma unroll
    for (int i = 0; i < 4; i++) {
        float inv = 1.0f / l[i];
        float4 r;
        r.x = acc[i][0] * inv;
        r.y = acc[i][1] * inv;
        r.z = acc[i][2] * inv;
        r.w = acc[i][3] * inv;
        *(float4*)&o[(size_t)(qb * 64 + ty * 4 + i) * D_MODEL + h * HD + tx * 4] = r;
    }
}

// ---------------- launch ---------------------------------------------------
extern "C" void kernel_launch(void* const* d_in, const int* in_sizes, int n_in,
                              void* d_out, int out_size)
{
    const float* X  = (const float*)d_in[0];   // query [4096,1024]
    const float* Wq = (const float*)d_in[1];   // [1024,1024]
    const float* Wk = (const float*)d_in[2];   // [1024,256]
    const float* Wv = (const float*)d_in[3];   // [1024,256]
    const float* W1 = (const float*)d_in[4];   // [1024,4096]
    const float* W2 = (const float*)d_in[5];   // [4096,1024]
    float* out = (float*)d_out;

    float *gq, *gk, *gv, *ga, *gh;
    cudaGetSymbolAddress((void**)&gq, g_q);
    cudaGetSymbolAddress((void**)&gk, g_k);
    cudaGetSymbolAddress((void**)&gv, g_v);
    cudaGetSymbolAddress((void**)&ga, g_attn);
    cudaGetSymbolAddress((void**)&gh, g_h1);

    cudaFuncSetAttribute(attn_kernel,
                         cudaFuncAttributeMaxDynamicSharedMemorySize, 65536);

    rope_table_kernel<<<T_SEQ, 32>>>();

    // QKV projections
    sgemm_kernel<0><<<dim3(D_MODEL / 128, T_SEQ / 128), 256>>>(
        X, Wq, gq, T_SEQ, D_MODEL, D_MODEL);
    sgemm_kernel<0><<<dim3((NKV * HD) / 128, T_SEQ / 128), 256>>>(
        X, Wk, gk, T_SEQ, NKV * HD, D_MODEL);
    sgemm_kernel<0><<<dim3((NKV * HD) / 128, T_SEQ / 128), 256>>>(
        X, Wv, gv, T_SEQ, NKV * HD, D_MODEL);

    // RoPE on q and k
    rope_apply_kernel<<<T_SEQ, NH * 32>>>(gq, NH);
    rope_apply_kernel<<<T_SEQ, NKV * 32>>>(gk, NKV);

    // causal flash attention
    attn_kernel<<<dim3(T_SEQ / 64, NH), 256, 65536>>>(gq, gk, gv, ga);

    // MLP
    sgemm_kernel<1><<<dim3(D_FF / 128, T_SEQ / 128), 256>>>(
        ga, W1, gh, T_SEQ, D_FF, D_MODEL);
    sgemm_kernel<0><<<dim3(D_MODEL / 128, T_SEQ / 128), 256>>>(
        gh, W2, out, T_SEQ, D_MODEL, D_FF);
}

// round 2
// speedup vs baseline: 1.1354x; 1.1354x over previous
#include <cuda_runtime.h>
#include <math.h>
#include <stdint.h>

// Problem constants
#define T_SEQ  4096
#define D_MODEL 1024
#define NH     16
#define NKV    4
#define HD     64
#define D_FF   4096

// ---------------- scratch (device globals; no allocation allowed) ----------
__device__ float g_q[T_SEQ * D_MODEL];          // 16 MB
__device__ float g_k[T_SEQ * NKV * HD];         // 4 MB
__device__ float g_v[T_SEQ * NKV * HD];         // 4 MB
__device__ float g_attn[T_SEQ * D_MODEL];       // 16 MB
__device__ float g_h1[(size_t)T_SEQ * D_FF];    // 64 MB
__device__ float g_cos[T_SEQ * 32];
__device__ float g_sin[T_SEQ * 32];

// ---------------- RoPE table (replicates reference fp32 path) --------------
__global__ void rope_table_kernel() {
    int t = blockIdx.x, i = threadIdx.x;            // i in [0,32)
    float inv = 1.0f / powf(10000.0f, (float)(2 * i) / 64.0f);
    float ang = (float)t * inv;
    g_cos[t * 32 + i] = cosf(ang);
    g_sin[t * 32 + i] = sinf(ang);
}

__global__ void rope_apply_kernel(float* __restrict__ x, int nh) {
    int t = blockIdx.x;
    int h = threadIdx.x >> 5;
    int i = threadIdx.x & 31;
    float c = g_cos[t * 32 + i];
    float s = g_sin[t * 32 + i];
    float* p = x + (size_t)t * nh * HD + h * HD;
    float x1 = p[i], x2 = p[i + 32];
    p[i]      = x1 * c - x2 * s;
    p[i + 32] = x2 * c + x1 * s;
}

// ---------------- tf32 tensor-core helpers ---------------------------------
__device__ __forceinline__ uint32_t f2tf32(float x) {
    uint32_t r;
    asm("cvt.rna.tf32.f32 %0, %1;" : "=r"(r) : "f"(x));
    return r;
}

__device__ __forceinline__ void mma_tf32(float* d, const uint32_t* a,
                                         const uint32_t* b, const float* c) {
    asm volatile(
        "mma.sync.aligned.m16n8k8.row.col.f32.tf32.tf32.f32 "
        "{%0,%1,%2,%3}, {%4,%5,%6,%7}, {%8,%9}, {%10,%11,%12,%13};"
        : "=f"(d[0]), "=f"(d[1]), "=f"(d[2]), "=f"(d[3])
        : "r"(a[0]), "r"(a[1]), "r"(a[2]), "r"(a[3]),
          "r"(b[0]), "r"(b[1]),
          "f"(c[0]), "f"(c[1]), "f"(c[2]), "f"(c[3]));
}

// ---------------- tf32 MMA GEMM: C[M,N] = A[M,K] @ B[K,N] ------------------
// BM=BN=128, BK=16, 256 threads (8 warps, 2x4), warp tile 64x32 via m16n8k8.
// As stride 20 / Bs stride 136: conflict-free fragment loads.
#define AS_STRIDE 20
#define BS_STRIDE 136

template <int SILU>
__global__ void __launch_bounds__(256) tgemm_kernel(
    const float* __restrict__ A, const float* __restrict__ B,
    float* __restrict__ C, int M, int N, int K)
{
    __shared__ uint32_t As[2][128 * AS_STRIDE];
    __shared__ uint32_t Bs[2][16 * BS_STRIDE];

    int tid  = threadIdx.x;
    int lane = tid & 31;
    int warp = tid >> 5;
    int wm = (warp & 1) * 64;     // warp row offset within block tile
    int wn = (warp >> 1) * 32;    // warp col offset within block tile
    int rowBase = blockIdx.y * 128;
    int colBase = blockIdx.x * 128;

    float acc[4][4][4];
#pragma unroll
    for (int i = 0; i < 4; i++)
#pragma unroll
        for (int j = 0; j < 4; j++)
#pragma unroll
            for (int q = 0; q < 4; q++) acc[i][j][q] = 0.0f;

    // global-load assignment
    int ar  = tid >> 2;           // 0..63  (A rows, +64 for 2nd half)
    int ac  = (tid & 3) << 2;     // 0,4,8,12
    int bkr = tid >> 5;           // 0..7   (B k-rows, +8 for 2nd half)
    int bc  = (tid & 31) << 2;    // 0..124

    const float* Arow0 = A + (size_t)(rowBase + ar) * K + ac;
    const float* Arow1 = A + (size_t)(rowBase + 64 + ar) * K + ac;
    const float* Bp    = B + colBase + bc;

    float4 pfA0, pfA1, pfB0, pfB1;

    // prologue: load first tile
    pfA0 = *(const float4*)(Arow0);
    pfA1 = *(const float4*)(Arow1);
    pfB0 = *(const float4*)(Bp + (size_t)bkr * N);
    pfB1 = *(const float4*)(Bp + (size_t)(bkr + 8) * N);
    {
        uint32_t* as = As[0];
        uint32_t* bs = Bs[0];
        as[ar * AS_STRIDE + ac + 0] = f2tf32(pfA0.x);
        as[ar * AS_STRIDE + ac + 1] = f2tf32(pfA0.y);
        as[ar * AS_STRIDE + ac + 2] = f2tf32(pfA0.z);
        as[ar * AS_STRIDE + ac + 3] = f2tf32(pfA0.w);
        as[(ar + 64) * AS_STRIDE + ac + 0] = f2tf32(pfA1.x);
        as[(ar + 64) * AS_STRIDE + ac + 1] = f2tf32(pfA1.y);
        as[(ar + 64) * AS_STRIDE + ac + 2] = f2tf32(pfA1.z);
        as[(ar + 64) * AS_STRIDE + ac + 3] = f2tf32(pfA1.w);
        bs[bkr * BS_STRIDE + bc + 0] = f2tf32(pfB0.x);
        bs[bkr * BS_STRIDE + bc + 1] = f2tf32(pfB0.y);
        bs[bkr * BS_STRIDE + bc + 2] = f2tf32(pfB0.z);
        bs[bkr * BS_STRIDE + bc + 3] = f2tf32(pfB0.w);
        bs[(bkr + 8) * BS_STRIDE + bc + 0] = f2tf32(pfB1.x);
        bs[(bkr + 8) * BS_STRIDE + bc + 1] = f2tf32(pfB1.y);
        bs[(bkr + 8) * BS_STRIDE + bc + 2] = f2tf32(pfB1.z);
        bs[(bkr + 8) * BS_STRIDE + bc + 3] = f2tf32(pfB1.w);
    }
    __syncthreads();

    int nk = K >> 4;
    for (int kt = 0; kt < nk; kt++) {
        int buf = kt & 1;
        bool more = (kt + 1 < nk);
        if (more) {
            int k0 = (kt + 1) << 4;
            pfA0 = *(const float4*)(Arow0 + k0);
            pfA1 = *(const float4*)(Arow1 + k0);
            pfB0 = *(const float4*)(Bp + (size_t)(k0 + bkr) * N);
            pfB1 = *(const float4*)(Bp + (size_t)(k0 + 8 + bkr) * N);
        }

        const uint32_t* as = As[buf];
        const uint32_t* bs = Bs[buf];
#pragma unroll
        for (int ks = 0; ks < 16; ks += 8) {
            uint32_t af[4][4], bf[4][2];
#pragma unroll
            for (int i = 0; i < 4; i++) {
                int r = wm + i * 16 + (lane >> 2);
                int c = ks + (lane & 3);
                af[i][0] = as[r * AS_STRIDE + c];
                af[i][1] = as[(r + 8) * AS_STRIDE + c];
                af[i][2] = as[r * AS_STRIDE + c + 4];
                af[i][3] = as[(r + 8) * AS_STRIDE + c + 4];
            }
#pragma unroll
            for (int j = 0; j < 4; j++) {
                int kk = ks + (lane & 3);
                int n  = wn + j * 8 + (lane >> 2);
                bf[j][0] = bs[kk * BS_STRIDE + n];
                bf[j][1] = bs[(kk + 4) * BS_STRIDE + n];
            }
#pragma unroll
            for (int i = 0; i < 4; i++)
#pragma unroll
                for (int j = 0; j < 4; j++)
                    mma_tf32(acc[i][j], af[i], bf[j], acc[i][j]);
        }

        if (more) {
            uint32_t* asn = As[buf ^ 1];
            uint32_t* bsn = Bs[buf ^ 1];
            asn[ar * AS_STRIDE + ac + 0] = f2tf32(pfA0.x);
            asn[ar * AS_STRIDE + ac + 1] = f2tf32(pfA0.y);
            asn[ar * AS_STRIDE + ac + 2] = f2tf32(pfA0.z);
            asn[ar * AS_STRIDE + ac + 3] = f2tf32(pfA0.w);
            asn[(ar + 64) * AS_STRIDE + ac + 0] = f2tf32(pfA1.x);
            asn[(ar + 64) * AS_STRIDE + ac + 1] = f2tf32(pfA1.y);
            asn[(ar + 64) * AS_STRIDE + ac + 2] = f2tf32(pfA1.z);
            asn[(ar + 64) * AS_STRIDE + ac + 3] = f2tf32(pfA1.w);
            bsn[bkr * BS_STRIDE + bc + 0] = f2tf32(pfB0.x);
            bsn[bkr * BS_STRIDE + bc + 1] = f2tf32(pfB0.y);
            bsn[bkr * BS_STRIDE + bc + 2] = f2tf32(pfB0.z);
            bsn[bkr * BS_STRIDE + bc + 3] = f2tf32(pfB0.w);
            bsn[(bkr + 8) * BS_STRIDE + bc + 0] = f2tf32(pfB1.x);
            bsn[(bkr + 8) * BS_STRIDE + bc + 1] = f2tf32(pfB1.y);
            bsn[(bkr + 8) * BS_STRIDE + bc + 2] = f2tf32(pfB1.z);
            bsn[(bkr + 8) * BS_STRIDE + bc + 3] = f2tf32(pfB1.w);
            __syncthreads();
        }
    }

    // epilogue
#pragma unroll
    for (int i = 0; i < 4; i++) {
        int r0 = rowBase + wm + i * 16 + (lane >> 2);
#pragma unroll
        for (int j = 0; j < 4; j++) {
            int c0 = colBase + wn + j * 8 + (lane & 3) * 2;
            float2 v0, v1;
            v0.x = acc[i][j][0]; v0.y = acc[i][j][1];
            v1.x = acc[i][j][2]; v1.y = acc[i][j][3];
            if (SILU) {
                v0.x = v0.x / (1.0f + expf(-v0.x));
                v0.y = v0.y / (1.0f + expf(-v0.y));
                v1.x = v1.x / (1.0f + expf(-v1.x));
                v1.y = v1.y / (1.0f + expf(-v1.y));
            }
            *(float2*)&C[(size_t)r0 * N + c0]       = v0;
            *(float2*)&C[(size_t)(r0 + 8) * N + c0] = v1;
        }
    }
}

// ---------------- flash attention (causal, GQA 16q/4kv, d=64) -------------
// BM=BN=64, 256 threads, 4x4 micro-tiles. smem: Qs,Ks,Vs,Ps (64x64 each).
__global__ void __launch_bounds__(256) attn_kernel(
    const float* __restrict__ q, const float* __restrict__ k,
    const float* __restrict__ v, float* __restrict__ o)
{
    extern __shared__ float sm[];
    float* Qs = sm;
    float* Ks = sm + 4096;
    float* Vs = sm + 8192;
    float* Ps = sm + 12288;

    int qb  = gridDim.x - 1 - blockIdx.x;   // heavy blocks first
    int h   = blockIdx.y;
    int kvh = h >> 2;
    int tid = threadIdx.x;
    int tx  = tid & 15;
    int ty  = tid >> 4;

#pragma unroll
    for (int it = 0; it < 4; it++) {
        int idx = tid + 256 * it;
        int r = idx >> 4, d4 = (idx & 15) << 2;
        *(float4*)&Qs[r * 64 + d4] =
            *(const float4*)&q[(size_t)(qb * 64 + r) * D_MODEL + h * HD + d4];
    }

    float m[4], l[4], acc[4][4];
#pragma unroll
    for (int i = 0; i < 4; i++) {
        m[i] = -1e30f;
        l[i] = 0.0f;
#pragma unroll
        for (int j = 0; j < 4; j++) acc[i][j] = 0.0f;
    }

    for (int kb = 0; kb <= qb; kb++) {
        __syncthreads();
#pragma unroll
        for (int it = 0; it < 4; it++) {
            int idx = tid + 256 * it;
            int c = idx >> 4, d4 = (idx & 15) << 2;
            int sw = d4 ^ (((c >> 2) & 15) << 2);
            size_t goff = (size_t)(kb * 64 + c) * (NKV * HD) + kvh * HD + d4;
            *(float4*)&Ks[c * 64 + sw] = *(const float4*)&k[goff];
            *(float4*)&Vs[c * 64 + d4] = *(const float4*)&v[goff];
        }
        __syncthreads();

        float s[4][4];
#pragma unroll
        for (int i = 0; i < 4; i++)
#pragma unroll
            for (int j = 0; j < 4; j++) s[i][j] = 0.0f;

#pragma unroll
        for (int d4 = 0; d4 < 64; d4 += 4) {
            float4 qv[4], kv[4];
#pragma unroll
            for (int i = 0; i < 4; i++)
                qv[i] = *(float4*)&Qs[(ty * 4 + i) * 64 + d4];
#pragma unroll
            for (int j = 0; j < 4; j++)
                kv[j] = *(float4*)&Ks[(tx * 4 + j) * 64 + (d4 ^ (tx << 2))];
#pragma unroll
            for (int i = 0; i < 4; i++)
#pragma unroll
                for (int j = 0; j < 4; j++)
                    s[i][j] += qv[i].x * kv[j].x + qv[i].y * kv[j].y +
                               qv[i].z * kv[j].z + qv[i].w * kv[j].w;
        }

#pragma unroll
        for (int i = 0; i < 4; i++)
#pragma unroll
            for (int j = 0; j < 4; j++) s[i][j] *= 0.125f;
        if (kb == qb) {
#pragma unroll
            for (int i = 0; i < 4; i++)
#pragma unroll
                for (int j = 0; j < 4; j++)
                    if (tx * 4 + j > ty * 4 + i) s[i][j] = -INFINITY;
        }

#pragma unroll
        for (int i = 0; i < 4; i++) {
            float tm = s[i][0];
            tm = fmaxf(tm, s[i][1]);
            tm = fmaxf(tm, s[i][2]);
            tm = fmaxf(tm, s[i][3]);
#pragma unroll
            for (int off = 8; off >= 1; off >>= 1)
                tm = fmaxf(tm, __shfl_xor_sync(0xffffffffu, tm, off));
            float mn = fmaxf(m[i], tm);
            float corr = __expf(m[i] - mn);
            float rs = 0.0f;
#pragma unroll
            for (int j = 0; j < 4; j++) {
                float p = __expf(s[i][j] - mn);
                s[i][j] = p;
                rs += p;
            }
#pragma unroll
            for (int off = 8; off >= 1; off >>= 1)
                rs += __shfl_xor_sync(0xffffffffu, rs, off);
            l[i] = l[i] * corr + rs;
            m[i] = mn;
#pragma unroll
            for (int j = 0; j < 4; j++) acc[i][j] *= corr;
        }

#pragma unroll
        for (int i = 0; i < 4; i++) {
            float4 pv;
            pv.x = s[i][0]; pv.y = s[i][1]; pv.z = s[i][2]; pv.w = s[i][3];
            *(float4*)&Ps[(ty * 4 + i) * 64 + tx * 4] = pv;
        }
        __syncthreads();

#pragma unroll
        for (int k4 = 0; k4 < 64; k4 += 4) {
            float4 pv[4], vv[4];
#pragma unroll
            for (int i = 0; i < 4; i++)
                pv[i] = *(float4*)&Ps[(ty * 4 + i) * 64 + k4];
#pragma unroll
            for (int lsub = 0; lsub < 4; lsub++)
                vv[lsub] = *(float4*)&Vs[(k4 + lsub) * 64 + tx * 4];
#pragma unroll
            for (int i = 0; i < 4; i++) {
                acc[i][0] += pv[i].x * vv[0].x + pv[i].y * vv[1].x +
                             pv[i].z * vv[2].x + pv[i].w * vv[3].x;
                acc[i][1] += pv[i].x * vv[0].y + pv[i].y * vv[1].y +
                             pv[i].z * vv[2].y + pv[i].w * vv[3].y;
                acc[i][2] += pv[i].x * vv[0].z + pv[i].y * vv[1].z +
                             pv[i].z * vv[2].z + pv[i].w * vv[3].z;
                acc[i][3] += pv[i].x * vv[0].w + pv[i].y * vv[1].w +
                             pv[i].z * vv[2].w + pv[i].w * vv[3].w;
            }
        }
    }

#pragma unroll
    for (int i = 0; i < 4; i++) {
        float inv = 1.0f / l[i];
        float4 r;
        r.x = acc[i][0] * inv;
        r.y = acc[i][1] * inv;
        r.z = acc[i][2] * inv;
        r.w = acc[i][3] * inv;
        *(float4*)&o[(size_t)(qb * 64 + ty * 4 + i) * D_MODEL + h * HD + tx * 4] = r;
    }
}

// ---------------- launch ---------------------------------------------------
extern "C" void kernel_launch(void* const* d_in, const int* in_sizes, int n_in,
                              void* d_out, int out_size)
{
    const float* X  = (const float*)d_in[0];   // query [4096,1024]
    const float* Wq = (const float*)d_in[1];   // [1024,1024]
    const float* Wk = (const float*)d_in[2];   // [1024,256]
    const float* Wv = (const float*)d_in[3];   // [1024,256]
    const float* W1 = (const float*)d_in[4];   // [1024,4096]
    const float* W2 = (const float*)d_in[5];   // [4096,1024]
    float* out = (float*)d_out;

    float *gq, *gk, *gv, *ga, *gh;
    cudaGetSymbolAddress((void**)&gq, g_q);
    cudaGetSymbolAddress((void**)&gk, g_k);
    cudaGetSymbolAddress((void**)&gv, g_v);
    cudaGetSymbolAddress((void**)&ga, g_attn);
    cudaGetSymbolAddress((void**)&gh, g_h1);

    cudaFuncSetAttribute(attn_kernel,
                         cudaFuncAttributeMaxDynamicSharedMemorySize, 65536);

    rope_table_kernel<<<T_SEQ, 32>>>();

    // QKV projections (tf32 tensor cores)
    tgemm_kernel<0><<<dim3(D_MODEL / 128, T_SEQ / 128), 256>>>(
        X, Wq, gq, T_SEQ, D_MODEL, D_MODEL);
    tgemm_kernel<0><<<dim3((NKV * HD) / 128, T_SEQ / 128), 256>>>(
        X, Wk, gk, T_SEQ, NKV * HD, D_MODEL);
    tgemm_kernel<0><<<dim3((NKV * HD) / 128, T_SEQ / 128), 256>>>(
        X, Wv, gv, T_SEQ, NKV * HD, D_MODEL);

    // RoPE on q and k
    rope_apply_kernel<<<T_SEQ, NH * 32>>>(gq, NH);
    rope_apply_kernel<<<T_SEQ, NKV * 32>>>(gk, NKV);

    // causal flash attention
    attn_kernel<<<dim3(T_SEQ / 64, NH), 256, 65536>>>(gq, gk, gv, ga);

    // MLP (tf32 tensor cores)
    tgemm_kernel<1><<<dim3(D_FF / 128, T_SEQ / 128), 256>>>(
        ga, W1, gh, T_SEQ, D_FF, D_MODEL);
    tgemm_kernel<0><<<dim3(D_MODEL / 128, T_SEQ / 128), 256>>>(
        gh, W2, out, T_SEQ, D_MODEL, D_FF);
}

// round 3
// speedup vs baseline: 2.2753x; 2.0039x over previous
#include <cuda_runtime.h>
#include <math.h>
#include <stdint.h>

// Problem constants
#define T_SEQ  4096
#define D_MODEL 1024
#define NH     16
#define NKV    4
#define HD     64
#define D_FF   4096

// ---------------- scratch (device globals; no allocation allowed) ----------
__device__ float g_q[T_SEQ * D_MODEL];          // 16 MB
__device__ float g_k[T_SEQ * NKV * HD];         // 4 MB
__device__ float g_v[T_SEQ * NKV * HD];         // 4 MB
__device__ float g_attn[T_SEQ * D_MODEL];       // 16 MB
__device__ float g_h1[(size_t)T_SEQ * D_FF];    // 64 MB
__device__ float g_cos[T_SEQ * 32];
__device__ float g_sin[T_SEQ * 32];

// ---------------- RoPE table (replicates reference fp32 path) --------------
__global__ void rope_table_kernel() {
    int t = blockIdx.x, i = threadIdx.x;            // i in [0,32)
    float inv = 1.0f / powf(10000.0f, (float)(2 * i) / 64.0f);
    float ang = (float)t * inv;
    g_cos[t * 32 + i] = cosf(ang);
    g_sin[t * 32 + i] = sinf(ang);
}

__global__ void rope_apply_kernel(float* __restrict__ x, int nh) {
    int t = blockIdx.x;
    int h = threadIdx.x >> 5;
    int i = threadIdx.x & 31;
    float c = g_cos[t * 32 + i];
    float s = g_sin[t * 32 + i];
    float* p = x + (size_t)t * nh * HD + h * HD;
    float x1 = p[i], x2 = p[i + 32];
    p[i]      = x1 * c - x2 * s;
    p[i + 32] = x2 * c + x1 * s;
}

// ---------------- tf32 tensor-core helpers ---------------------------------
__device__ __forceinline__ uint32_t f2tf32(float x) {
    uint32_t r;
    asm("cvt.rna.tf32.f32 %0, %1;" : "=r"(r) : "f"(x));
    return r;
}

__device__ __forceinline__ void mma_tf32(float* d, const uint32_t* a,
                                         const uint32_t* b, const float* c) {
    asm volatile(
        "mma.sync.aligned.m16n8k8.row.col.f32.tf32.tf32.f32 "
        "{%0,%1,%2,%3}, {%4,%5,%6,%7}, {%8,%9}, {%10,%11,%12,%13};"
        : "=f"(d[0]), "=f"(d[1]), "=f"(d[2]), "=f"(d[3])
        : "r"(a[0]), "r"(a[1]), "r"(a[2]), "r"(a[3]),
          "r"(b[0]), "r"(b[1]),
          "f"(c[0]), "f"(c[1]), "f"(c[2]), "f"(c[3]));
}

// ---------------- tf32 MMA GEMM: C[M,N] = A[M,K] @ B[K,N] ------------------
#define AS_STRIDE 20
#define BS_STRIDE 136

template <int SILU>
__global__ void __launch_bounds__(256) tgemm_kernel(
    const float* __restrict__ A, const float* __restrict__ B,
    float* __restrict__ C, int M, int N, int K)
{
    __shared__ uint32_t As[2][128 * AS_STRIDE];
    __shared__ uint32_t Bs[2][16 * BS_STRIDE];

    int tid  = threadIdx.x;
    int lane = tid & 31;
    int warp = tid >> 5;
    int wm = (warp & 1) * 64;
    int wn = (warp >> 1) * 32;
    int rowBase = blockIdx.y * 128;
    int colBase = blockIdx.x * 128;

    float acc[4][4][4];
#pragma unroll
    for (int i = 0; i < 4; i++)
#pragma unroll
        for (int j = 0; j < 4; j++)
#pragma unroll
            for (int q = 0; q < 4; q++) acc[i][j][q] = 0.0f;

    int ar  = tid >> 2;
    int ac  = (tid & 3) << 2;
    int bkr = tid >> 5;
    int bc  = (tid & 31) << 2;

    const float* Arow0 = A + (size_t)(rowBase + ar) * K + ac;
    const float* Arow1 = A + (size_t)(rowBase + 64 + ar) * K + ac;
    const float* Bp    = B + colBase + bc;

    float4 pfA0, pfA1, pfB0, pfB1;

    pfA0 = *(const float4*)(Arow0);
    pfA1 = *(const float4*)(Arow1);
    pfB0 = *(const float4*)(Bp + (size_t)bkr * N);
    pfB1 = *(const float4*)(Bp + (size_t)(bkr + 8) * N);
    {
        uint32_t* as = As[0];
        uint32_t* bs = Bs[0];
        as[ar * AS_STRIDE + ac + 0] = f2tf32(pfA0.x);
        as[ar * AS_STRIDE + ac + 1] = f2tf32(pfA0.y);
        as[ar * AS_STRIDE + ac + 2] = f2tf32(pfA0.z);
        as[ar * AS_STRIDE + ac + 3] = f2tf32(pfA0.w);
        as[(ar + 64) * AS_STRIDE + ac + 0] = f2tf32(pfA1.x);
        as[(ar + 64) * AS_STRIDE + ac + 1] = f2tf32(pfA1.y);
        as[(ar + 64) * AS_STRIDE + ac + 2] = f2tf32(pfA1.z);
        as[(ar + 64) * AS_STRIDE + ac + 3] = f2tf32(pfA1.w);
        bs[bkr * BS_STRIDE + bc + 0] = f2tf32(pfB0.x);
        bs[bkr * BS_STRIDE + bc + 1] = f2tf32(pfB0.y);
        bs[bkr * BS_STRIDE + bc + 2] = f2tf32(pfB0.z);
        bs[bkr * BS_STRIDE + bc + 3] = f2tf32(pfB0.w);
        bs[(bkr + 8) * BS_STRIDE + bc + 0] = f2tf32(pfB1.x);
        bs[(bkr + 8) * BS_STRIDE + bc + 1] = f2tf32(pfB1.y);
        bs[(bkr + 8) * BS_STRIDE + bc + 2] = f2tf32(pfB1.z);
        bs[(bkr + 8) * BS_STRIDE + bc + 3] = f2tf32(pfB1.w);
    }
    __syncthreads();

    int nk = K >> 4;
    for (int kt = 0; kt < nk; kt++) {
        int buf = kt & 1;
        bool more = (kt + 1 < nk);
        if (more) {
            int k0 = (kt + 1) << 4;
            pfA0 = *(const float4*)(Arow0 + k0);
            pfA1 = *(const float4*)(Arow1 + k0);
            pfB0 = *(const float4*)(Bp + (size_t)(k0 + bkr) * N);
            pfB1 = *(const float4*)(Bp + (size_t)(k0 + 8 + bkr) * N);
        }

        const uint32_t* as = As[buf];
        const uint32_t* bs = Bs[buf];
#pragma unroll
        for (int ks = 0; ks < 16; ks += 8) {
            uint32_t af[4][4], bf[4][2];
#pragma unroll
            for (int i = 0; i < 4; i++) {
                int r = wm + i * 16 + (lane >> 2);
                int c = ks + (lane & 3);
                af[i][0] = as[r * AS_STRIDE + c];
                af[i][1] = as[(r + 8) * AS_STRIDE + c];
                af[i][2] = as[r * AS_STRIDE + c + 4];
                af[i][3] = as[(r + 8) * AS_STRIDE + c + 4];
            }
#pragma unroll
            for (int j = 0; j < 4; j++) {
                int kk = ks + (lane & 3);
                int n  = wn + j * 8 + (lane >> 2);
                bf[j][0] = bs[kk * BS_STRIDE + n];
                bf[j][1] = bs[(kk + 4) * BS_STRIDE + n];
            }
#pragma unroll
            for (int i = 0; i < 4; i++)
#pragma unroll
                for (int j = 0; j < 4; j++)
                    mma_tf32(acc[i][j], af[i], bf[j], acc[i][j]);
        }

        if (more) {
            uint32_t* asn = As[buf ^ 1];
            uint32_t* bsn = Bs[buf ^ 1];
            asn[ar * AS_STRIDE + ac + 0] = f2tf32(pfA0.x);
            asn[ar * AS_STRIDE + ac + 1] = f2tf32(pfA0.y);
            asn[ar * AS_STRIDE + ac + 2] = f2tf32(pfA0.z);
            asn[ar * AS_STRIDE + ac + 3] = f2tf32(pfA0.w);
            asn[(ar + 64) * AS_STRIDE + ac + 0] = f2tf32(pfA1.x);
            asn[(ar + 64) * AS_STRIDE + ac + 1] = f2tf32(pfA1.y);
            asn[(ar + 64) * AS_STRIDE + ac + 2] = f2tf32(pfA1.z);
            asn[(ar + 64) * AS_STRIDE + ac + 3] = f2tf32(pfA1.w);
            bsn[bkr * BS_STRIDE + bc + 0] = f2tf32(pfB0.x);
            bsn[bkr * BS_STRIDE + bc + 1] = f2tf32(pfB0.y);
            bsn[bkr * BS_STRIDE + bc + 2] = f2tf32(pfB0.z);
            bsn[bkr * BS_STRIDE + bc + 3] = f2tf32(pfB0.w);
            bsn[(bkr + 8) * BS_STRIDE + bc + 0] = f2tf32(pfB1.x);
            bsn[(bkr + 8) * BS_STRIDE + bc + 1] = f2tf32(pfB1.y);
            bsn[(bkr + 8) * BS_STRIDE + bc + 2] = f2tf32(pfB1.z);
            bsn[(bkr + 8) * BS_STRIDE + bc + 3] = f2tf32(pfB1.w);
            __syncthreads();
        }
    }

#pragma unroll
    for (int i = 0; i < 4; i++) {
        int r0 = rowBase + wm + i * 16 + (lane >> 2);
#pragma unroll
        for (int j = 0; j < 4; j++) {
            int c0 = colBase + wn + j * 8 + (lane & 3) * 2;
            float2 v0, v1;
            v0.x = acc[i][j][0]; v0.y = acc[i][j][1];
            v1.x = acc[i][j][2]; v1.y = acc[i][j][3];
            if (SILU) {
                v0.x = v0.x / (1.0f + expf(-v0.x));
                v0.y = v0.y / (1.0f + expf(-v0.y));
                v1.x = v1.x / (1.0f + expf(-v1.x));
                v1.y = v1.y / (1.0f + expf(-v1.y));
            }
            *(float2*)&C[(size_t)r0 * N + c0]       = v0;
            *(float2*)&C[(size_t)(r0 + 8) * N + c0] = v1;
        }
    }
}

// ---------------- MMA flash attention (causal, GQA, d=64, 3xTF32) ----------
// BM=128, BN=64, 8 warps (16 rows each). K/V pre-split hi/lo in smem.
// Strides: Khi/Klo 68 (4n+d conflict-free), Vhi/Vlo 72 (8k+n), P 68.
#define KST 68
#define VST 72
#define PST 68
#define ATT_SMEM ((64*KST*2 + 64*VST*2 + 128*PST) * 4)

__global__ void __launch_bounds__(256) attn_mma_kernel(
    const float* __restrict__ qp, const float* __restrict__ kp,
    const float* __restrict__ vp, float* __restrict__ op)
{
    extern __shared__ float sm[];
    float* Khi = sm;                       // 64 x 68
    float* Klo = Khi + 64 * KST;
    float* Vhi = Klo + 64 * KST;           // 64 x 72
    float* Vlo = Vhi + 64 * VST;
    float* Pf  = Vlo + 64 * VST;           // 128 x 68 (also Q staging)

    int qb   = gridDim.x - 1 - blockIdx.x;   // heavy blocks first
    int h    = blockIdx.y;
    int kvh  = h >> 2;
    int tid  = threadIdx.x;
    int lane = tid & 31;
    int warp = tid >> 5;
    int wm   = warp * 16;

    int fr = wm + (lane >> 2);       // fragment row (first of pair)
    int fc = lane & 3;               // fragment k-col

    // ---- stage Q tile into Pf, coalesced ----
#pragma unroll
    for (int i = 0; i < 8; i++) {
        int e = tid + 256 * i;           // 2048 float4 groups
        int r = e >> 4, c4 = (e & 15) << 2;
        *(float4*)&Pf[r * PST + c4] =
            *(const float4*)&qp[(size_t)(qb * 128 + r) * D_MODEL + h * HD + c4];
    }
    __syncthreads();

    // ---- extract Q fragments (scaled by 1/8, exact), split hi/lo ----
    uint32_t qhi[8][4], qlo[8][4];
#pragma unroll
    for (int kt = 0; kt < 8; kt++) {
        float v0 = Pf[fr * PST + kt * 8 + fc]       * 0.125f;
        float v1 = Pf[(fr + 8) * PST + kt * 8 + fc] * 0.125f;
        float v2 = Pf[fr * PST + kt * 8 + fc + 4]   * 0.125f;
        float v3 = Pf[(fr + 8) * PST + kt * 8 + fc + 4] * 0.125f;
        qhi[kt][0] = f2tf32(v0); qlo[kt][0] = f2tf32(v0 - __uint_as_float(qhi[kt][0]));
        qhi[kt][1] = f2tf32(v1); qlo[kt][1] = f2tf32(v1 - __uint_as_float(qhi[kt][1]));
        qhi[kt][2] = f2tf32(v2); qlo[kt][2] = f2tf32(v2 - __uint_as_float(qhi[kt][2]));
        qhi[kt][3] = f2tf32(v3); qlo[kt][3] = f2tf32(v3 - __uint_as_float(qhi[kt][3]));
    }

    float oacc[8][4];
#pragma unroll
    for (int nt = 0; nt < 8; nt++)
#pragma unroll
        for (int j = 0; j < 4; j++) oacc[nt][j] = 0.0f;
    float m0 = -1e30f, m1 = -1e30f, l0 = 0.0f, l1 = 0.0f;

    int kbmax = 2 * qb + 1;
    for (int kb = 0; kb <= kbmax; kb++) {
        __syncthreads();   // prior-iter smem reads done (also covers Q staging)

        // ---- load K/V tile, split hi/lo ----
        int kbase = kb * 64;
#pragma unroll
        for (int i = 0; i < 4; i++) {
            int e = tid + 256 * i;       // 1024 float4 groups
            int r = e >> 4, c4 = (e & 15) << 2;
            size_t g = (size_t)(kbase + r) * (NKV * HD) + kvh * HD + c4;
            float4 kk = *(const float4*)&kp[g];
            float4 vv = *(const float4*)&vp[g];
            float kvals[4] = {kk.x, kk.y, kk.z, kk.w};
            float vvals[4] = {vv.x, vv.y, vv.z, vv.w};
#pragma unroll
            for (int j = 0; j < 4; j++) {
                uint32_t hk = f2tf32(kvals[j]);
                Khi[r * KST + c4 + j] = __uint_as_float(hk);
                Klo[r * KST + c4 + j] =
                    __uint_as_float(f2tf32(kvals[j] - __uint_as_float(hk)));
                uint32_t hv = f2tf32(vvals[j]);
                Vhi[r * VST + c4 + j] = __uint_as_float(hv);
                Vlo[r * VST + c4 + j] =
                    __uint_as_float(f2tf32(vvals[j] - __uint_as_float(hv)));
            }
        }
        __syncthreads();

        // ---- S = (Q/8) @ K^T  via 3xTF32 ----
        float sacc[8][4];
#pragma unroll
        for (int nt = 0; nt < 8; nt++)
#pragma unroll
            for (int j = 0; j < 4; j++) sacc[nt][j] = 0.0f;

#pragma unroll
        for (int nt = 0; nt < 8; nt++) {
            int bn = nt * 8 + (lane >> 2);
#pragma unroll
            for (int ks = 0; ks < 8; ks++) {
                int d = ks * 8 + (lane & 3);
                uint32_t bh[2], bl[2];
                bh[0] = __float_as_uint(Khi[bn * KST + d]);
                bh[1] = __float_as_uint(Khi[bn * KST + d + 4]);
                bl[0] = __float_as_uint(Klo[bn * KST + d]);
                bl[1] = __float_as_uint(Klo[bn * KST + d + 4]);
                mma_tf32(sacc[nt], qhi[ks], bh, sacc[nt]);
                mma_tf32(sacc[nt], qlo[ks], bh, sacc[nt]);
                mma_tf32(sacc[nt], qhi[ks], bl, sacc[nt]);
            }
        }

        // ---- causal mask (only last two kb tiles can cross diagonal) ----
        if (kb >= 2 * qb) {
            int grow0 = qb * 128 + fr;
            int grow1 = grow0 + 8;
#pragma unroll
            for (int nt = 0; nt < 8; nt++) {
                int gc = kb * 64 + nt * 8 + (lane & 3) * 2;
                if (gc     > grow0) sacc[nt][0] = -1e30f;
                if (gc + 1 > grow0) sacc[nt][1] = -1e30f;
                if (gc     > grow1) sacc[nt][2] = -1e30f;
                if (gc + 1 > grow1) sacc[nt][3] = -1e30f;
            }
        }

        // ---- online softmax (rows fr, fr+8; quad lanes share a row) ----
        float mx0 = -1e30f, mx1 = -1e30f;
#pragma unroll
        for (int nt = 0; nt < 8; nt++) {
            mx0 = fmaxf(mx0, fmaxf(sacc[nt][0], sacc[nt][1]));
            mx1 = fmaxf(mx1, fmaxf(sacc[nt][2], sacc[nt][3]));
        }
        mx0 = fmaxf(mx0, __shfl_xor_sync(0xffffffffu, mx0, 1));
        mx0 = fmaxf(mx0, __shfl_xor_sync(0xffffffffu, mx0, 2));
        mx1 = fmaxf(mx1, __shfl_xor_sync(0xffffffffu, mx1, 1));
        mx1 = fmaxf(mx1, __shfl_xor_sync(0xffffffffu, mx1, 2));

        float mn0 = fmaxf(m0, mx0), mn1 = fmaxf(m1, mx1);
        float c0 = __expf(m0 - mn0), c1 = __expf(m1 - mn1);
        float rs0 = 0.0f, rs1 = 0.0f;
#pragma unroll
        for (int nt = 0; nt < 8; nt++) {
            float p0 = __expf(sacc[nt][0] - mn0);
            float p1 = __expf(sacc[nt][1] - mn0);
            float p2 = __expf(sacc[nt][2] - mn1);
            float p3 = __expf(sacc[nt][3] - mn1);
            sacc[nt][0] = p0; sacc[nt][1] = p1;
            sacc[nt][2] = p2; sacc[nt][3] = p3;
            rs0 += p0 + p1;
            rs1 += p2 + p3;
        }
        rs0 += __shfl_xor_sync(0xffffffffu, rs0, 1);
        rs0 += __shfl_xor_sync(0xffffffffu, rs0, 2);
        rs1 += __shfl_xor_sync(0xffffffffu, rs1, 1);
        rs1 += __shfl_xor_sync(0xffffffffu, rs1, 2);
        l0 = l0 * c0 + rs0;  m0 = mn0;
        l1 = l1 * c1 + rs1;  m1 = mn1;
#pragma unroll
        for (int nt = 0; nt < 8; nt++) {
            oacc[nt][0] *= c0; oacc[nt][1] *= c0;
            oacc[nt][2] *= c1; oacc[nt][3] *= c1;
        }

        // ---- write P (warp-local rows only) ----
#pragma unroll
        for (int nt = 0; nt < 8; nt++) {
            float2 w0; w0.x = sacc[nt][0]; w0.y = sacc[nt][1];
            float2 w1; w1.x = sacc[nt][2]; w1.y = sacc[nt][3];
            *(float2*)&Pf[fr * PST + nt * 8 + (lane & 3) * 2]       = w0;
            *(float2*)&Pf[(fr + 8) * PST + nt * 8 + (lane & 3) * 2] = w1;
        }
        __syncwarp();

        // ---- O += P @ V  via 3xTF32 ----
#pragma unroll
        for (int kt = 0; kt < 8; kt++) {
            float a0 = Pf[fr * PST + kt * 8 + fc];
            float a1 = Pf[(fr + 8) * PST + kt * 8 + fc];
            float a2 = Pf[fr * PST + kt * 8 + fc + 4];
            float a3 = Pf[(fr + 8) * PST + kt * 8 + fc + 4];
            uint32_t ahi[4], alo[4];
            ahi[0] = f2tf32(a0); alo[0] = f2tf32(a0 - __uint_as_float(ahi[0]));
            ahi[1] = f2tf32(a1); alo[1] = f2tf32(a1 - __uint_as_float(ahi[1]));
            ahi[2] = f2tf32(a2); alo[2] = f2tf32(a2 - __uint_as_float(ahi[2]));
            ahi[3] = f2tf32(a3); alo[3] = f2tf32(a3 - __uint_as_float(ahi[3]));
#pragma unroll
            for (int nt = 0; nt < 8; nt++) {
                int bn = nt * 8 + (lane >> 2);
                int bk = kt * 8 + (lane & 3);
                uint32_t bh[2], bl[2];
                bh[0] = __float_as_uint(Vhi[bk * VST + bn]);
                bh[1] = __float_as_uint(Vhi[(bk + 4) * VST + bn]);
                bl[0] = __float_as_uint(Vlo[bk * VST + bn]);
                bl[1] = __float_as_uint(Vlo[(bk + 4) * VST + bn]);
                mma_tf32(oacc[nt], ahi, bh, oacc[nt]);
                mma_tf32(oacc[nt], alo, bh, oacc[nt]);
                mma_tf32(oacc[nt], ahi, bl, oacc[nt]);
            }
        }
    }

    // ---- finalize: divide by l, write O ----
    float inv0 = 1.0f / l0, inv1 = 1.0f / l1;
#pragma unroll
    for (int nt = 0; nt < 8; nt++) {
        int col = h * HD + nt * 8 + (lane & 3) * 2;
        float2 w0; w0.x = oacc[nt][0] * inv0; w0.y = oacc[nt][1] * inv0;
        float2 w1; w1.x = oacc[nt][2] * inv1; w1.y = oacc[nt][3] * inv1;
        *(float2*)&op[(size_t)(qb * 128 + fr) * D_MODEL + col]     = w0;
        *(float2*)&op[(size_t)(qb * 128 + fr + 8) * D_MODEL + col] = w1;
    }
}

// ---------------- launch ---------------------------------------------------
extern "C" void kernel_launch(void* const* d_in, const int* in_sizes, int n_in,
                              void* d_out, int out_size)
{
    const float* X  = (const float*)d_in[0];   // query [4096,1024]
    const float* Wq = (const float*)d_in[1];   // [1024,1024]
    const float* Wk = (const float*)d_in[2];   // [1024,256]
    const float* Wv = (const float*)d_in[3];   // [1024,256]
    const float* W1 = (const float*)d_in[4];   // [1024,4096]
    const float* W2 = (const float*)d_in[5];   // [4096,1024]
    float* out = (float*)d_out;

    float *gq, *gk, *gv, *ga, *gh;
    cudaGetSymbolAddress((void**)&gq, g_q);
    cudaGetSymbolAddress((void**)&gk, g_k);
    cudaGetSymbolAddress((void**)&gv, g_v);
    cudaGetSymbolAddress((void**)&ga, g_attn);
    cudaGetSymbolAddress((void**)&gh, g_h1);

    cudaFuncSetAttribute(attn_mma_kernel,
                         cudaFuncAttributeMaxDynamicSharedMemorySize, ATT_SMEM);

    rope_table_kernel<<<T_SEQ, 32>>>();

    // QKV projections (tf32 tensor cores)
    tgemm_kernel<0><<<dim3(D_MODEL / 128, T_SEQ / 128), 256>>>(
        X, Wq, gq, T_SEQ, D_MODEL, D_MODEL);
    tgemm_kernel<0><<<dim3((NKV * HD) / 128, T_SEQ / 128), 256>>>(
        X, Wk, gk, T_SEQ, NKV * HD, D_MODEL);
    tgemm_kernel<0><<<dim3((NKV * HD) / 128, T_SEQ / 128), 256>>>(
        X, Wv, gv, T_SEQ, NKV * HD, D_MODEL);

    // RoPE on q and k
    rope_apply_kernel<<<T_SEQ, NH * 32>>>(gq, NH);
    rope_apply_kernel<<<T_SEQ, NKV * 32>>>(gk, NKV);

    // causal flash attention on tensor cores
    attn_mma_kernel<<<dim3(T_SEQ / 128, NH), 256, ATT_SMEM>>>(gq, gk, gv, ga);

    // MLP (tf32 tensor cores)
    tgemm_kernel<1><<<dim3(D_FF / 128, T_SEQ / 128), 256>>>(
        ga, W1, gh, T_SEQ, D_FF, D_MODEL);
    tgemm_kernel<0><<<dim3(D_MODEL / 128, T_SEQ / 128), 256>>>(
        gh, W2, out, T_SEQ, D_MODEL, D_FF);
}

// round 4
// speedup vs baseline: 2.3510x; 1.0333x over previous
#include <cuda_runtime.h>
#include <math.h>
#include <stdint.h>

// Problem constants
#define T_SEQ  4096
#define D_MODEL 1024
#define NH     16
#define NKV    4
#define HD     64
#define D_FF   4096

// ---------------- scratch (device globals; no allocation allowed) ----------
__device__ float g_q[T_SEQ * D_MODEL];          // 16 MB
__device__ float g_k[T_SEQ * NKV * HD];         // 4 MB
__device__ float g_v[T_SEQ * NKV * HD];         // 4 MB
__device__ float g_attn[T_SEQ * D_MODEL];       // 16 MB (tf32-rounded)
__device__ float g_h1[(size_t)T_SEQ * D_FF];    // 64 MB (tf32-rounded)
__device__ float g_cos[T_SEQ * 32];
__device__ float g_sin[T_SEQ * 32];
// tf32-pre-rounded operands
__device__ float g_xt[T_SEQ * D_MODEL];         // 16 MB
__device__ float g_wqt[D_MODEL * D_MODEL];      // 4 MB
__device__ float g_wkt[D_MODEL * NKV * HD];     // 1 MB
__device__ float g_wvt[D_MODEL * NKV * HD];     // 1 MB
__device__ float g_w1t[D_MODEL * D_FF];         // 16 MB
__device__ float g_w2t[D_FF * D_MODEL];         // 16 MB

// ---------------- helpers ---------------------------------------------------
__device__ __forceinline__ uint32_t f2tf32(float x) {
    uint32_t r;
    asm("cvt.rna.tf32.f32 %0, %1;" : "=r"(r) : "f"(x));
    return r;
}
__device__ __forceinline__ float roundtf(float x) {
    return __uint_as_float(f2tf32(x));
}

__device__ __forceinline__ void mma_tf32(float* d, const uint32_t* a,
                                         const uint32_t* b, const float* c) {
    asm volatile(
        "mma.sync.aligned.m16n8k8.row.col.f32.tf32.tf32.f32 "
        "{%0,%1,%2,%3}, {%4,%5,%6,%7}, {%8,%9}, {%10,%11,%12,%13};"
        : "=f"(d[0]), "=f"(d[1]), "=f"(d[2]), "=f"(d[3])
        : "r"(a[0]), "r"(a[1]), "r"(a[2]), "r"(a[3]),
          "r"(b[0]), "r"(b[1]),
          "f"(c[0]), "f"(c[1]), "f"(c[2]), "f"(c[3]));
}

__device__ __forceinline__ void cp16(float* smem_dst, const float* g) {
    uint32_t a = (uint32_t)__cvta_generic_to_shared(smem_dst);
    asm volatile("cp.async.ca.shared.global [%0], [%1], 16;" :: "r"(a), "l"(g));
}

// ---------------- pre-round pass -------------------------------------------
__global__ void round_tf32_kernel(const float* __restrict__ in,
                                  float* __restrict__ out, int n4) {
    int i = blockIdx.x * 256 + threadIdx.x;
    if (i < n4) {
        float4 v = ((const float4*)in)[i];
        v.x = roundtf(v.x); v.y = roundtf(v.y);
        v.z = roundtf(v.z); v.w = roundtf(v.w);
        ((float4*)out)[i] = v;
    }
}

// ---------------- RoPE ------------------------------------------------------
__global__ void rope_table_kernel() {
    int t = blockIdx.x, i = threadIdx.x;            // i in [0,32)
    float inv = 1.0f / powf(10000.0f, (float)(2 * i) / 64.0f);
    float ang = (float)t * inv;
    g_cos[t * 32 + i] = cosf(ang);
    g_sin[t * 32 + i] = sinf(ang);
}

__global__ void rope_apply_kernel(float* __restrict__ x, int nh) {
    int t = blockIdx.x;
    int h = threadIdx.x >> 5;
    int i = threadIdx.x & 31;
    float c = g_cos[t * 32 + i];
    float s = g_sin[t * 32 + i];
    float* p = x + (size_t)t * nh * HD + h * HD;
    float x1 = p[i], x2 = p[i + 32];
    p[i]      = x1 * c - x2 * s;
    p[i + 32] = x2 * c + x1 * s;
}

// ---------------- cp.async pipelined tf32 GEMM ------------------------------
// C[.,N] = A[.,K] @ B[K,N]; A,B pre-rounded to tf32 values in fp32 storage.
// BM=BN=128, BK=16, 256 threads (8 warps 2x4), 4-stage cp.async pipeline.
#define AS_ST 20
#define BS_ST 136
#define AS_STAGE (128 * AS_ST)
#define BS_STAGE (16 * BS_ST)
#define GEMM_SMEM ((4 * (AS_STAGE + BS_STAGE)) * 4)

template <int SILU, int ROUND>
__device__ __forceinline__ void gemm_body(
    const float* __restrict__ A, const float* __restrict__ B,
    float* __restrict__ C, int N, int K, int rowBase, int colBase)
{
    extern __shared__ float smp[];
    float* As = smp;                  // 4 stages x 128x20
    float* Bs = smp + 4 * AS_STAGE;   // 4 stages x 16x136

    int tid  = threadIdx.x;
    int lane = tid & 31;
    int warp = tid >> 5;
    int wm = (warp & 1) * 64;
    int wn = (warp >> 1) * 32;

    int ar  = tid >> 2;           // 0..63
    int ac  = (tid & 3) << 2;     // 0,4,8,12
    int bkr = tid >> 5;           // 0..7
    int bc  = (tid & 31) << 2;    // 0..124

    const float* Ag0 = A + (size_t)(rowBase + ar) * K + ac;
    const float* Ag1 = A + (size_t)(rowBase + 64 + ar) * K + ac;
    const float* Bg  = B + colBase + bc;

    int nk = K >> 4;

    // prologue: stages 0..2
#pragma unroll
    for (int s = 0; s < 3; s++) {
        if (s < nk) {
            float* as = As + s * AS_STAGE;
            float* bs = Bs + s * BS_STAGE;
            int k0 = s << 4;
            cp16(as + ar * AS_ST + ac,        Ag0 + k0);
            cp16(as + (ar + 64) * AS_ST + ac, Ag1 + k0);
            cp16(bs + bkr * BS_ST + bc,       Bg + (size_t)(k0 + bkr) * N);
            cp16(bs + (bkr + 8) * BS_ST + bc, Bg + (size_t)(k0 + 8 + bkr) * N);
        }
        asm volatile("cp.async.commit_group;");
    }

    float acc[4][4][4];
#pragma unroll
    for (int i = 0; i < 4; i++)
#pragma unroll
        for (int j = 0; j < 4; j++)
#pragma unroll
            for (int q = 0; q < 4; q++) acc[i][j][q] = 0.0f;

    for (int kt = 0; kt < nk; kt++) {
        asm volatile("cp.async.wait_group 2;");
        __syncthreads();

        int nx = kt + 3;
        if (nx < nk) {
            int bufn = nx & 3;
            float* as = As + bufn * AS_STAGE;
            float* bs = Bs + bufn * BS_STAGE;
            int k0 = nx << 4;
            cp16(as + ar * AS_ST + ac,        Ag0 + k0);
            cp16(as + (ar + 64) * AS_ST + ac, Ag1 + k0);
            cp16(bs + bkr * BS_ST + bc,       Bg + (size_t)(k0 + bkr) * N);
            cp16(bs + (bkr + 8) * BS_ST + bc, Bg + (size_t)(k0 + 8 + bkr) * N);
        }
        asm volatile("cp.async.commit_group;");

        const float* as = As + (kt & 3) * AS_STAGE;
        const float* bs = Bs + (kt & 3) * BS_STAGE;
#pragma unroll
        for (int ks = 0; ks < 16; ks += 8) {
            uint32_t af[4][4], bf[4][2];
#pragma unroll
            for (int i = 0; i < 4; i++) {
                int r = wm + i * 16 + (lane >> 2);
                int c = ks + (lane & 3);
                af[i][0] = __float_as_uint(as[r * AS_ST + c]);
                af[i][1] = __float_as_uint(as[(r + 8) * AS_ST + c]);
                af[i][2] = __float_as_uint(as[r * AS_ST + c + 4]);
                af[i][3] = __float_as_uint(as[(r + 8) * AS_ST + c + 4]);
            }
#pragma unroll
            for (int j = 0; j < 4; j++) {
                int kk = ks + (lane & 3);
                int n  = wn + j * 8 + (lane >> 2);
                bf[j][0] = __float_as_uint(bs[kk * BS_ST + n]);
                bf[j][1] = __float_as_uint(bs[(kk + 4) * BS_ST + n]);
            }
#pragma unroll
            for (int i = 0; i < 4; i++)
#pragma unroll
                for (int j = 0; j < 4; j++)
                    mma_tf32(acc[i][j], af[i], bf[j], acc[i][j]);
        }
    }

    // epilogue
#pragma unroll
    for (int i = 0; i < 4; i++) {
        int r0 = rowBase + wm + i * 16 + (lane >> 2);
#pragma unroll
        for (int j = 0; j < 4; j++) {
            int c0 = colBase + wn + j * 8 + (lane & 3) * 2;
            float2 v0, v1;
            v0.x = acc[i][j][0]; v0.y = acc[i][j][1];
            v1.x = acc[i][j][2]; v1.y = acc[i][j][3];
            if (SILU) {
                v0.x = v0.x / (1.0f + expf(-v0.x));
                v0.y = v0.y / (1.0f + expf(-v0.y));
                v1.x = v1.x / (1.0f + expf(-v1.x));
                v1.y = v1.y / (1.0f + expf(-v1.y));
            }
            if (ROUND) {
                v0.x = roundtf(v0.x); v0.y = roundtf(v0.y);
                v1.x = roundtf(v1.x); v1.y = roundtf(v1.y);
            }
            *(float2*)&C[(size_t)r0 * N + c0]       = v0;
            *(float2*)&C[(size_t)(r0 + 8) * N + c0] = v1;
        }
    }
}

template <int SILU, int ROUND>
__global__ void __launch_bounds__(256) tgemm2_kernel(
    const float* __restrict__ A, const float* __restrict__ B,
    float* __restrict__ C, int N, int K)
{
    gemm_body<SILU, ROUND>(A, B, C, N, K, blockIdx.y * 128, blockIdx.x * 128);
}

// fused QKV: grid.x = 12 (8 Wq cols, 2 Wk, 2 Wv), grid.y = 32
__global__ void __launch_bounds__(256) qkv_kernel(
    const float* __restrict__ Xt,
    const float* __restrict__ Wqt, const float* __restrict__ Wkt,
    const float* __restrict__ Wvt,
    float* __restrict__ q, float* __restrict__ k, float* __restrict__ v)
{
    int bx = blockIdx.x;
    const float* B;
    float* C;
    int N, colBase;
    if (bx < 8)       { B = Wqt; C = q; N = D_MODEL;  colBase = bx * 128; }
    else if (bx < 10) { B = Wkt; C = k; N = NKV * HD; colBase = (bx - 8) * 128; }
    else              { B = Wvt; C = v; N = NKV * HD; colBase = (bx - 10) * 128; }
    gemm_body<0, 0>(Xt, B, C, N, D_MODEL, blockIdx.y * 128, colBase);
}

// ---------------- MMA flash attention (causal, GQA, d=64, 3xTF32) ----------
#define KST 68
#define VST 72
#define PST 68
#define ATT_SMEM ((64*KST*2 + 64*VST*2 + 128*PST) * 4)

__global__ void __launch_bounds__(256) attn_mma_kernel(
    const float* __restrict__ qp, const float* __restrict__ kp,
    const float* __restrict__ vp, float* __restrict__ op)
{
    extern __shared__ float sm[];
    float* Khi = sm;                       // 64 x 68
    float* Klo = Khi + 64 * KST;
    float* Vhi = Klo + 64 * KST;           // 64 x 72
    float* Vlo = Vhi + 64 * VST;
    float* Pf  = Vlo + 64 * VST;           // 128 x 68 (also Q staging)

    int qb   = gridDim.x - 1 - blockIdx.x;   // heavy blocks first
    int h    = blockIdx.y;
    int kvh  = h >> 2;
    int tid  = threadIdx.x;
    int lane = tid & 31;
    int warp = tid >> 5;
    int wm   = warp * 16;

    int fr = wm + (lane >> 2);
    int fc = lane & 3;

#pragma unroll
    for (int i = 0; i < 8; i++) {
        int e = tid + 256 * i;
        int r = e >> 4, c4 = (e & 15) << 2;
        *(float4*)&Pf[r * PST + c4] =
            *(const float4*)&qp[(size_t)(qb * 128 + r) * D_MODEL + h * HD + c4];
    }
    __syncthreads();

    uint32_t qhi[8][4], qlo[8][4];
#pragma unroll
    for (int kt = 0; kt < 8; kt++) {
        float v0 = Pf[fr * PST + kt * 8 + fc]       * 0.125f;
        float v1 = Pf[(fr + 8) * PST + kt * 8 + fc] * 0.125f;
        float v2 = Pf[fr * PST + kt * 8 + fc + 4]   * 0.125f;
        float v3 = Pf[(fr + 8) * PST + kt * 8 + fc + 4] * 0.125f;
        qhi[kt][0] = f2tf32(v0); qlo[kt][0] = f2tf32(v0 - __uint_as_float(qhi[kt][0]));
        qhi[kt][1] = f2tf32(v1); qlo[kt][1] = f2tf32(v1 - __uint_as_float(qhi[kt][1]));
        qhi[kt][2] = f2tf32(v2); qlo[kt][2] = f2tf32(v2 - __uint_as_float(qhi[kt][2]));
        qhi[kt][3] = f2tf32(v3); qlo[kt][3] = f2tf32(v3 - __uint_as_float(qhi[kt][3]));
    }

    float oacc[8][4];
#pragma unroll
    for (int nt = 0; nt < 8; nt++)
#pragma unroll
        for (int j = 0; j < 4; j++) oacc[nt][j] = 0.0f;
    float m0 = -1e30f, m1 = -1e30f, l0 = 0.0f, l1 = 0.0f;

    int kbmax = 2 * qb + 1;
    for (int kb = 0; kb <= kbmax; kb++) {
        __syncthreads();

        int kbase = kb * 64;
#pragma unroll
        for (int i = 0; i < 4; i++) {
            int e = tid + 256 * i;
            int r = e >> 4, c4 = (e & 15) << 2;
            size_t g = (size_t)(kbase + r) * (NKV * HD) + kvh * HD + c4;
            float4 kk = *(const float4*)&kp[g];
            float4 vv = *(const float4*)&vp[g];
            float kvals[4] = {kk.x, kk.y, kk.z, kk.w};
            float vvals[4] = {vv.x, vv.y, vv.z, vv.w};
#pragma unroll
            for (int j = 0; j < 4; j++) {
                uint32_t hk = f2tf32(kvals[j]);
                Khi[r * KST + c4 + j] = __uint_as_float(hk);
                Klo[r * KST + c4 + j] =
                    __uint_as_float(f2tf32(kvals[j] - __uint_as_float(hk)));
                uint32_t hv = f2tf32(vvals[j]);
                Vhi[r * VST + c4 + j] = __uint_as_float(hv);
                Vlo[r * VST + c4 + j] =
                    __uint_as_float(f2tf32(vvals[j] - __uint_as_float(hv)));
            }
        }
        __syncthreads();

        float sacc[8][4];
#pragma unroll
        for (int nt = 0; nt < 8; nt++)
#pragma unroll
            for (int j = 0; j < 4; j++) sacc[nt][j] = 0.0f;

#pragma unroll
        for (int nt = 0; nt < 8; nt++) {
            int bn = nt * 8 + (lane >> 2);
#pragma unroll
            for (int ks = 0; ks < 8; ks++) {
                int d = ks * 8 + (lane & 3);
                uint32_t bh[2], bl[2];
                bh[0] = __float_as_uint(Khi[bn * KST + d]);
                bh[1] = __float_as_uint(Khi[bn * KST + d + 4]);
                bl[0] = __float_as_uint(Klo[bn * KST + d]);
                bl[1] = __float_as_uint(Klo[bn * KST + d + 4]);
                mma_tf32(sacc[nt], qhi[ks], bh, sacc[nt]);
                mma_tf32(sacc[nt], qlo[ks], bh, sacc[nt]);
                mma_tf32(sacc[nt], qhi[ks], bl, sacc[nt]);
            }
        }

        if (kb >= 2 * qb) {
            int grow0 = qb * 128 + fr;
            int grow1 = grow0 + 8;
#pragma unroll
            for (int nt = 0; nt < 8; nt++) {
                int gc = kb * 64 + nt * 8 + (lane & 3) * 2;
                if (gc     > grow0) sacc[nt][0] = -1e30f;
                if (gc + 1 > grow0) sacc[nt][1] = -1e30f;
                if (gc     > grow1) sacc[nt][2] = -1e30f;
                if (gc + 1 > grow1) sacc[nt][3] = -1e30f;
            }
        }

        float mx0 = -1e30f, mx1 = -1e30f;
#pragma unroll
        for (int nt = 0; nt < 8; nt++) {
            mx0 = fmaxf(mx0, fmaxf(sacc[nt][0], sacc[nt][1]));
            mx1 = fmaxf(mx1, fmaxf(sacc[nt][2], sacc[nt][3]));
        }
        mx0 = fmaxf(mx0, __shfl_xor_sync(0xffffffffu, mx0, 1));
        mx0 = fmaxf(mx0, __shfl_xor_sync(0xffffffffu, mx0, 2));
        mx1 = fmaxf(mx1, __shfl_xor_sync(0xffffffffu, mx1, 1));
        mx1 = fmaxf(mx1, __shfl_xor_sync(0xffffffffu, mx1, 2));

        float mn0 = fmaxf(m0, mx0), mn1 = fmaxf(m1, mx1);
        float c0 = __expf(m0 - mn0), c1 = __expf(m1 - mn1);
        float rs0 = 0.0f, rs1 = 0.0f;
#pragma unroll
        for (int nt = 0; nt < 8; nt++) {
            float p0 = __expf(sacc[nt][0] - mn0);
            float p1 = __expf(sacc[nt][1] - mn0);
            float p2 = __expf(sacc[nt][2] - mn1);
            float p3 = __expf(sacc[nt][3] - mn1);
            sacc[nt][0] = p0; sacc[nt][1] = p1;
            sacc[nt][2] = p2; sacc[nt][3] = p3;
            rs0 += p0 + p1;
            rs1 += p2 + p3;
        }
        rs0 += __shfl_xor_sync(0xffffffffu, rs0, 1);
        rs0 += __shfl_xor_sync(0xffffffffu, rs0, 2);
        rs1 += __shfl_xor_sync(0xffffffffu, rs1, 1);
        rs1 += __shfl_xor_sync(0xffffffffu, rs1, 2);
        l0 = l0 * c0 + rs0;  m0 = mn0;
        l1 = l1 * c1 + rs1;  m1 = mn1;
#pragma unroll
        for (int nt = 0; nt < 8; nt++) {
            oacc[nt][0] *= c0; oacc[nt][1] *= c0;
            oacc[nt][2] *= c1; oacc[nt][3] *= c1;
        }

#pragma unroll
        for (int nt = 0; nt < 8; nt++) {
            float2 w0; w0.x = sacc[nt][0]; w0.y = sacc[nt][1];
            float2 w1; w1.x = sacc[nt][2]; w1.y = sacc[nt][3];
            *(float2*)&Pf[fr * PST + nt * 8 + (lane & 3) * 2]       = w0;
            *(float2*)&Pf[(fr + 8) * PST + nt * 8 + (lane & 3) * 2] = w1;
        }
        __syncwarp();

#pragma unroll
        for (int kt = 0; kt < 8; kt++) {
            float a0 = Pf[fr * PST + kt * 8 + fc];
            float a1 = Pf[(fr + 8) * PST + kt * 8 + fc];
            float a2 = Pf[fr * PST + kt * 8 + fc + 4];
            float a3 = Pf[(fr + 8) * PST + kt * 8 + fc + 4];
            uint32_t ahi[4], alo[4];
            ahi[0] = f2tf32(a0); alo[0] = f2tf32(a0 - __uint_as_float(ahi[0]));
            ahi[1] = f2tf32(a1); alo[1] = f2tf32(a1 - __uint_as_float(ahi[1]));
            ahi[2] = f2tf32(a2); alo[2] = f2tf32(a2 - __uint_as_float(ahi[2]));
            ahi[3] = f2tf32(a3); alo[3] = f2tf32(a3 - __uint_as_float(ahi[3]));
#pragma unroll
            for (int nt = 0; nt < 8; nt++) {
                int bn = nt * 8 + (lane >> 2);
                int bk = kt * 8 + (lane & 3);
                uint32_t bh[2], bl[2];
                bh[0] = __float_as_uint(Vhi[bk * VST + bn]);
                bh[1] = __float_as_uint(Vhi[(bk + 4) * VST + bn]);
                bl[0] = __float_as_uint(Vlo[bk * VST + bn]);
                bl[1] = __float_as_uint(Vlo[(bk + 4) * VST + bn]);
                mma_tf32(oacc[nt], ahi, bh, oacc[nt]);
                mma_tf32(oacc[nt], alo, bh, oacc[nt]);
                mma_tf32(oacc[nt], ahi, bl, oacc[nt]);
            }
        }
    }

    // finalize: divide by l, round to tf32 (feeds W1 GEMM), write
    float inv0 = 1.0f / l0, inv1 = 1.0f / l1;
#pragma unroll
    for (int nt = 0; nt < 8; nt++) {
        int col = h * HD + nt * 8 + (lane & 3) * 2;
        float2 w0, w1;
        w0.x = roundtf(oacc[nt][0] * inv0); w0.y = roundtf(oacc[nt][1] * inv0);
        w1.x = roundtf(oacc[nt][2] * inv1); w1.y = roundtf(oacc[nt][3] * inv1);
        *(float2*)&op[(size_t)(qb * 128 + fr) * D_MODEL + col]     = w0;
        *(float2*)&op[(size_t)(qb * 128 + fr + 8) * D_MODEL + col] = w1;
    }
}

// ---------------- launch ---------------------------------------------------
extern "C" void kernel_launch(void* const* d_in, const int* in_sizes, int n_in,
                              void* d_out, int out_size)
{
    const float* X  = (const float*)d_in[0];   // [4096,1024]
    const float* Wq = (const float*)d_in[1];   // [1024,1024]
    const float* Wk = (const float*)d_in[2];   // [1024,256]
    const float* Wv = (const float*)d_in[3];   // [1024,256]
    const float* W1 = (const float*)d_in[4];   // [1024,4096]
    const float* W2 = (const float*)d_in[5];   // [4096,1024]
    float* out = (float*)d_out;

    float *gq, *gk, *gv, *ga, *gh;
    float *gxt, *gwqt, *gwkt, *gwvt, *gw1t, *gw2t;
    cudaGetSymbolAddress((void**)&gq, g_q);
    cudaGetSymbolAddress((void**)&gk, g_k);
    cudaGetSymbolAddress((void**)&gv, g_v);
    cudaGetSymbolAddress((void**)&ga, g_attn);
    cudaGetSymbolAddress((void**)&gh, g_h1);
    cudaGetSymbolAddress((void**)&gxt, g_xt);
    cudaGetSymbolAddress((void**)&gwqt, g_wqt);
    cudaGetSymbolAddress((void**)&gwkt, g_wkt);
    cudaGetSymbolAddress((void**)&gwvt, g_wvt);
    cudaGetSymbolAddress((void**)&gw1t, g_w1t);
    cudaGetSymbolAddress((void**)&gw2t, g_w2t);

    cudaFuncSetAttribute(attn_mma_kernel,
                         cudaFuncAttributeMaxDynamicSharedMemorySize, ATT_SMEM);
    cudaFuncSetAttribute(qkv_kernel,
                         cudaFuncAttributeMaxDynamicSharedMemorySize, GEMM_SMEM);
    cudaFuncSetAttribute(tgemm2_kernel<1, 1>,
                         cudaFuncAttributeMaxDynamicSharedMemorySize, GEMM_SMEM);
    cudaFuncSetAttribute(tgemm2_kernel<0, 0>,
                         cudaFuncAttributeMaxDynamicSharedMemorySize, GEMM_SMEM);

    // pre-round all GEMM operands to tf32
    round_tf32_kernel<<<(T_SEQ * D_MODEL / 4 + 255) / 256, 256>>>(X,  gxt,  T_SEQ * D_MODEL / 4);
    round_tf32_kernel<<<(D_MODEL * D_MODEL / 4 + 255) / 256, 256>>>(Wq, gwqt, D_MODEL * D_MODEL / 4);
    round_tf32_kernel<<<(D_MODEL * 256 / 4 + 255) / 256, 256>>>(Wk, gwkt, D_MODEL * 256 / 4);
    round_tf32_kernel<<<(D_MODEL * 256 / 4 + 255) / 256, 256>>>(Wv, gwvt, D_MODEL * 256 / 4);
    round_tf32_kernel<<<(D_MODEL * D_FF / 4 + 255) / 256, 256>>>(W1, gw1t, D_MODEL * D_FF / 4);
    round_tf32_kernel<<<(D_FF * D_MODEL / 4 + 255) / 256, 256>>>(W2, gw2t, D_FF * D_MODEL / 4);

    rope_table_kernel<<<T_SEQ, 32>>>();

    // fused QKV projection
    qkv_kernel<<<dim3(12, T_SEQ / 128), 256, GEMM_SMEM>>>(
        gxt, gwqt, gwkt, gwvt, gq, gk, gv);

    // RoPE on q and k
    rope_apply_kernel<<<T_SEQ, NH * 32>>>(gq, NH);
    rope_apply_kernel<<<T_SEQ, NKV * 32>>>(gk, NKV);

    // causal flash attention on tensor cores
    attn_mma_kernel<<<dim3(T_SEQ / 128, NH), 256, ATT_SMEM>>>(gq, gk, gv, ga);

    // MLP
    tgemm2_kernel<1, 1><<<dim3(D_FF / 128, T_SEQ / 128), 256, GEMM_SMEM>>>(
        ga, gw1t, gh, D_FF, D_MODEL);
    tgemm2_kernel<0, 0><<<dim3(D_MODEL / 128, T_SEQ / 128), 256, GEMM_SMEM>>>(
        gh, gw2t, out, D_MODEL, D_FF);
}

// round 5
// speedup vs baseline: 3.0496x; 1.2971x over previous
#include <cuda_runtime.h>
#include <cuda_bf16.h>
#include <math.h>
#include <stdint.h>

// Problem constants
#define T_SEQ  4096
#define D_MODEL 1024
#define NH     16
#define NKV    4
#define HD     64
#define D_FF   4096

// ---------------- scratch (device globals; no allocation allowed) ----------
__device__ float g_q[T_SEQ * D_MODEL];          // 16 MB
__device__ float g_k[T_SEQ * NKV * HD];         // 4 MB  [token][256]
__device__ float g_v[NKV * HD * T_SEQ];         // 4 MB  TRANSPOSED [256][4096]
__device__ float g_attn[T_SEQ * D_MODEL];       // 16 MB (tf32-rounded)
__device__ float g_h1[(size_t)T_SEQ * D_FF];    // 64 MB (tf32-rounded)
__device__ float g_cos[T_SEQ * 32];
__device__ float g_sin[T_SEQ * 32];
// tf32-pre-rounded operands
__device__ float g_xt[T_SEQ * D_MODEL];
__device__ float g_wqt[D_MODEL * D_MODEL];
__device__ float g_wkt[D_MODEL * NKV * HD];
__device__ float g_wvt[D_MODEL * NKV * HD];
__device__ float g_w1t[D_MODEL * D_FF];
__device__ float g_w2t[D_FF * D_MODEL];

// ---------------- helpers ---------------------------------------------------
__device__ __forceinline__ uint32_t f2tf32(float x) {
    uint32_t r;
    asm("cvt.rna.tf32.f32 %0, %1;" : "=r"(r) : "f"(x));
    return r;
}
__device__ __forceinline__ float roundtf(float x) {
    return __uint_as_float(f2tf32(x));
}

__device__ __forceinline__ void mma_tf32(float* d, const uint32_t* a,
                                         const uint32_t* b, const float* c) {
    asm volatile(
        "mma.sync.aligned.m16n8k8.row.col.f32.tf32.tf32.f32 "
        "{%0,%1,%2,%3}, {%4,%5,%6,%7}, {%8,%9}, {%10,%11,%12,%13};"
        : "=f"(d[0]), "=f"(d[1]), "=f"(d[2]), "=f"(d[3])
        : "r"(a[0]), "r"(a[1]), "r"(a[2]), "r"(a[3]),
          "r"(b[0]), "r"(b[1]),
          "f"(c[0]), "f"(c[1]), "f"(c[2]), "f"(c[3]));
}

__device__ __forceinline__ void mma_bf16(float* d, const uint32_t* a,
                                         const uint32_t* b, const float* c) {
    asm volatile(
        "mma.sync.aligned.m16n8k16.row.col.f32.bf16.bf16.f32 "
        "{%0,%1,%2,%3}, {%4,%5,%6,%7}, {%8,%9}, {%10,%11,%12,%13};"
        : "=f"(d[0]), "=f"(d[1]), "=f"(d[2]), "=f"(d[3])
        : "r"(a[0]), "r"(a[1]), "r"(a[2]), "r"(a[3]),
          "r"(b[0]), "r"(b[1]),
          "f"(c[0]), "f"(c[1]), "f"(c[2]), "f"(c[3]));
}

// pack two floats as bf16x2 (x -> low half), plus residual-lo word
__device__ __forceinline__ uint32_t packbf(float x, float y) {
    __nv_bfloat162 t = __floats2bfloat162_rn(x, y);
    return *(uint32_t*)&t;
}
__device__ __forceinline__ void splitbf(float x, float y,
                                        uint32_t& hi, uint32_t& lo) {
    __nv_bfloat16 hx = __float2bfloat16_rn(x);
    __nv_bfloat16 hy = __float2bfloat16_rn(y);
    hi = packbf(__bfloat162float(hx), __bfloat162float(hy));
    // recompute via pack of residuals
    lo = packbf(x - __bfloat162float(hx), y - __bfloat162float(hy));
}

__device__ __forceinline__ void cp16(float* smem_dst, const float* g) {
    uint32_t a = (uint32_t)__cvta_generic_to_shared(smem_dst);
    asm volatile("cp.async.ca.shared.global [%0], [%1], 16;" :: "r"(a), "l"(g));
}

// ---------------- pre-round pass -------------------------------------------
__global__ void round_tf32_kernel(const float* __restrict__ in,
                                  float* __restrict__ out, int n4) {
    int i = blockIdx.x * 256 + threadIdx.x;
    if (i < n4) {
        float4 v = ((const float4*)in)[i];
        v.x = roundtf(v.x); v.y = roundtf(v.y);
        v.z = roundtf(v.z); v.w = roundtf(v.w);
        ((float4*)out)[i] = v;
    }
}

// ---------------- RoPE ------------------------------------------------------
__global__ void rope_table_kernel() {
    int t = blockIdx.x, i = threadIdx.x;
    float inv = 1.0f / powf(10000.0f, (float)(2 * i) / 64.0f);
    float ang = (float)t * inv;
    g_cos[t * 32 + i] = cosf(ang);
    g_sin[t * 32 + i] = sinf(ang);
}

__global__ void rope_apply_kernel(float* __restrict__ x, int nh) {
    int t = blockIdx.x;
    int h = threadIdx.x >> 5;
    int i = threadIdx.x & 31;
    float c = g_cos[t * 32 + i];
    float s = g_sin[t * 32 + i];
    float* p = x + (size_t)t * nh * HD + h * HD;
    float x1 = p[i], x2 = p[i + 32];
    p[i]      = x1 * c - x2 * s;
    p[i + 32] = x2 * c + x1 * s;
}

// ---------------- cp.async pipelined tf32 GEMM ------------------------------
#define AS_ST 20
#define BS_ST 136
#define AS_STAGE (128 * AS_ST)
#define BS_STAGE (16 * BS_ST)
#define GEMM_SMEM ((4 * (AS_STAGE + BS_STAGE)) * 4)

template <int SILU, int ROUND, int TRANSC>
__device__ __forceinline__ void gemm_body(
    const float* __restrict__ A, const float* __restrict__ B,
    float* __restrict__ C, int N, int K, int rowBase, int colBase)
{
    extern __shared__ float smp[];
    float* As = smp;
    float* Bs = smp + 4 * AS_STAGE;

    int tid  = threadIdx.x;
    int lane = tid & 31;
    int warp = tid >> 5;
    int wm = (warp & 1) * 64;
    int wn = (warp >> 1) * 32;

    int ar  = tid >> 2;
    int ac  = (tid & 3) << 2;
    int bkr = tid >> 5;
    int bc  = (tid & 31) << 2;

    const float* Ag0 = A + (size_t)(rowBase + ar) * K + ac;
    const float* Ag1 = A + (size_t)(rowBase + 64 + ar) * K + ac;
    const float* Bg  = B + colBase + bc;

    int nk = K >> 4;

#pragma unroll
    for (int s = 0; s < 3; s++) {
        if (s < nk) {
            float* as = As + s * AS_STAGE;
            float* bs = Bs + s * BS_STAGE;
            int k0 = s << 4;
            cp16(as + ar * AS_ST + ac,        Ag0 + k0);
            cp16(as + (ar + 64) * AS_ST + ac, Ag1 + k0);
            cp16(bs + bkr * BS_ST + bc,       Bg + (size_t)(k0 + bkr) * N);
            cp16(bs + (bkr + 8) * BS_ST + bc, Bg + (size_t)(k0 + 8 + bkr) * N);
        }
        asm volatile("cp.async.commit_group;");
    }

    float acc[4][4][4];
#pragma unroll
    for (int i = 0; i < 4; i++)
#pragma unroll
        for (int j = 0; j < 4; j++)
#pragma unroll
            for (int q = 0; q < 4; q++) acc[i][j][q] = 0.0f;

    for (int kt = 0; kt < nk; kt++) {
        asm volatile("cp.async.wait_group 2;");
        __syncthreads();

        int nx = kt + 3;
        if (nx < nk) {
            int bufn = nx & 3;
            float* as = As + bufn * AS_STAGE;
            float* bs = Bs + bufn * BS_STAGE;
            int k0 = nx << 4;
            cp16(as + ar * AS_ST + ac,        Ag0 + k0);
            cp16(as + (ar + 64) * AS_ST + ac, Ag1 + k0);
            cp16(bs + bkr * BS_ST + bc,       Bg + (size_t)(k0 + bkr) * N);
            cp16(bs + (bkr + 8) * BS_ST + bc, Bg + (size_t)(k0 + 8 + bkr) * N);
        }
        asm volatile("cp.async.commit_group;");

        const float* as = As + (kt & 3) * AS_STAGE;
        const float* bs = Bs + (kt & 3) * BS_STAGE;
#pragma unroll
        for (int ks = 0; ks < 16; ks += 8) {
            uint32_t af[4][4], bf[4][2];
#pragma unroll
            for (int i = 0; i < 4; i++) {
                int r = wm + i * 16 + (lane >> 2);
                int c = ks + (lane & 3);
                af[i][0] = __float_as_uint(as[r * AS_ST + c]);
                af[i][1] = __float_as_uint(as[(r + 8) * AS_ST + c]);
                af[i][2] = __float_as_uint(as[r * AS_ST + c + 4]);
                af[i][3] = __float_as_uint(as[(r + 8) * AS_ST + c + 4]);
            }
#pragma unroll
            for (int j = 0; j < 4; j++) {
                int kk = ks + (lane & 3);
                int n  = wn + j * 8 + (lane >> 2);
                bf[j][0] = __float_as_uint(bs[kk * BS_ST + n]);
                bf[j][1] = __float_as_uint(bs[(kk + 4) * BS_ST + n]);
            }
#pragma unroll
            for (int i = 0; i < 4; i++)
#pragma unroll
                for (int j = 0; j < 4; j++)
                    mma_tf32(acc[i][j], af[i], bf[j], acc[i][j]);
        }
    }

#pragma unroll
    for (int i = 0; i < 4; i++) {
        int r0 = rowBase + wm + i * 16 + (lane >> 2);
#pragma unroll
        for (int j = 0; j < 4; j++) {
            int c0 = colBase + wn + j * 8 + (lane & 3) * 2;
            float2 v0, v1;
            v0.x = acc[i][j][0]; v0.y = acc[i][j][1];
            v1.x = acc[i][j][2]; v1.y = acc[i][j][3];
            if (SILU) {
                v0.x = v0.x / (1.0f + expf(-v0.x));
                v0.y = v0.y / (1.0f + expf(-v0.y));
                v1.x = v1.x / (1.0f + expf(-v1.x));
                v1.y = v1.y / (1.0f + expf(-v1.y));
            }
            if (ROUND) {
                v0.x = roundtf(v0.x); v0.y = roundtf(v0.y);
                v1.x = roundtf(v1.x); v1.y = roundtf(v1.y);
            }
            if (TRANSC) {
                // transposed output: C[col][row], ld = T_SEQ
                C[(size_t)c0 * T_SEQ + r0]           = v0.x;
                C[(size_t)(c0 + 1) * T_SEQ + r0]     = v0.y;
                C[(size_t)c0 * T_SEQ + r0 + 8]       = v1.x;
                C[(size_t)(c0 + 1) * T_SEQ + r0 + 8] = v1.y;
            } else {
                *(float2*)&C[(size_t)r0 * N + c0]       = v0;
                *(float2*)&C[(size_t)(r0 + 8) * N + c0] = v1;
            }
        }
    }
}

template <int SILU, int ROUND>
__global__ void __launch_bounds__(256) tgemm2_kernel(
    const float* __restrict__ A, const float* __restrict__ B,
    float* __restrict__ C, int N, int K)
{
    gemm_body<SILU, ROUND, 0>(A, B, C, N, K, blockIdx.y * 128, blockIdx.x * 128);
}

// fused QKV: grid.x = 12 (8 Wq cols, 2 Wk, 2 Wv); V written transposed
__global__ void __launch_bounds__(256) qkv_kernel(
    const float* __restrict__ Xt,
    const float* __restrict__ Wqt, const float* __restrict__ Wkt,
    const float* __restrict__ Wvt,
    float* __restrict__ q, float* __restrict__ k, float* __restrict__ v)
{
    int bx = blockIdx.x;
    if (bx < 8) {
        gemm_body<0, 0, 0>(Xt, Wqt, q, D_MODEL, D_MODEL,
                           blockIdx.y * 128, bx * 128);
    } else if (bx < 10) {
        gemm_body<0, 0, 0>(Xt, Wkt, k, NKV * HD, D_MODEL,
                           blockIdx.y * 128, (bx - 8) * 128);
    } else {
        gemm_body<0, 0, 1>(Xt, Wvt, v, NKV * HD, D_MODEL,
                           blockIdx.y * 128, (bx - 10) * 128);
    }
}

// ---------------- bf16 MMA flash attention (causal, GQA, d=64, 3-term) -----
// BM=128, BN=64, 8 warps. K (token-major) and V^T (dim-major) split hi/lo
// into bf16x2 smem at uint32 stride 36 (conflict-free fragment reads).
#define KVST 36

__global__ void __launch_bounds__(256) attn_bf16_kernel(
    const float* __restrict__ qp, const float* __restrict__ kp,
    const float* __restrict__ vtp, float* __restrict__ op)
{
    __shared__ uint32_t smu[4 * 64 * KVST];   // 36864 B
    uint32_t* Khi = smu;
    uint32_t* Klo = smu + 64 * KVST;
    uint32_t* Vhi = smu + 2 * 64 * KVST;
    uint32_t* Vlo = smu + 3 * 64 * KVST;
    float* Qs = (float*)smu;                  // Q staging (32 KB), pre-loop only

    int qb   = gridDim.x - 1 - blockIdx.x;    // heavy blocks first
    int h    = blockIdx.y;
    int kvh  = h >> 2;
    int tid  = threadIdx.x;
    int lane = tid & 31;
    int warp = tid >> 5;
    int gid  = lane >> 2;        // 0..7
    int tig  = lane & 3;         // 0..3
    int tg2  = tig * 2;
    int fr   = warp * 16 + gid;  // fragment row (first of pair)

    // ---- stage Q tile ----
#pragma unroll
    for (int i = 0; i < 8; i++) {
        int e = tid + 256 * i;
        int r = e >> 4, c4 = (e & 15) << 2;
        *(float4*)&Qs[r * 64 + c4] =
            *(const float4*)&qp[(size_t)(qb * 128 + r) * D_MODEL + h * HD + c4];
    }
    __syncthreads();

    // ---- extract Q fragments (scaled 1/8), split hi/lo, pack bf16x2 ----
    uint32_t qhi[4][4], qlo[4][4];
#pragma unroll
    for (int kt = 0; kt < 4; kt++) {
        float2 x0 = *(float2*)&Qs[fr * 64 + kt * 16 + tg2];
        float2 x1 = *(float2*)&Qs[(fr + 8) * 64 + kt * 16 + tg2];
        float2 x2 = *(float2*)&Qs[fr * 64 + kt * 16 + tg2 + 8];
        float2 x3 = *(float2*)&Qs[(fr + 8) * 64 + kt * 16 + tg2 + 8];
        splitbf(x0.x * 0.125f, x0.y * 0.125f, qhi[kt][0], qlo[kt][0]);
        splitbf(x1.x * 0.125f, x1.y * 0.125f, qhi[kt][1], qlo[kt][1]);
        splitbf(x2.x * 0.125f, x2.y * 0.125f, qhi[kt][2], qlo[kt][2]);
        splitbf(x3.x * 0.125f, x3.y * 0.125f, qhi[kt][3], qlo[kt][3]);
    }

    float oacc[8][4];
#pragma unroll
    for (int nt = 0; nt < 8; nt++)
#pragma unroll
        for (int j = 0; j < 4; j++) oacc[nt][j] = 0.0f;
    float m0 = -1e30f, m1 = -1e30f, l0 = 0.0f, l1 = 0.0f;

    int kbmax = 2 * qb + 1;
    for (int kb = 0; kb <= kbmax; kb++) {
        __syncthreads();   // prior-iter reads done (also covers Q staging)

        // ---- load K / V^T tile, split hi/lo, pack ----
        int kbase = kb * 64;
#pragma unroll
        for (int i = 0; i < 4; i++) {
            int e = tid + 256 * i;
            int r = e >> 4, c4 = (e & 15) << 2;
            float4 kk = *(const float4*)&kp[(size_t)(kbase + r) * (NKV * HD) + kvh * HD + c4];
            float4 vv = *(const float4*)&vtp[(size_t)(kvh * HD + r) * T_SEQ + kbase + c4];
            int w = r * KVST + (c4 >> 1);
            splitbf(kk.x, kk.y, Khi[w],     Klo[w]);
            splitbf(kk.z, kk.w, Khi[w + 1], Klo[w + 1]);
            splitbf(vv.x, vv.y, Vhi[w],     Vlo[w]);
            splitbf(vv.z, vv.w, Vhi[w + 1], Vlo[w + 1]);
        }
        __syncthreads();

        // ---- S = (Q/8) @ K^T : 3-term bf16 ----
        float sacc[8][4];
#pragma unroll
        for (int nt = 0; nt < 8; nt++)
#pragma unroll
            for (int j = 0; j < 4; j++) sacc[nt][j] = 0.0f;

#pragma unroll
        for (int nt = 0; nt < 8; nt++) {
            int base = (nt * 8 + gid) * KVST;
#pragma unroll
            for (int ks = 0; ks < 4; ks++) {
                uint32_t bh[2], bl[2];
                bh[0] = Khi[base + ks * 8 + tig];
                bh[1] = Khi[base + ks * 8 + tig + 4];
                bl[0] = Klo[base + ks * 8 + tig];
                bl[1] = Klo[base + ks * 8 + tig + 4];
                mma_bf16(sacc[nt], qhi[ks], bh, sacc[nt]);
                mma_bf16(sacc[nt], qlo[ks], bh, sacc[nt]);
                mma_bf16(sacc[nt], qhi[ks], bl, sacc[nt]);
            }
        }

        // ---- causal mask ----
        if (kb >= 2 * qb) {
            int grow0 = qb * 128 + fr;
            int grow1 = grow0 + 8;
#pragma unroll
            for (int nt = 0; nt < 8; nt++) {
                int gc = kb * 64 + nt * 8 + tg2;
                if (gc     > grow0) sacc[nt][0] = -1e30f;
                if (gc + 1 > grow0) sacc[nt][1] = -1e30f;
                if (gc     > grow1) sacc[nt][2] = -1e30f;
                if (gc + 1 > grow1) sacc[nt][3] = -1e30f;
            }
        }

        // ---- online softmax ----
        float mx0 = -1e30f, mx1 = -1e30f;
#pragma unroll
        for (int nt = 0; nt < 8; nt++) {
            mx0 = fmaxf(mx0, fmaxf(sacc[nt][0], sacc[nt][1]));
            mx1 = fmaxf(mx1, fmaxf(sacc[nt][2], sacc[nt][3]));
        }
        mx0 = fmaxf(mx0, __shfl_xor_sync(0xffffffffu, mx0, 1));
        mx0 = fmaxf(mx0, __shfl_xor_sync(0xffffffffu, mx0, 2));
        mx1 = fmaxf(mx1, __shfl_xor_sync(0xffffffffu, mx1, 1));
        mx1 = fmaxf(mx1, __shfl_xor_sync(0xffffffffu, mx1, 2));

        float mn0 = fmaxf(m0, mx0), mn1 = fmaxf(m1, mx1);
        float c0 = __expf(m0 - mn0), c1 = __expf(m1 - mn1);
        float rs0 = 0.0f, rs1 = 0.0f;
#pragma unroll
        for (int nt = 0; nt < 8; nt++) {
            float p0 = __expf(sacc[nt][0] - mn0);
            float p1 = __expf(sacc[nt][1] - mn0);
            float p2 = __expf(sacc[nt][2] - mn1);
            float p3 = __expf(sacc[nt][3] - mn1);
            sacc[nt][0] = p0; sacc[nt][1] = p1;
            sacc[nt][2] = p2; sacc[nt][3] = p3;
            rs0 += p0 + p1;
            rs1 += p2 + p3;
        }
        rs0 += __shfl_xor_sync(0xffffffffu, rs0, 1);
        rs0 += __shfl_xor_sync(0xffffffffu, rs0, 2);
        rs1 += __shfl_xor_sync(0xffffffffu, rs1, 1);
        rs1 += __shfl_xor_sync(0xffffffffu, rs1, 2);
        l0 = l0 * c0 + rs0;  m0 = mn0;
        l1 = l1 * c1 + rs1;  m1 = mn1;
#pragma unroll
        for (int nt = 0; nt < 8; nt++) {
            oacc[nt][0] *= c0; oacc[nt][1] *= c0;
            oacc[nt][2] *= c1; oacc[nt][3] *= c1;
        }

        // ---- O += P @ V : A-fragments straight from sacc registers ----
#pragma unroll
        for (int kt = 0; kt < 4; kt++) {
            uint32_t ahi[4], alo[4];
            splitbf(sacc[2*kt][0],     sacc[2*kt][1],     ahi[0], alo[0]);
            splitbf(sacc[2*kt][2],     sacc[2*kt][3],     ahi[1], alo[1]);
            splitbf(sacc[2*kt + 1][0], sacc[2*kt + 1][1], ahi[2], alo[2]);
            splitbf(sacc[2*kt + 1][2], sacc[2*kt + 1][3], ahi[3], alo[3]);
#pragma unroll
            for (int nt = 0; nt < 8; nt++) {
                int base = (nt * 8 + gid) * KVST;
                uint32_t bh[2], bl[2];
                bh[0] = Vhi[base + kt * 8 + tig];
                bh[1] = Vhi[base + kt * 8 + tig + 4];
                bl[0] = Vlo[base + kt * 8 + tig];
                bl[1] = Vlo[base + kt * 8 + tig + 4];
                mma_bf16(oacc[nt], ahi, bh, oacc[nt]);
                mma_bf16(oacc[nt], alo, bh, oacc[nt]);
                mma_bf16(oacc[nt], ahi, bl, oacc[nt]);
            }
        }
    }

    // ---- finalize: divide by l, round to tf32 (feeds W1 GEMM), write ----
    float inv0 = 1.0f / l0, inv1 = 1.0f / l1;
#pragma unroll
    for (int nt = 0; nt < 8; nt++) {
        int col = h * HD + nt * 8 + tg2;
        float2 w0, w1;
        w0.x = roundtf(oacc[nt][0] * inv0); w0.y = roundtf(oacc[nt][1] * inv0);
        w1.x = roundtf(oacc[nt][2] * inv1); w1.y = roundtf(oacc[nt][3] * inv1);
        *(float2*)&op[(size_t)(qb * 128 + fr) * D_MODEL + col]     = w0;
        *(float2*)&op[(size_t)(qb * 128 + fr + 8) * D_MODEL + col] = w1;
    }
}

// ---------------- launch ---------------------------------------------------
extern "C" void kernel_launch(void* const* d_in, const int* in_sizes, int n_in,
                              void* d_out, int out_size)
{
    const float* X  = (const float*)d_in[0];
    const float* Wq = (const float*)d_in[1];
    const float* Wk = (const float*)d_in[2];
    const float* Wv = (const float*)d_in[3];
    const float* W1 = (const float*)d_in[4];
    const float* W2 = (const float*)d_in[5];
    float* out = (float*)d_out;

    float *gq, *gk, *gv, *ga, *gh;
    float *gxt, *gwqt, *gwkt, *gwvt, *gw1t, *gw2t;
    cudaGetSymbolAddress((void**)&gq, g_q);
    cudaGetSymbolAddress((void**)&gk, g_k);
    cudaGetSymbolAddress((void**)&gv, g_v);
    cudaGetSymbolAddress((void**)&ga, g_attn);
    cudaGetSymbolAddress((void**)&gh, g_h1);
    cudaGetSymbolAddress((void**)&gxt, g_xt);
    cudaGetSymbolAddress((void**)&gwqt, g_wqt);
    cudaGetSymbolAddress((void**)&gwkt, g_wkt);
    cudaGetSymbolAddress((void**)&gwvt, g_wvt);
    cudaGetSymbolAddress((void**)&gw1t, g_w1t);
    cudaGetSymbolAddress((void**)&gw2t, g_w2t);

    cudaFuncSetAttribute(qkv_kernel,
                         cudaFuncAttributeMaxDynamicSharedMemorySize, GEMM_SMEM);
    cudaFuncSetAttribute(tgemm2_kernel<1, 1>,
                         cudaFuncAttributeMaxDynamicSharedMemorySize, GEMM_SMEM);
    cudaFuncSetAttribute(tgemm2_kernel<0, 0>,
                         cudaFuncAttributeMaxDynamicSharedMemorySize, GEMM_SMEM);

    // pre-round all GEMM operands to tf32
    round_tf32_kernel<<<(T_SEQ * D_MODEL / 4 + 255) / 256, 256>>>(X,  gxt,  T_SEQ * D_MODEL / 4);
    round_tf32_kernel<<<(D_MODEL * D_MODEL / 4 + 255) / 256, 256>>>(Wq, gwqt, D_MODEL * D_MODEL / 4);
    round_tf32_kernel<<<(D_MODEL * 256 / 4 + 255) / 256, 256>>>(Wk, gwkt, D_MODEL * 256 / 4);
    round_tf32_kernel<<<(D_MODEL * 256 / 4 + 255) / 256, 256>>>(Wv, gwvt, D_MODEL * 256 / 4);
    round_tf32_kernel<<<(D_MODEL * D_FF / 4 + 255) / 256, 256>>>(W1, gw1t, D_MODEL * D_FF / 4);
    round_tf32_kernel<<<(D_FF * D_MODEL / 4 + 255) / 256, 256>>>(W2, gw2t, D_FF * D_MODEL / 4);

    rope_table_kernel<<<T_SEQ, 32>>>();

    // fused QKV projection (V written transposed)
    qkv_kernel<<<dim3(12, T_SEQ / 128), 256, GEMM_SMEM>>>(
        gxt, gwqt, gwkt, gwvt, gq, gk, gv);

    // RoPE on q and k (V needs none)
    rope_apply_kernel<<<T_SEQ, NH * 32>>>(gq, NH);
    rope_apply_kernel<<<T_SEQ, NKV * 32>>>(gk, NKV);

    // causal flash attention, bf16 tensor cores
    attn_bf16_kernel<<<dim3(T_SEQ / 128, NH), 256>>>(gq, gk, gv, ga);

    // MLP
    tgemm2_kernel<1, 1><<<dim3(D_FF / 128, T_SEQ / 128), 256, GEMM_SMEM>>>(
        ga, gw1t, gh, D_FF, D_MODEL);
    tgemm2_kernel<0, 0><<<dim3(D_MODEL / 128, T_SEQ / 128), 256, GEMM_SMEM>>>(
        gh, gw2t, out, D_MODEL, D_FF);
}

// round 6
// speedup vs baseline: 3.1374x; 1.0288x over previous
#include <cuda_runtime.h>
#include <cuda_bf16.h>
#include <math.h>
#include <stdint.h>

// Problem constants
#define T_SEQ  4096
#define D_MODEL 1024
#define NH     16
#define NKV    4
#define HD     64
#define D_FF   4096

// ---------------- scratch (device globals; no allocation allowed) ----------
__device__ float g_q[T_SEQ * D_MODEL];          // 16 MB
__device__ float g_k[T_SEQ * NKV * HD];         // 4 MB  [token][256] (pre-rope)
__device__ float g_v[NKV * HD * T_SEQ];         // 4 MB  TRANSPOSED [256][4096]
__device__ float g_attn[T_SEQ * D_MODEL];       // 16 MB (tf32-rounded)
__device__ float g_h1[(size_t)T_SEQ * D_FF];    // 64 MB (tf32-rounded)
__device__ float g_cos[T_SEQ * 32];
__device__ float g_sin[T_SEQ * 32];
// tf32-pre-rounded operands
__device__ float g_xt[T_SEQ * D_MODEL];
__device__ float g_wqt[D_MODEL * D_MODEL];
__device__ float g_wkt[D_MODEL * NKV * HD];
__device__ float g_wvt[D_MODEL * NKV * HD];
__device__ float g_w1t[D_MODEL * D_FF];
__device__ float g_w2t[D_FF * D_MODEL];
// pre-split bf16 hi/lo packed K (post-rope) and V^T
__device__ uint32_t g_khp[T_SEQ * 128];         // [token][kvh*32 + d2]
__device__ uint32_t g_klp[T_SEQ * 128];
__device__ uint32_t g_vhp[NKV * HD * (T_SEQ / 2)];  // [dim][token-pair]
__device__ uint32_t g_vlp[NKV * HD * (T_SEQ / 2)];

// ---------------- helpers ---------------------------------------------------
__device__ __forceinline__ uint32_t f2tf32(float x) {
    uint32_t r;
    asm("cvt.rna.tf32.f32 %0, %1;" : "=r"(r) : "f"(x));
    return r;
}
__device__ __forceinline__ float roundtf(float x) {
    return __uint_as_float(f2tf32(x));
}

__device__ __forceinline__ void mma_tf32(float* d, const uint32_t* a,
                                         const uint32_t* b, const float* c) {
    asm volatile(
        "mma.sync.aligned.m16n8k8.row.col.f32.tf32.tf32.f32 "
        "{%0,%1,%2,%3}, {%4,%5,%6,%7}, {%8,%9}, {%10,%11,%12,%13};"
        : "=f"(d[0]), "=f"(d[1]), "=f"(d[2]), "=f"(d[3])
        : "r"(a[0]), "r"(a[1]), "r"(a[2]), "r"(a[3]),
          "r"(b[0]), "r"(b[1]),
          "f"(c[0]), "f"(c[1]), "f"(c[2]), "f"(c[3]));
}

__device__ __forceinline__ void mma_bf16(float* d, const uint32_t* a,
                                         const uint32_t* b, const float* c) {
    asm volatile(
        "mma.sync.aligned.m16n8k16.row.col.f32.bf16.bf16.f32 "
        "{%0,%1,%2,%3}, {%4,%5,%6,%7}, {%8,%9}, {%10,%11,%12,%13};"
        : "=f"(d[0]), "=f"(d[1]), "=f"(d[2]), "=f"(d[3])
        : "r"(a[0]), "r"(a[1]), "r"(a[2]), "r"(a[3]),
          "r"(b[0]), "r"(b[1]),
          "f"(c[0]), "f"(c[1]), "f"(c[2]), "f"(c[3]));
}

__device__ __forceinline__ uint32_t packbf(float x, float y) {
    __nv_bfloat162 t = __floats2bfloat162_rn(x, y);
    return *(uint32_t*)&t;
}
__device__ __forceinline__ void splitbf(float x, float y,
                                        uint32_t& hi, uint32_t& lo) {
    __nv_bfloat16 hx = __float2bfloat16_rn(x);
    __nv_bfloat16 hy = __float2bfloat16_rn(y);
    hi = packbf(__bfloat162float(hx), __bfloat162float(hy));
    lo = packbf(x - __bfloat162float(hx), y - __bfloat162float(hy));
}

__device__ __forceinline__ void cp16(float* smem_dst, const float* g) {
    uint32_t a = (uint32_t)__cvta_generic_to_shared(smem_dst);
    asm volatile("cp.async.ca.shared.global [%0], [%1], 16;" :: "r"(a), "l"(g));
}
__device__ __forceinline__ void cp16u(uint32_t* smem_dst, const uint32_t* g) {
    uint32_t a = (uint32_t)__cvta_generic_to_shared(smem_dst);
    asm volatile("cp.async.ca.shared.global [%0], [%1], 16;" :: "r"(a), "l"(g));
}

// ---------------- pre-round pass -------------------------------------------
__global__ void round_tf32_kernel(const float* __restrict__ in,
                                  float* __restrict__ out, int n4) {
    int i = blockIdx.x * 256 + threadIdx.x;
    if (i < n4) {
        float4 v = ((const float4*)in)[i];
        v.x = roundtf(v.x); v.y = roundtf(v.y);
        v.z = roundtf(v.z); v.w = roundtf(v.w);
        ((float4*)out)[i] = v;
    }
}

// ---------------- RoPE ------------------------------------------------------
__global__ void rope_table_kernel() {
    int t = blockIdx.x, i = threadIdx.x;
    float inv = 1.0f / powf(10000.0f, (float)(2 * i) / 64.0f);
    float ang = (float)t * inv;
    g_cos[t * 32 + i] = cosf(ang);
    g_sin[t * 32 + i] = sinf(ang);
}

__global__ void rope_apply_kernel(float* __restrict__ x, int nh) {
    int t = blockIdx.x;
    int h = threadIdx.x >> 5;
    int i = threadIdx.x & 31;
    float c = g_cos[t * 32 + i];
    float s = g_sin[t * 32 + i];
    float* p = x + (size_t)t * nh * HD + h * HD;
    float x1 = p[i], x2 = p[i + 32];
    p[i]      = x1 * c - x2 * s;
    p[i + 32] = x2 * c + x1 * s;
}

// rope K + split to packed bf16 hi/lo (one token per block, 4 heads x 32)
__global__ void rope_split_k_kernel() {
    __shared__ float buf[NKV][64];
    int t = blockIdx.x;
    int h = threadIdx.x >> 5;
    int i = threadIdx.x & 31;
    float c = g_cos[t * 32 + i];
    float s = g_sin[t * 32 + i];
    const float* p = g_k + (size_t)t * (NKV * HD) + h * HD;
    float x1 = p[i], x2 = p[i + 32];
    buf[h][i]      = x1 * c - x2 * s;
    buf[h][i + 32] = x2 * c + x1 * s;
    __syncthreads();
    float a = buf[h][2 * i], b = buf[h][2 * i + 1];
    uint32_t hi, lo;
    splitbf(a, b, hi, lo);
    g_khp[t * 128 + h * 32 + i] = hi;
    g_klp[t * 128 + h * 32 + i] = lo;
}

// split transposed V into packed bf16 hi/lo pairs along tokens
__global__ void split_v_kernel() {
    int idx = blockIdx.x * 256 + threadIdx.x;   // 0 .. 524287
    float2 v = *(const float2*)&g_v[(size_t)idx * 2];
    uint32_t hi, lo;
    splitbf(v.x, v.y, hi, lo);
    g_vhp[idx] = hi;
    g_vlp[idx] = lo;
}

// ---------------- cp.async pipelined tf32 GEMM ------------------------------
#define AS_ST 20
#define BS_ST 136
#define AS_STAGE (128 * AS_ST)
#define BS_STAGE (16 * BS_ST)
#define GEMM_SMEM ((4 * (AS_STAGE + BS_STAGE)) * 4)

template <int SILU, int ROUND, int TRANSC>
__device__ __forceinline__ void gemm_body(
    const float* __restrict__ A, const float* __restrict__ B,
    float* __restrict__ C, int N, int K, int rowBase, int colBase)
{
    extern __shared__ float smp[];
    float* As = smp;
    float* Bs = smp + 4 * AS_STAGE;

    int tid  = threadIdx.x;
    int lane = tid & 31;
    int warp = tid >> 5;
    int wm = (warp & 1) * 64;
    int wn = (warp >> 1) * 32;

    int ar  = tid >> 2;
    int ac  = (tid & 3) << 2;
    int bkr = tid >> 5;
    int bc  = (tid & 31) << 2;

    const float* Ag0 = A + (size_t)(rowBase + ar) * K + ac;
    const float* Ag1 = A + (size_t)(rowBase + 64 + ar) * K + ac;
    const float* Bg  = B + colBase + bc;

    int nk = K >> 4;

#pragma unroll
    for (int s = 0; s < 3; s++) {
        if (s < nk) {
            float* as = As + s * AS_STAGE;
            float* bs = Bs + s * BS_STAGE;
            int k0 = s << 4;
            cp16(as + ar * AS_ST + ac,        Ag0 + k0);
            cp16(as + (ar + 64) * AS_ST + ac, Ag1 + k0);
            cp16(bs + bkr * BS_ST + bc,       Bg + (size_t)(k0 + bkr) * N);
            cp16(bs + (bkr + 8) * BS_ST + bc, Bg + (size_t)(k0 + 8 + bkr) * N);
        }
        asm volatile("cp.async.commit_group;");
    }

    float acc[4][4][4];
#pragma unroll
    for (int i = 0; i < 4; i++)
#pragma unroll
        for (int j = 0; j < 4; j++)
#pragma unroll
            for (int q = 0; q < 4; q++) acc[i][j][q] = 0.0f;

    for (int kt = 0; kt < nk; kt++) {
        asm volatile("cp.async.wait_group 2;");
        __syncthreads();

        int nx = kt + 3;
        if (nx < nk) {
            int bufn = nx & 3;
            float* as = As + bufn * AS_STAGE;
            float* bs = Bs + bufn * BS_STAGE;
            int k0 = nx << 4;
            cp16(as + ar * AS_ST + ac,        Ag0 + k0);
            cp16(as + (ar + 64) * AS_ST + ac, Ag1 + k0);
            cp16(bs + bkr * BS_ST + bc,       Bg + (size_t)(k0 + bkr) * N);
            cp16(bs + (bkr + 8) * BS_ST + bc, Bg + (size_t)(k0 + 8 + bkr) * N);
        }
        asm volatile("cp.async.commit_group;");

        const float* as = As + (kt & 3) * AS_STAGE;
        const float* bs = Bs + (kt & 3) * BS_STAGE;
#pragma unroll
        for (int ks = 0; ks < 16; ks += 8) {
            uint32_t af[4][4], bf[4][2];
#pragma unroll
            for (int i = 0; i < 4; i++) {
                int r = wm + i * 16 + (lane >> 2);
                int c = ks + (lane & 3);
                af[i][0] = __float_as_uint(as[r * AS_ST + c]);
                af[i][1] = __float_as_uint(as[(r + 8) * AS_ST + c]);
                af[i][2] = __float_as_uint(as[r * AS_ST + c + 4]);
                af[i][3] = __float_as_uint(as[(r + 8) * AS_ST + c + 4]);
            }
#pragma unroll
            for (int j = 0; j < 4; j++) {
                int kk = ks + (lane & 3);
                int n  = wn + j * 8 + (lane >> 2);
                bf[j][0] = __float_as_uint(bs[kk * BS_ST + n]);
                bf[j][1] = __float_as_uint(bs[(kk + 4) * BS_ST + n]);
            }
#pragma unroll
            for (int i = 0; i < 4; i++)
#pragma unroll
                for (int j = 0; j < 4; j++)
                    mma_tf32(acc[i][j], af[i], bf[j], acc[i][j]);
        }
    }

#pragma unroll
    for (int i = 0; i < 4; i++) {
        int r0 = rowBase + wm + i * 16 + (lane >> 2);
#pragma unroll
        for (int j = 0; j < 4; j++) {
            int c0 = colBase + wn + j * 8 + (lane & 3) * 2;
            float2 v0, v1;
            v0.x = acc[i][j][0]; v0.y = acc[i][j][1];
            v1.x = acc[i][j][2]; v1.y = acc[i][j][3];
            if (SILU) {
                v0.x = v0.x / (1.0f + expf(-v0.x));
                v0.y = v0.y / (1.0f + expf(-v0.y));
                v1.x = v1.x / (1.0f + expf(-v1.x));
                v1.y = v1.y / (1.0f + expf(-v1.y));
            }
            if (ROUND) {
                v0.x = roundtf(v0.x); v0.y = roundtf(v0.y);
                v1.x = roundtf(v1.x); v1.y = roundtf(v1.y);
            }
            if (TRANSC) {
                C[(size_t)c0 * T_SEQ + r0]           = v0.x;
                C[(size_t)(c0 + 1) * T_SEQ + r0]     = v0.y;
                C[(size_t)c0 * T_SEQ + r0 + 8]       = v1.x;
                C[(size_t)(c0 + 1) * T_SEQ + r0 + 8] = v1.y;
            } else {
                *(float2*)&C[(size_t)r0 * N + c0]       = v0;
                *(float2*)&C[(size_t)(r0 + 8) * N + c0] = v1;
            }
        }
    }
}

template <int SILU, int ROUND>
__global__ void __launch_bounds__(256, 2) tgemm2_kernel(
    const float* __restrict__ A, const float* __restrict__ B,
    float* __restrict__ C, int N, int K)
{
    gemm_body<SILU, ROUND, 0>(A, B, C, N, K, blockIdx.y * 128, blockIdx.x * 128);
}

// fused QKV: grid.x = 12 (8 Wq cols, 2 Wk, 2 Wv); V written transposed
__global__ void __launch_bounds__(256, 2) qkv_kernel(
    const float* __restrict__ Xt,
    const float* __restrict__ Wqt, const float* __restrict__ Wkt,
    const float* __restrict__ Wvt,
    float* __restrict__ q, float* __restrict__ k, float* __restrict__ v)
{
    int bx = blockIdx.x;
    if (bx < 8) {
        gemm_body<0, 0, 0>(Xt, Wqt, q, D_MODEL, D_MODEL,
                           blockIdx.y * 128, bx * 128);
    } else if (bx < 10) {
        gemm_body<0, 0, 0>(Xt, Wkt, k, NKV * HD, D_MODEL,
                           blockIdx.y * 128, (bx - 8) * 128);
    } else {
        gemm_body<0, 0, 1>(Xt, Wvt, v, NKV * HD, D_MODEL,
                           blockIdx.y * 128, (bx - 10) * 128);
    }
}

// ---------------- bf16 MMA flash attention (pre-split, double-buffered) ----
// Per stage: Khi | Klo | Vhi | Vlo, each 64 rows x 36 uint32 (32 data + pad).
#define KVST 36
#define ARR (64 * KVST)             // 2304 uint32 per array
#define STAGE_U (4 * ARR)           // 9216 uint32 per stage
#define ATT_SMEM (2 * STAGE_U * 4)  // 73728 bytes

__global__ void __launch_bounds__(256) attn_bf16_kernel(
    const float* __restrict__ qp,
    const uint32_t* __restrict__ khp, const uint32_t* __restrict__ klp,
    const uint32_t* __restrict__ vhp, const uint32_t* __restrict__ vlp,
    float* __restrict__ op)
{
    extern __shared__ uint32_t smu[];
    float* Qs = (float*)smu;                  // Q staging, pre-loop only

    int qb   = gridDim.x - 1 - blockIdx.x;    // heavy blocks first
    int h    = blockIdx.y;
    int kvh  = h >> 2;
    int tid  = threadIdx.x;
    int lane = tid & 31;
    int warp = tid >> 5;
    int gid  = lane >> 2;
    int tig  = lane & 3;
    int tg2  = tig * 2;
    int fr   = warp * 16 + gid;

    // ---- stage Q tile ----
#pragma unroll
    for (int i = 0; i < 8; i++) {
        int e = tid + 256 * i;
        int r = e >> 4, c4 = (e & 15) << 2;
        *(float4*)&Qs[r * 64 + c4] =
            *(const float4*)&qp[(size_t)(qb * 128 + r) * D_MODEL + h * HD + c4];
    }
    __syncthreads();

    uint32_t qhi[4][4], qlo[4][4];
#pragma unroll
    for (int kt = 0; kt < 4; kt++) {
        float2 x0 = *(float2*)&Qs[fr * 64 + kt * 16 + tg2];
        float2 x1 = *(float2*)&Qs[(fr + 8) * 64 + kt * 16 + tg2];
        float2 x2 = *(float2*)&Qs[fr * 64 + kt * 16 + tg2 + 8];
        float2 x3 = *(float2*)&Qs[(fr + 8) * 64 + kt * 16 + tg2 + 8];
        splitbf(x0.x * 0.125f, x0.y * 0.125f, qhi[kt][0], qlo[kt][0]);
        splitbf(x1.x * 0.125f, x1.y * 0.125f, qhi[kt][1], qlo[kt][1]);
        splitbf(x2.x * 0.125f, x2.y * 0.125f, qhi[kt][2], qlo[kt][2]);
        splitbf(x3.x * 0.125f, x3.y * 0.125f, qhi[kt][3], qlo[kt][3]);
    }
    __syncthreads();   // all Q reads done before cp.async overwrites stage 0

    // per-thread load slots: 8 chunks of 16B (2 per array)
    int r_ld = tid >> 3;              // 0..31 -> rows r_ld and r_ld+32
    int c_ld = (tid & 7) * 4;         // uint32 col 0..28
    const uint32_t* gk_h = khp + kvh * 32 + c_ld;
    const uint32_t* gk_l = klp + kvh * 32 + c_ld;
    const uint32_t* gv_h = vhp + (size_t)(kvh * HD) * (T_SEQ / 2) + c_ld;
    const uint32_t* gv_l = vlp + (size_t)(kvh * HD) * (T_SEQ / 2) + c_ld;

    int kbmax = 2 * qb + 1;

    // prefetch tile 0 into stage 0
    {
        uint32_t* st = smu;
#pragma unroll
        for (int half = 0; half < 2; half++) {
            int r = r_ld + half * 32;
            cp16u(st + r * KVST + c_ld,           gk_h + (size_t)r * 128);
            cp16u(st + ARR + r * KVST + c_ld,     gk_l + (size_t)r * 128);
            cp16u(st + 2 * ARR + r * KVST + c_ld, gv_h + (size_t)r * (T_SEQ / 2));
            cp16u(st + 3 * ARR + r * KVST + c_ld, gv_l + (size_t)r * (T_SEQ / 2));
        }
        asm volatile("cp.async.commit_group;");
    }

    float oacc[8][4];
#pragma unroll
    for (int nt = 0; nt < 8; nt++)
#pragma unroll
        for (int j = 0; j < 4; j++) oacc[nt][j] = 0.0f;
    float m0 = -1e30f, m1 = -1e30f, l0 = 0.0f, l1 = 0.0f;

    for (int kb = 0; kb <= kbmax; kb++) {
        asm volatile("cp.async.wait_group 0;");
        __syncthreads();   // tile kb visible; stage (kb+1)&1 readers done

        // prefetch next tile (overlaps with compute below)
        if (kb < kbmax) {
            uint32_t* st = smu + ((kb + 1) & 1) * STAGE_U;
            int kb1 = (kb + 1) * 64;
#pragma unroll
            for (int half = 0; half < 2; half++) {
                int r = r_ld + half * 32;
                cp16u(st + r * KVST + c_ld,           gk_h + (size_t)(kb1 + r) * 128);
                cp16u(st + ARR + r * KVST + c_ld,     gk_l + (size_t)(kb1 + r) * 128);
                cp16u(st + 2 * ARR + r * KVST + c_ld, gv_h + (size_t)r * (T_SEQ / 2) + kb1 / 2);
                cp16u(st + 3 * ARR + r * KVST + c_ld, gv_l + (size_t)r * (T_SEQ / 2) + kb1 / 2);
            }
        }
        asm volatile("cp.async.commit_group;");

        const uint32_t* Khi = smu + (kb & 1) * STAGE_U;
        const uint32_t* Klo = Khi + ARR;
        const uint32_t* Vhi = Khi + 2 * ARR;
        const uint32_t* Vlo = Khi + 3 * ARR;

        // ---- S = (Q/8) @ K^T : 3-term bf16 ----
        float sacc[8][4];
#pragma unroll
        for (int nt = 0; nt < 8; nt++)
#pragma unroll
            for (int j = 0; j < 4; j++) sacc[nt][j] = 0.0f;

#pragma unroll
        for (int nt = 0; nt < 8; nt++) {
            int base = (nt * 8 + gid) * KVST;
#pragma unroll
            for (int ks = 0; ks < 4; ks++) {
                uint32_t bh[2], bl[2];
                bh[0] = Khi[base + ks * 8 + tig];
                bh[1] = Khi[base + ks * 8 + tig + 4];
                bl[0] = Klo[base + ks * 8 + tig];
                bl[1] = Klo[base + ks * 8 + tig + 4];
                mma_bf16(sacc[nt], qhi[ks], bh, sacc[nt]);
                mma_bf16(sacc[nt], qlo[ks], bh, sacc[nt]);
                mma_bf16(sacc[nt], qhi[ks], bl, sacc[nt]);
            }
        }

        // ---- causal mask ----
        if (kb >= 2 * qb) {
            int grow0 = qb * 128 + fr;
            int grow1 = grow0 + 8;
#pragma unroll
            for (int nt = 0; nt < 8; nt++) {
                int gc = kb * 64 + nt * 8 + tg2;
                if (gc     > grow0) sacc[nt][0] = -1e30f;
                if (gc + 1 > grow0) sacc[nt][1] = -1e30f;
                if (gc     > grow1) sacc[nt][2] = -1e30f;
                if (gc + 1 > grow1) sacc[nt][3] = -1e30f;
            }
        }

        // ---- online softmax ----
        float mx0 = -1e30f, mx1 = -1e30f;
#pragma unroll
        for (int nt = 0; nt < 8; nt++) {
            mx0 = fmaxf(mx0, fmaxf(sacc[nt][0], sacc[nt][1]));
            mx1 = fmaxf(mx1, fmaxf(sacc[nt][2], sacc[nt][3]));
        }
        mx0 = fmaxf(mx0, __shfl_xor_sync(0xffffffffu, mx0, 1));
        mx0 = fmaxf(mx0, __shfl_xor_sync(0xffffffffu, mx0, 2));
        mx1 = fmaxf(mx1, __shfl_xor_sync(0xffffffffu, mx1, 1));
        mx1 = fmaxf(mx1, __shfl_xor_sync(0xffffffffu, mx1, 2));

        float mn0 = fmaxf(m0, mx0), mn1 = fmaxf(m1, mx1);
        float c0 = __expf(m0 - mn0), c1 = __expf(m1 - mn1);
        float rs0 = 0.0f, rs1 = 0.0f;
#pragma unroll
        for (int nt = 0; nt < 8; nt++) {
            float p0 = __expf(sacc[nt][0] - mn0);
            float p1 = __expf(sacc[nt][1] - mn0);
            float p2 = __expf(sacc[nt][2] - mn1);
            float p3 = __expf(sacc[nt][3] - mn1);
            sacc[nt][0] = p0; sacc[nt][1] = p1;
            sacc[nt][2] = p2; sacc[nt][3] = p3;
            rs0 += p0 + p1;
            rs1 += p2 + p3;
        }
        rs0 += __shfl_xor_sync(0xffffffffu, rs0, 1);
        rs0 += __shfl_xor_sync(0xffffffffu, rs0, 2);
        rs1 += __shfl_xor_sync(0xffffffffu, rs1, 1);
        rs1 += __shfl_xor_sync(0xffffffffu, rs1, 2);
        l0 = l0 * c0 + rs0;  m0 = mn0;
        l1 = l1 * c1 + rs1;  m1 = mn1;
#pragma unroll
        for (int nt = 0; nt < 8; nt++) {
            oacc[nt][0] *= c0; oacc[nt][1] *= c0;
            oacc[nt][2] *= c1; oacc[nt][3] *= c1;
        }

        // ---- O += P @ V : A-fragments straight from sacc registers ----
#pragma unroll
        for (int kt = 0; kt < 4; kt++) {
            uint32_t ahi[4], alo[4];
            splitbf(sacc[2*kt][0],     sacc[2*kt][1],     ahi[0], alo[0]);
            splitbf(sacc[2*kt][2],     sacc[2*kt][3],     ahi[1], alo[1]);
            splitbf(sacc[2*kt + 1][0], sacc[2*kt + 1][1], ahi[2], alo[2]);
            splitbf(sacc[2*kt + 1][2], sacc[2*kt + 1][3], ahi[3], alo[3]);
#pragma unroll
            for (int nt = 0; nt < 8; nt++) {
                int base = (nt * 8 + gid) * KVST;
                uint32_t bh[2], bl[2];
                bh[0] = Vhi[base + kt * 8 + tig];
                bh[1] = Vhi[base + kt * 8 + tig + 4];
                bl[0] = Vlo[base + kt * 8 + tig];
                bl[1] = Vlo[base + kt * 8 + tig + 4];
                mma_bf16(oacc[nt], ahi, bh, oacc[nt]);
                mma_bf16(oacc[nt], alo, bh, oacc[nt]);
                mma_bf16(oacc[nt], ahi, bl, oacc[nt]);
            }
        }
        __syncthreads();   // compute done before next iter's prefetch lands
    }

    // ---- finalize ----
    float inv0 = 1.0f / l0, inv1 = 1.0f / l1;
#pragma unroll
    for (int nt = 0; nt < 8; nt++) {
        int col = h * HD + nt * 8 + tg2;
        float2 w0, w1;
        w0.x = roundtf(oacc[nt][0] * inv0); w0.y = roundtf(oacc[nt][1] * inv0);
        w1.x = roundtf(oacc[nt][2] * inv1); w1.y = roundtf(oacc[nt][3] * inv1);
        *(float2*)&op[(size_t)(qb * 128 + fr) * D_MODEL + col]     = w0;
        *(float2*)&op[(size_t)(qb * 128 + fr + 8) * D_MODEL + col] = w1;
    }
}

// ---------------- launch ---------------------------------------------------
extern "C" void kernel_launch(void* const* d_in, const int* in_sizes, int n_in,
                              void* d_out, int out_size)
{
    const float* X  = (const float*)d_in[0];
    const float* Wq = (const float*)d_in[1];
    const float* Wk = (const float*)d_in[2];
    const float* Wv = (const float*)d_in[3];
    const float* W1 = (const float*)d_in[4];
    const float* W2 = (const float*)d_in[5];
    float* out = (float*)d_out;

    float *gq, *gk, *gv, *ga, *gh;
    float *gxt, *gwqt, *gwkt, *gwvt, *gw1t, *gw2t;
    uint32_t *gkh, *gkl, *gvh, *gvl;
    cudaGetSymbolAddress((void**)&gq, g_q);
    cudaGetSymbolAddress((void**)&gk, g_k);
    cudaGetSymbolAddress((void**)&gv, g_v);
    cudaGetSymbolAddress((void**)&ga, g_attn);
    cudaGetSymbolAddress((void**)&gh, g_h1);
    cudaGetSymbolAddress((void**)&gxt, g_xt);
    cudaGetSymbolAddress((void**)&gwqt, g_wqt);
    cudaGetSymbolAddress((void**)&gwkt, g_wkt);
    cudaGetSymbolAddress((void**)&gwvt, g_wvt);
    cudaGetSymbolAddress((void**)&gw1t, g_w1t);
    cudaGetSymbolAddress((void**)&gw2t, g_w2t);
    cudaGetSymbolAddress((void**)&gkh, g_khp);
    cudaGetSymbolAddress((void**)&gkl, g_klp);
    cudaGetSymbolAddress((void**)&gvh, g_vhp);
    cudaGetSymbolAddress((void**)&gvl, g_vlp);

    cudaFuncSetAttribute(attn_bf16_kernel,
                         cudaFuncAttributeMaxDynamicSharedMemorySize, ATT_SMEM);
    cudaFuncSetAttribute(qkv_kernel,
                         cudaFuncAttributeMaxDynamicSharedMemorySize, GEMM_SMEM);
    cudaFuncSetAttribute(tgemm2_kernel<1, 1>,
                         cudaFuncAttributeMaxDynamicSharedMemorySize, GEMM_SMEM);
    cudaFuncSetAttribute(tgemm2_kernel<0, 0>,
                         cudaFuncAttributeMaxDynamicSharedMemorySize, GEMM_SMEM);

    // pre-round all GEMM operands to tf32
    round_tf32_kernel<<<(T_SEQ * D_MODEL / 4 + 255) / 256, 256>>>(X,  gxt,  T_SEQ * D_MODEL / 4);
    round_tf32_kernel<<<(D_MODEL * D_MODEL / 4 + 255) / 256, 256>>>(Wq, gwqt, D_MODEL * D_MODEL / 4);
    round_tf32_kernel<<<(D_MODEL * 256 / 4 + 255) / 256, 256>>>(Wk, gwkt, D_MODEL * 256 / 4);
    round_tf32_kernel<<<(D_MODEL * 256 / 4 + 255) / 256, 256>>>(Wv, gwvt, D_MODEL * 256 / 4);
    round_tf32_kernel<<<(D_MODEL * D_FF / 4 + 255) / 256, 256>>>(W1, gw1t, D_MODEL * D_FF / 4);
    round_tf32_kernel<<<(D_FF * D_MODEL / 4 + 255) / 256, 256>>>(W2, gw2t, D_FF * D_MODEL / 4);

    rope_table_kernel<<<T_SEQ, 32>>>();

    // fused QKV projection (V written transposed)
    qkv_kernel<<<dim3(12, T_SEQ / 128), 256, GEMM_SMEM>>>(
        gxt, gwqt, gwkt, gwvt, gq, gk, gv);

    // RoPE Q in-place; RoPE K fused with bf16 hi/lo split; split V
    rope_apply_kernel<<<T_SEQ, NH * 32>>>(gq, NH);
    rope_split_k_kernel<<<T_SEQ, NKV * 32>>>();
    split_v_kernel<<<NKV * HD * (T_SEQ / 2) / 256, 256>>>();

    // causal flash attention, bf16 tensor cores, double-buffered
    attn_bf16_kernel<<<dim3(T_SEQ / 128, NH), 256, ATT_SMEM>>>(
        gq, gkh, gkl, gvh, gvl, ga);

    // MLP
    tgemm2_kernel<1, 1><<<dim3(D_FF / 128, T_SEQ / 128), 256, GEMM_SMEM>>>(
        ga, gw1t, gh, D_FF, D_MODEL);
    tgemm2_kernel<0, 0><<<dim3(D_MODEL / 128, T_SEQ / 128), 256, GEMM_SMEM>>>(
        gh, gw2t, out, D_MODEL, D_FF);
}

// round 7
// speedup vs baseline: 3.2099x; 1.0231x over previous
#include <cuda_runtime.h>
#include <cuda_bf16.h>
#include <math.h>
#include <stdint.h>

// Problem constants
#define T_SEQ  4096
#define D_MODEL 1024
#define NH     16
#define NKV    4
#define HD     64
#define D_FF   4096

// ---------------- scratch (device globals; no allocation allowed) ----------
__device__ float g_q[T_SEQ * D_MODEL];          // 16 MB
__device__ float g_k[T_SEQ * NKV * HD];         // 4 MB  [token][256] (pre-rope)
__device__ float g_v[NKV * HD * T_SEQ];         // 4 MB  TRANSPOSED [256][4096]
__device__ float g_attn[T_SEQ * D_MODEL];       // 16 MB (tf32-rounded)
__device__ float g_h1[(size_t)T_SEQ * D_FF];    // 64 MB (tf32-rounded)
__device__ float g_cos[T_SEQ * 32];
__device__ float g_sin[T_SEQ * 32];
// tf32-pre-rounded operands
__device__ float g_xt[T_SEQ * D_MODEL];
__device__ float g_wqt[D_MODEL * D_MODEL];
__device__ float g_wkt[D_MODEL * NKV * HD];
__device__ float g_wvt[D_MODEL * NKV * HD];
__device__ float g_w1t[D_MODEL * D_FF];
__device__ float g_w2t[D_FF * D_MODEL];
// pre-split bf16 hi/lo packed K (post-rope) and V^T
__device__ uint32_t g_khp[T_SEQ * 128];         // [token][kvh*32 + d2]
__device__ uint32_t g_klp[T_SEQ * 128];
__device__ uint32_t g_vhp[NKV * HD * (T_SEQ / 2)];  // [dim][token-pair]
__device__ uint32_t g_vlp[NKV * HD * (T_SEQ / 2)];

// ---------------- helpers ---------------------------------------------------
__device__ __forceinline__ uint32_t f2tf32(float x) {
    uint32_t r;
    asm("cvt.rna.tf32.f32 %0, %1;" : "=r"(r) : "f"(x));
    return r;
}
__device__ __forceinline__ float roundtf(float x) {
    return __uint_as_float(f2tf32(x));
}

__device__ __forceinline__ void mma_tf32(float* d, const uint32_t* a,
                                         const uint32_t* b, const float* c) {
    asm volatile(
        "mma.sync.aligned.m16n8k8.row.col.f32.tf32.tf32.f32 "
        "{%0,%1,%2,%3}, {%4,%5,%6,%7}, {%8,%9}, {%10,%11,%12,%13};"
        : "=f"(d[0]), "=f"(d[1]), "=f"(d[2]), "=f"(d[3])
        : "r"(a[0]), "r"(a[1]), "r"(a[2]), "r"(a[3]),
          "r"(b[0]), "r"(b[1]),
          "f"(c[0]), "f"(c[1]), "f"(c[2]), "f"(c[3]));
}

__device__ __forceinline__ void mma_bf16(float* d, const uint32_t* a,
                                         const uint32_t* b, const float* c) {
    asm volatile(
        "mma.sync.aligned.m16n8k16.row.col.f32.bf16.bf16.f32 "
        "{%0,%1,%2,%3}, {%4,%5,%6,%7}, {%8,%9}, {%10,%11,%12,%13};"
        : "=f"(d[0]), "=f"(d[1]), "=f"(d[2]), "=f"(d[3])
        : "r"(a[0]), "r"(a[1]), "r"(a[2]), "r"(a[3]),
          "r"(b[0]), "r"(b[1]),
          "f"(c[0]), "f"(c[1]), "f"(c[2]), "f"(c[3]));
}

__device__ __forceinline__ void ldsm_x4(uint32_t& r0, uint32_t& r1,
                                        uint32_t& r2, uint32_t& r3,
                                        uint32_t saddr) {
    asm volatile(
        "ldmatrix.sync.aligned.m8n8.x4.shared.b16 {%0,%1,%2,%3}, [%4];"
        : "=r"(r0), "=r"(r1), "=r"(r2), "=r"(r3) : "r"(saddr));
}

__device__ __forceinline__ uint32_t packbf(float x, float y) {
    __nv_bfloat162 t = __floats2bfloat162_rn(x, y);
    return *(uint32_t*)&t;
}
__device__ __forceinline__ void splitbf(float x, float y,
                                        uint32_t& hi, uint32_t& lo) {
    __nv_bfloat16 hx = __float2bfloat16_rn(x);
    __nv_bfloat16 hy = __float2bfloat16_rn(y);
    hi = packbf(__bfloat162float(hx), __bfloat162float(hy));
    lo = packbf(x - __bfloat162float(hx), y - __bfloat162float(hy));
}

__device__ __forceinline__ void cp16(float* smem_dst, const float* g) {
    uint32_t a = (uint32_t)__cvta_generic_to_shared(smem_dst);
    asm volatile("cp.async.ca.shared.global [%0], [%1], 16;" :: "r"(a), "l"(g));
}
__device__ __forceinline__ void cp16u(uint32_t* smem_dst, const uint32_t* g) {
    uint32_t a = (uint32_t)__cvta_generic_to_shared(smem_dst);
    asm volatile("cp.async.ca.shared.global [%0], [%1], 16;" :: "r"(a), "l"(g));
}

// ---------------- pre-round pass -------------------------------------------
__global__ void round_tf32_kernel(const float* __restrict__ in,
                                  float* __restrict__ out, int n4) {
    int i = blockIdx.x * 256 + threadIdx.x;
    if (i < n4) {
        float4 v = ((const float4*)in)[i];
        v.x = roundtf(v.x); v.y = roundtf(v.y);
        v.z = roundtf(v.z); v.w = roundtf(v.w);
        ((float4*)out)[i] = v;
    }
}

// ---------------- RoPE ------------------------------------------------------
__global__ void rope_table_kernel() {
    int t = blockIdx.x, i = threadIdx.x;
    float inv = 1.0f / powf(10000.0f, (float)(2 * i) / 64.0f);
    float ang = (float)t * inv;
    g_cos[t * 32 + i] = cosf(ang);
    g_sin[t * 32 + i] = sinf(ang);
}

__global__ void rope_apply_kernel(float* __restrict__ x, int nh) {
    int t = blockIdx.x;
    int h = threadIdx.x >> 5;
    int i = threadIdx.x & 31;
    float c = g_cos[t * 32 + i];
    float s = g_sin[t * 32 + i];
    float* p = x + (size_t)t * nh * HD + h * HD;
    float x1 = p[i], x2 = p[i + 32];
    p[i]      = x1 * c - x2 * s;
    p[i + 32] = x2 * c + x1 * s;
}

// rope K + split to packed bf16 hi/lo
__global__ void rope_split_k_kernel() {
    __shared__ float buf[NKV][64];
    int t = blockIdx.x;
    int h = threadIdx.x >> 5;
    int i = threadIdx.x & 31;
    float c = g_cos[t * 32 + i];
    float s = g_sin[t * 32 + i];
    const float* p = g_k + (size_t)t * (NKV * HD) + h * HD;
    float x1 = p[i], x2 = p[i + 32];
    buf[h][i]      = x1 * c - x2 * s;
    buf[h][i + 32] = x2 * c + x1 * s;
    __syncthreads();
    float a = buf[h][2 * i], b = buf[h][2 * i + 1];
    uint32_t hi, lo;
    splitbf(a, b, hi, lo);
    g_khp[t * 128 + h * 32 + i] = hi;
    g_klp[t * 128 + h * 32 + i] = lo;
}

// split transposed V into packed bf16 hi/lo pairs along tokens
__global__ void split_v_kernel() {
    int idx = blockIdx.x * 256 + threadIdx.x;
    float2 v = *(const float2*)&g_v[(size_t)idx * 2];
    uint32_t hi, lo;
    splitbf(v.x, v.y, hi, lo);
    g_vhp[idx] = hi;
    g_vlp[idx] = lo;
}

// ---------------- cp.async pipelined tf32 GEMM ------------------------------
#define AS_ST 20
#define BS_ST 136
#define AS_STAGE (128 * AS_ST)
#define BS_STAGE (16 * BS_ST)
#define GEMM_SMEM ((4 * (AS_STAGE + BS_STAGE)) * 4)

template <int SILU, int ROUND, int TRANSC>
__device__ __forceinline__ void gemm_body(
    const float* __restrict__ A, const float* __restrict__ B,
    float* __restrict__ C, int N, int K, int rowBase, int colBase)
{
    extern __shared__ float smp[];
    float* As = smp;
    float* Bs = smp + 4 * AS_STAGE;

    int tid  = threadIdx.x;
    int lane = tid & 31;
    int warp = tid >> 5;
    int wm = (warp & 1) * 64;
    int wn = (warp >> 1) * 32;

    int ar  = tid >> 2;
    int ac  = (tid & 3) << 2;
    int bkr = tid >> 5;
    int bc  = (tid & 31) << 2;

    const float* Ag0 = A + (size_t)(rowBase + ar) * K + ac;
    const float* Ag1 = A + (size_t)(rowBase + 64 + ar) * K + ac;
    const float* Bg  = B + colBase + bc;

    int nk = K >> 4;

#pragma unroll
    for (int s = 0; s < 3; s++) {
        if (s < nk) {
            float* as = As + s * AS_STAGE;
            float* bs = Bs + s * BS_STAGE;
            int k0 = s << 4;
            cp16(as + ar * AS_ST + ac,        Ag0 + k0);
            cp16(as + (ar + 64) * AS_ST + ac, Ag1 + k0);
            cp16(bs + bkr * BS_ST + bc,       Bg + (size_t)(k0 + bkr) * N);
            cp16(bs + (bkr + 8) * BS_ST + bc, Bg + (size_t)(k0 + 8 + bkr) * N);
        }
        asm volatile("cp.async.commit_group;");
    }

    float acc[4][4][4];
#pragma unroll
    for (int i = 0; i < 4; i++)
#pragma unroll
        for (int j = 0; j < 4; j++)
#pragma unroll
            for (int q = 0; q < 4; q++) acc[i][j][q] = 0.0f;

    for (int kt = 0; kt < nk; kt++) {
        asm volatile("cp.async.wait_group 2;");
        __syncthreads();

        int nx = kt + 3;
        if (nx < nk) {
            int bufn = nx & 3;
            float* as = As + bufn * AS_STAGE;
            float* bs = Bs + bufn * BS_STAGE;
            int k0 = nx << 4;
            cp16(as + ar * AS_ST + ac,        Ag0 + k0);
            cp16(as + (ar + 64) * AS_ST + ac, Ag1 + k0);
            cp16(bs + bkr * BS_ST + bc,       Bg + (size_t)(k0 + bkr) * N);
            cp16(bs + (bkr + 8) * BS_ST + bc, Bg + (size_t)(k0 + 8 + bkr) * N);
        }
        asm volatile("cp.async.commit_group;");

        const float* as = As + (kt & 3) * AS_STAGE;
        const float* bs = Bs + (kt & 3) * BS_STAGE;
#pragma unroll
        for (int ks = 0; ks < 16; ks += 8) {
            uint32_t af[4][4], bf[4][2];
#pragma unroll
            for (int i = 0; i < 4; i++) {
                int r = wm + i * 16 + (lane >> 2);
                int c = ks + (lane & 3);
                af[i][0] = __float_as_uint(as[r * AS_ST + c]);
                af[i][1] = __float_as_uint(as[(r + 8) * AS_ST + c]);
                af[i][2] = __float_as_uint(as[r * AS_ST + c + 4]);
                af[i][3] = __float_as_uint(as[(r + 8) * AS_ST + c + 4]);
            }
#pragma unroll
            for (int j = 0; j < 4; j++) {
                int kk = ks + (lane & 3);
                int n  = wn + j * 8 + (lane >> 2);
                bf[j][0] = __float_as_uint(bs[kk * BS_ST + n]);
                bf[j][1] = __float_as_uint(bs[(kk + 4) * BS_ST + n]);
            }
#pragma unroll
            for (int i = 0; i < 4; i++)
#pragma unroll
                for (int j = 0; j < 4; j++)
                    mma_tf32(acc[i][j], af[i], bf[j], acc[i][j]);
        }
    }

#pragma unroll
    for (int i = 0; i < 4; i++) {
        int r0 = rowBase + wm + i * 16 + (lane >> 2);
#pragma unroll
        for (int j = 0; j < 4; j++) {
            int c0 = colBase + wn + j * 8 + (lane & 3) * 2;
            float2 v0, v1;
            v0.x = acc[i][j][0]; v0.y = acc[i][j][1];
            v1.x = acc[i][j][2]; v1.y = acc[i][j][3];
            if (SILU) {
                v0.x = v0.x / (1.0f + expf(-v0.x));
                v0.y = v0.y / (1.0f + expf(-v0.y));
                v1.x = v1.x / (1.0f + expf(-v1.x));
                v1.y = v1.y / (1.0f + expf(-v1.y));
            }
            if (ROUND) {
                v0.x = roundtf(v0.x); v0.y = roundtf(v0.y);
                v1.x = roundtf(v1.x); v1.y = roundtf(v1.y);
            }
            if (TRANSC) {
                C[(size_t)c0 * T_SEQ + r0]           = v0.x;
                C[(size_t)(c0 + 1) * T_SEQ + r0]     = v0.y;
                C[(size_t)c0 * T_SEQ + r0 + 8]       = v1.x;
                C[(size_t)(c0 + 1) * T_SEQ + r0 + 8] = v1.y;
            } else {
                *(float2*)&C[(size_t)r0 * N + c0]       = v0;
                *(float2*)&C[(size_t)(r0 + 8) * N + c0] = v1;
            }
        }
    }
}

template <int SILU, int ROUND>
__global__ void __launch_bounds__(256, 2) tgemm2_kernel(
    const float* __restrict__ A, const float* __restrict__ B,
    float* __restrict__ C, int N, int K)
{
    gemm_body<SILU, ROUND, 0>(A, B, C, N, K, blockIdx.y * 128, blockIdx.x * 128);
}

// fused QKV: grid.x = 12 (8 Wq cols, 2 Wk, 2 Wv); V written transposed
__global__ void __launch_bounds__(256, 2) qkv_kernel(
    const float* __restrict__ Xt,
    const float* __restrict__ Wqt, const float* __restrict__ Wkt,
    const float* __restrict__ Wvt,
    float* __restrict__ q, float* __restrict__ k, float* __restrict__ v)
{
    int bx = blockIdx.x;
    if (bx < 8) {
        gemm_body<0, 0, 0>(Xt, Wqt, q, D_MODEL, D_MODEL,
                           blockIdx.y * 128, bx * 128);
    } else if (bx < 10) {
        gemm_body<0, 0, 0>(Xt, Wkt, k, NKV * HD, D_MODEL,
                           blockIdx.y * 128, (bx - 8) * 128);
    } else {
        gemm_body<0, 0, 1>(Xt, Wvt, v, NKV * HD, D_MODEL,
                           blockIdx.y * 128, (bx - 10) * 128);
    }
}

// ---------------- bf16 MMA flash attention (ldmatrix, double-buffered) -----
// Per stage: K then V; each 64 rows x 68 uint32 (32 hi | 32 lo | 4 pad).
// ldmatrix.x4 per (nt,ks) fetches {bh0,bh1,bl0,bl1} in one instruction;
// row stride 272B -> 8-row 16B footprints at 16*r mod 128: conflict-free.
#define KROW 68
#define KARR (64 * KROW)            // 4352 uint32 per array
#define STAGE_U (2 * KARR)          // 8704 uint32 per stage (K + V)
#define ATT_SMEM (2 * STAGE_U * 4)  // 69632 bytes

__global__ void __launch_bounds__(256) attn_bf16_kernel(
    const float* __restrict__ qp,
    const uint32_t* __restrict__ khp, const uint32_t* __restrict__ klp,
    const uint32_t* __restrict__ vhp, const uint32_t* __restrict__ vlp,
    float* __restrict__ op)
{
    extern __shared__ uint32_t smu[];
    float* Qs = (float*)smu;                  // Q staging, pre-loop only

    int qb   = gridDim.x - 1 - blockIdx.x;    // heavy blocks first
    int h    = blockIdx.y;
    int kvh  = h >> 2;
    int tid  = threadIdx.x;
    int lane = tid & 31;
    int warp = tid >> 5;
    int gid  = lane >> 2;
    int tig  = lane & 3;
    int tg2  = tig * 2;
    int fr   = warp * 16 + gid;

    // ---- stage Q tile ----
#pragma unroll
    for (int i = 0; i < 8; i++) {
        int e = tid + 256 * i;
        int r = e >> 4, c4 = (e & 15) << 2;
        *(float4*)&Qs[r * 64 + c4] =
            *(const float4*)&qp[(size_t)(qb * 128 + r) * D_MODEL + h * HD + c4];
    }
    __syncthreads();

    uint32_t qhi[4][4], qlo[4][4];
#pragma unroll
    for (int kt = 0; kt < 4; kt++) {
        float2 x0 = *(float2*)&Qs[fr * 64 + kt * 16 + tg2];
        float2 x1 = *(float2*)&Qs[(fr + 8) * 64 + kt * 16 + tg2];
        float2 x2 = *(float2*)&Qs[fr * 64 + kt * 16 + tg2 + 8];
        float2 x3 = *(float2*)&Qs[(fr + 8) * 64 + kt * 16 + tg2 + 8];
        splitbf(x0.x * 0.125f, x0.y * 0.125f, qhi[kt][0], qlo[kt][0]);
        splitbf(x1.x * 0.125f, x1.y * 0.125f, qhi[kt][1], qlo[kt][1]);
        splitbf(x2.x * 0.125f, x2.y * 0.125f, qhi[kt][2], qlo[kt][2]);
        splitbf(x3.x * 0.125f, x3.y * 0.125f, qhi[kt][3], qlo[kt][3]);
    }
    __syncthreads();   // all Q reads done before cp.async overwrites stage 0

    // ldmatrix per-lane offset: matrix id g = lane>>3:
    //   g&1 -> k-halves (+4 u32), g>>1 -> hi/lo (+32 u32)
    uint32_t smem_b = (uint32_t)__cvta_generic_to_shared(smu);
    int laneoff = (lane & 7) * KROW + ((lane >> 3) & 1) * 4 + (lane >> 4) * 32;

    // load slots
    int r_ld = tid >> 3;              // rows r_ld, r_ld+32
    int s4   = (tid & 7) * 4;         // u32 col within hi (or lo) half
    const uint32_t* khB = khp + kvh * 32 + s4;
    const uint32_t* klB = klp + kvh * 32 + s4;
    const uint32_t* vhB = vhp + (size_t)(kvh * HD) * (T_SEQ / 2) + s4;
    const uint32_t* vlB = vlp + (size_t)(kvh * HD) * (T_SEQ / 2) + s4;

    int kbmax = 2 * qb + 1;

    // prefetch tile 0 into stage 0
    {
        uint32_t* Ks = smu;
        uint32_t* Vs = smu + KARR;
#pragma unroll
        for (int half = 0; half < 2; half++) {
            int r = r_ld + half * 32;
            cp16u(Ks + r * KROW + s4,      khB + (size_t)r * 128);
            cp16u(Ks + r * KROW + 32 + s4, klB + (size_t)r * 128);
            cp16u(Vs + r * KROW + s4,      vhB + (size_t)r * (T_SEQ / 2));
            cp16u(Vs + r * KROW + 32 + s4, vlB + (size_t)r * (T_SEQ / 2));
        }
        asm volatile("cp.async.commit_group;");
    }

    float oacc[8][4];
#pragma unroll
    for (int nt = 0; nt < 8; nt++)
#pragma unroll
        for (int j = 0; j < 4; j++) oacc[nt][j] = 0.0f;
    float m0 = -1e30f, m1 = -1e30f, l0 = 0.0f, l1 = 0.0f;

    for (int kb = 0; kb <= kbmax; kb++) {
        asm volatile("cp.async.wait_group 0;");
        __syncthreads();   // tile kb visible; prior-iter readers of other stage done

        // prefetch next tile (overlaps with compute below)
        if (kb < kbmax) {
            uint32_t* st = smu + ((kb + 1) & 1) * STAGE_U;
            uint32_t* Ks = st;
            uint32_t* Vs = st + KARR;
            int kb1 = (kb + 1) * 64;
#pragma unroll
            for (int half = 0; half < 2; half++) {
                int r = r_ld + half * 32;
                cp16u(Ks + r * KROW + s4,      khB + (size_t)(kb1 + r) * 128);
                cp16u(Ks + r * KROW + 32 + s4, klB + (size_t)(kb1 + r) * 128);
                cp16u(Vs + r * KROW + s4,      vhB + (size_t)r * (T_SEQ / 2) + kb1 / 2);
                cp16u(Vs + r * KROW + 32 + s4, vlB + (size_t)r * (T_SEQ / 2) + kb1 / 2);
            }
        }
        asm volatile("cp.async.commit_group;");

        uint32_t stK = smem_b + 4 * ((kb & 1) * STAGE_U + laneoff);
        uint32_t stV = stK + 4 * KARR;

        // ---- S = (Q/8) @ K^T : 3-term bf16, ldmatrix fragments ----
        float sacc[8][4];
#pragma unroll
        for (int nt = 0; nt < 8; nt++)
#pragma unroll
            for (int j = 0; j < 4; j++) sacc[nt][j] = 0.0f;

#pragma unroll
        for (int nt = 0; nt < 8; nt++) {
            uint32_t rowa = stK + nt * (8 * KROW * 4);
#pragma unroll
            for (int ks = 0; ks < 4; ks++) {
                uint32_t bh0, bh1, bl0, bl1;
                ldsm_x4(bh0, bh1, bl0, bl1, rowa + ks * 32);
                uint32_t bh[2] = {bh0, bh1}, bl[2] = {bl0, bl1};
                mma_bf16(sacc[nt], qhi[ks], bh, sacc[nt]);
                mma_bf16(sacc[nt], qlo[ks], bh, sacc[nt]);
                mma_bf16(sacc[nt], qhi[ks], bl, sacc[nt]);
            }
        }

        // ---- causal mask ----
        if (kb >= 2 * qb) {
            int grow0 = qb * 128 + fr;
            int grow1 = grow0 + 8;
#pragma unroll
            for (int nt = 0; nt < 8; nt++) {
                int gc = kb * 64 + nt * 8 + tg2;
                if (gc     > grow0) sacc[nt][0] = -1e30f;
                if (gc + 1 > grow0) sacc[nt][1] = -1e30f;
                if (gc     > grow1) sacc[nt][2] = -1e30f;
                if (gc + 1 > grow1) sacc[nt][3] = -1e30f;
            }
        }

        // ---- online softmax ----
        float mx0 = -1e30f, mx1 = -1e30f;
#pragma unroll
        for (int nt = 0; nt < 8; nt++) {
            mx0 = fmaxf(mx0, fmaxf(sacc[nt][0], sacc[nt][1]));
            mx1 = fmaxf(mx1, fmaxf(sacc[nt][2], sacc[nt][3]));
        }
        mx0 = fmaxf(mx0, __shfl_xor_sync(0xffffffffu, mx0, 1));
        mx0 = fmaxf(mx0, __shfl_xor_sync(0xffffffffu, mx0, 2));
        mx1 = fmaxf(mx1, __shfl_xor_sync(0xffffffffu, mx1, 1));
        mx1 = fmaxf(mx1, __shfl_xor_sync(0xffffffffu, mx1, 2));

        float mn0 = fmaxf(m0, mx0), mn1 = fmaxf(m1, mx1);
        float c0 = __expf(m0 - mn0), c1 = __expf(m1 - mn1);
        float rs0 = 0.0f, rs1 = 0.0f;
#pragma unroll
        for (int nt = 0; nt < 8; nt++) {
            float p0 = __expf(sacc[nt][0] - mn0);
            float p1 = __expf(sacc[nt][1] - mn0);
            float p2 = __expf(sacc[nt][2] - mn1);
            float p3 = __expf(sacc[nt][3] - mn1);
            sacc[nt][0] = p0; sacc[nt][1] = p1;
            sacc[nt][2] = p2; sacc[nt][3] = p3;
            rs0 += p0 + p1;
            rs1 += p2 + p3;
        }
        rs0 += __shfl_xor_sync(0xffffffffu, rs0, 1);
        rs0 += __shfl_xor_sync(0xffffffffu, rs0, 2);
        rs1 += __shfl_xor_sync(0xffffffffu, rs1, 1);
        rs1 += __shfl_xor_sync(0xffffffffu, rs1, 2);
        l0 = l0 * c0 + rs0;  m0 = mn0;
        l1 = l1 * c1 + rs1;  m1 = mn1;
#pragma unroll
        for (int nt = 0; nt < 8; nt++) {
            oacc[nt][0] *= c0; oacc[nt][1] *= c0;
            oacc[nt][2] *= c1; oacc[nt][3] *= c1;
        }

        // ---- O += P @ V : A from sacc regs, B via ldmatrix ----
#pragma unroll
        for (int kt = 0; kt < 4; kt++) {
            uint32_t ahi[4], alo[4];
            splitbf(sacc[2*kt][0],     sacc[2*kt][1],     ahi[0], alo[0]);
            splitbf(sacc[2*kt][2],     sacc[2*kt][3],     ahi[1], alo[1]);
            splitbf(sacc[2*kt + 1][0], sacc[2*kt + 1][1], ahi[2], alo[2]);
            splitbf(sacc[2*kt + 1][2], sacc[2*kt + 1][3], ahi[3], alo[3]);
#pragma unroll
            for (int nt = 0; nt < 8; nt++) {
                uint32_t bh0, bh1, bl0, bl1;
                ldsm_x4(bh0, bh1, bl0, bl1,
                        stV + nt * (8 * KROW * 4) + kt * 32);
                uint32_t bh[2] = {bh0, bh1}, bl[2] = {bl0, bl1};
                mma_bf16(oacc[nt], ahi, bh, oacc[nt]);
                mma_bf16(oacc[nt], alo, bh, oacc[nt]);
                mma_bf16(oacc[nt], ahi, bl, oacc[nt]);
            }
        }
        // no trailing barrier: next iter's top wait_group+syncthreads fences
        // the stage being overwritten (its readers finished last iteration)
    }

    // ---- finalize ----
    float inv0 = 1.0f / l0, inv1 = 1.0f / l1;
#pragma unroll
    for (int nt = 0; nt < 8; nt++) {
        int col = h * HD + nt * 8 + tg2;
        float2 w0, w1;
        w0.x = roundtf(oacc[nt][0] * inv0); w0.y = roundtf(oacc[nt][1] * inv0);
        w1.x = roundtf(oacc[nt][2] * inv1); w1.y = roundtf(oacc[nt][3] * inv1);
        *(float2*)&op[(size_t)(qb * 128 + fr) * D_MODEL + col]     = w0;
        *(float2*)&op[(size_t)(qb * 128 + fr + 8) * D_MODEL + col] = w1;
    }
}

// ---------------- launch ---------------------------------------------------
extern "C" void kernel_launch(void* const* d_in, const int* in_sizes, int n_in,
                              void* d_out, int out_size)
{
    const float* X  = (const float*)d_in[0];
    const float* Wq = (const float*)d_in[1];
    const float* Wk = (const float*)d_in[2];
    const float* Wv = (const float*)d_in[3];
    const float* W1 = (const float*)d_in[4];
    const float* W2 = (const float*)d_in[5];
    float* out = (float*)d_out;

    float *gq, *gk, *gv, *ga, *gh;
    float *gxt, *gwqt, *gwkt, *gwvt, *gw1t, *gw2t;
    uint32_t *gkh, *gkl, *gvh, *gvl;
    cudaGetSymbolAddress((void**)&gq, g_q);
    cudaGetSymbolAddress((void**)&gk, g_k);
    cudaGetSymbolAddress((void**)&gv, g_v);
    cudaGetSymbolAddress((void**)&ga, g_attn);
    cudaGetSymbolAddress((void**)&gh, g_h1);
    cudaGetSymbolAddress((void**)&gxt, g_xt);
    cudaGetSymbolAddress((void**)&gwqt, g_wqt);
    cudaGetSymbolAddress((void**)&gwkt, g_wkt);
    cudaGetSymbolAddress((void**)&gwvt, g_wvt);
    cudaGetSymbolAddress((void**)&gw1t, g_w1t);
    cudaGetSymbolAddress((void**)&gw2t, g_w2t);
    cudaGetSymbolAddress((void**)&gkh, g_khp);
    cudaGetSymbolAddress((void**)&gkl, g_klp);
    cudaGetSymbolAddress((void**)&gvh, g_vhp);
    cudaGetSymbolAddress((void**)&gvl, g_vlp);

    cudaFuncSetAttribute(attn_bf16_kernel,
                         cudaFuncAttributeMaxDynamicSharedMemorySize, ATT_SMEM);
    cudaFuncSetAttribute(qkv_kernel,
                         cudaFuncAttributeMaxDynamicSharedMemorySize, GEMM_SMEM);
    cudaFuncSetAttribute(tgemm2_kernel<1, 1>,
                         cudaFuncAttributeMaxDynamicSharedMemorySize, GEMM_SMEM);
    cudaFuncSetAttribute(tgemm2_kernel<0, 0>,
                         cudaFuncAttributeMaxDynamicSharedMemorySize, GEMM_SMEM);

    // pre-round all GEMM operands to tf32
    round_tf32_kernel<<<(T_SEQ * D_MODEL / 4 + 255) / 256, 256>>>(X,  gxt,  T_SEQ * D_MODEL / 4);
    round_tf32_kernel<<<(D_MODEL * D_MODEL / 4 + 255) / 256, 256>>>(Wq, gwqt, D_MODEL * D_MODEL / 4);
    round_tf32_kernel<<<(D_MODEL * 256 / 4 + 255) / 256, 256>>>(Wk, gwkt, D_MODEL * 256 / 4);
    round_tf32_kernel<<<(D_MODEL * 256 / 4 + 255) / 256, 256>>>(Wv, gwvt, D_MODEL * 256 / 4);
    round_tf32_kernel<<<(D_MODEL * D_FF / 4 + 255) / 256, 256>>>(W1, gw1t, D_MODEL * D_FF / 4);
    round_tf32_kernel<<<(D_FF * D_MODEL / 4 + 255) / 256, 256>>>(W2, gw2t, D_FF * D_MODEL / 4);

    rope_table_kernel<<<T_SEQ, 32>>>();

    // fused QKV projection (V written transposed)
    qkv_kernel<<<dim3(12, T_SEQ / 128), 256, GEMM_SMEM>>>(
        gxt, gwqt, gwkt, gwvt, gq, gk, gv);

    // RoPE Q in-place; RoPE K fused with bf16 hi/lo split; split V
    rope_apply_kernel<<<T_SEQ, NH * 32>>>(gq, NH);
    rope_split_k_kernel<<<T_SEQ, NKV * 32>>>();
    split_v_kernel<<<NKV * HD * (T_SEQ / 2) / 256, 256>>>();

    // causal flash attention, bf16 tensor cores + ldmatrix
    attn_bf16_kernel<<<dim3(T_SEQ / 128, NH), 256, ATT_SMEM>>>(
        gq, gkh, gkl, gvh, gvl, ga);

    // MLP
    tgemm2_kernel<1, 1><<<dim3(D_FF / 128, T_SEQ / 128), 256, GEMM_SMEM>>>(
        ga, gw1t, gh, D_FF, D_MODEL);
    tgemm2_kernel<0, 0><<<dim3(D_MODEL / 128, T_SEQ / 128), 256, GEMM_SMEM>>>(
        gh, gw2t, out, D_MODEL, D_FF);
}

// round 9
// speedup vs baseline: 3.2708x; 1.0190x over previous
#include <cuda_runtime.h>
#include <cuda_bf16.h>
#include <math.h>
#include <stdint.h>

// Problem constants
#define T_SEQ  4096
#define D_MODEL 1024
#define NH     16
#define NKV    4
#define HD     64
#define D_FF   4096

// ---------------- scratch (device globals; no allocation allowed) ----------
__device__ float g_q[T_SEQ * D_MODEL];
__device__ float g_k[T_SEQ * NKV * HD];         // [token][256] (pre-rope)
__device__ float g_v[NKV * HD * T_SEQ];         // TRANSPOSED [256][4096]
__device__ float g_attn[T_SEQ * D_MODEL];       // tf32-rounded
__device__ float g_h1[(size_t)T_SEQ * D_FF];    // tf32-rounded
__device__ float g_cos[T_SEQ * 32];
__device__ float g_sin[T_SEQ * 32];
__device__ float g_xt[T_SEQ * D_MODEL];
__device__ float g_wqt[D_MODEL * D_MODEL];
__device__ float g_wkt[D_MODEL * NKV * HD];
__device__ float g_wvt[D_MODEL * NKV * HD];
__device__ float g_w1t[D_MODEL * D_FF];
__device__ float g_w2t[D_FF * D_MODEL];
__device__ uint32_t g_khp[T_SEQ * 128];         // [token][kvh*32 + d2] bf16x2 hi
__device__ uint32_t g_klp[T_SEQ * 128];
__device__ uint32_t g_vhp[NKV * HD * (T_SEQ / 2)];  // [dim][token-pair]
__device__ uint32_t g_vlp[NKV * HD * (T_SEQ / 2)];

// ---------------- helpers ---------------------------------------------------
__device__ __forceinline__ uint32_t f2tf32(float x) {
    uint32_t r;
    asm("cvt.rna.tf32.f32 %0, %1;" : "=r"(r) : "f"(x));
    return r;
}
__device__ __forceinline__ float roundtf(float x) {
    return __uint_as_float(f2tf32(x));
}

__device__ __forceinline__ void mma_tf32(float* d, const uint32_t* a,
                                         const uint32_t* b, const float* c) {
    asm volatile(
        "mma.sync.aligned.m16n8k8.row.col.f32.tf32.tf32.f32 "
        "{%0,%1,%2,%3}, {%4,%5,%6,%7}, {%8,%9}, {%10,%11,%12,%13};"
        : "=f"(d[0]), "=f"(d[1]), "=f"(d[2]), "=f"(d[3])
        : "r"(a[0]), "r"(a[1]), "r"(a[2]), "r"(a[3]),
          "r"(b[0]), "r"(b[1]),
          "f"(c[0]), "f"(c[1]), "f"(c[2]), "f"(c[3]));
}

__device__ __forceinline__ void mma_bf16(float* d, const uint32_t* a,
                                         const uint32_t* b, const float* c) {
    asm volatile(
        "mma.sync.aligned.m16n8k16.row.col.f32.bf16.bf16.f32 "
        "{%0,%1,%2,%3}, {%4,%5,%6,%7}, {%8,%9}, {%10,%11,%12,%13};"
        : "=f"(d[0]), "=f"(d[1]), "=f"(d[2]), "=f"(d[3])
        : "r"(a[0]), "r"(a[1]), "r"(a[2]), "r"(a[3]),
          "r"(b[0]), "r"(b[1]),
          "f"(c[0]), "f"(c[1]), "f"(c[2]), "f"(c[3]));
}

__device__ __forceinline__ void ldsm_x4(uint32_t& r0, uint32_t& r1,
                                        uint32_t& r2, uint32_t& r3,
                                        uint32_t saddr) {
    asm volatile(
        "ldmatrix.sync.aligned.m8n8.x4.shared.b16 {%0,%1,%2,%3}, [%4];"
        : "=r"(r0), "=r"(r1), "=r"(r2), "=r"(r3) : "r"(saddr));
}

__device__ __forceinline__ uint32_t packbf(float x, float y) {
    __nv_bfloat162 t = __floats2bfloat162_rn(x, y);
    return *(uint32_t*)&t;
}
__device__ __forceinline__ void splitbf(float x, float y,
                                        uint32_t& hi, uint32_t& lo) {
    __nv_bfloat16 hx = __float2bfloat16_rn(x);
    __nv_bfloat16 hy = __float2bfloat16_rn(y);
    hi = packbf(__bfloat162float(hx), __bfloat162float(hy));
    lo = packbf(x - __bfloat162float(hx), y - __bfloat162float(hy));
}

__device__ __forceinline__ void cp16(float* smem_dst, const float* g) {
    uint32_t a = (uint32_t)__cvta_generic_to_shared(smem_dst);
    asm volatile("cp.async.ca.shared.global [%0], [%1], 16;" :: "r"(a), "l"(g));
}
__device__ __forceinline__ void cp16u(uint32_t* smem_dst, const uint32_t* g) {
    uint32_t a = (uint32_t)__cvta_generic_to_shared(smem_dst);
    asm volatile("cp.async.ca.shared.global [%0], [%1], 16;" :: "r"(a), "l"(g));
}

// ---------------- merged pre-round pass (launch 0) --------------------------
// Segment sizes in float4-blocks-of-256:
//   X 4096 | Wq 1024 | Wk 256 | Wv 256 | W1 4096 | W2 4096  => 13824 blocks
__global__ void round_all_kernel(
    const float* __restrict__ X,  const float* __restrict__ Wq,
    const float* __restrict__ Wk, const float* __restrict__ Wv,
    const float* __restrict__ W1, const float* __restrict__ W2)
{
    int b = blockIdx.x;
    const float* src;
    float* dst;
    int base;
    if      (b < 4096) { src = X;  dst = g_xt;  base = 0;    }
    else if (b < 5120) { src = Wq; dst = g_wqt; base = 4096; }
    else if (b < 5376) { src = Wk; dst = g_wkt; base = 5120; }
    else if (b < 5632) { src = Wv; dst = g_wvt; base = 5376; }
    else if (b < 9728) { src = W1; dst = g_w1t; base = 5632; }
    else               { src = W2; dst = g_w2t; base = 9728; }
    int i = (b - base) * 256 + threadIdx.x;
    float4 v = ((const float4*)src)[i];
    v.x = roundtf(v.x); v.y = roundtf(v.y);
    v.z = roundtf(v.z); v.w = roundtf(v.w);
    ((float4*)dst)[i] = v;
}

// ---------------- RoPE (launch 1, 3) ----------------------------------------
__global__ void rope_table_kernel() {
    int t = blockIdx.x, i = threadIdx.x;
    float inv = 1.0f / powf(10000.0f, (float)(2 * i) / 64.0f);
    float ang = (float)t * inv;
    g_cos[t * 32 + i] = cosf(ang);
    g_sin[t * 32 + i] = sinf(ang);
}

__global__ void rope_apply_kernel(float* __restrict__ x, int nh) {
    int t = blockIdx.x;
    int h = threadIdx.x >> 5;
    int i = threadIdx.x & 31;
    float c = g_cos[t * 32 + i];
    float s = g_sin[t * 32 + i];
    float* p = x + (size_t)t * nh * HD + h * HD;
    float x1 = p[i], x2 = p[i + 32];
    p[i]      = x1 * c - x2 * s;
    p[i + 32] = x2 * c + x1 * s;
}

// ---------------- fused KV prep (launch 4) -----------------------------------
// blocks [0,2048): rope+split K (2 tokens/block). [2048,4096): split V.
__global__ void prep_kv_kernel() {
    int b = blockIdx.x;
    if (b < 2048) {
        __shared__ float buf[2][NKV][64];
        int sub = threadIdx.x >> 7;           // 0/1 -> token
        int wt  = threadIdx.x & 127;
        int t = b * 2 + sub;
        int h = wt >> 5;
        int i = wt & 31;
        float c = g_cos[t * 32 + i];
        float s = g_sin[t * 32 + i];
        const float* p = g_k + (size_t)t * (NKV * HD) + h * HD;
        float x1 = p[i], x2 = p[i + 32];
        buf[sub][h][i]      = x1 * c - x2 * s;
        buf[sub][h][i + 32] = x2 * c + x1 * s;
        __syncthreads();
        float a = buf[sub][h][2 * i], bb = buf[sub][h][2 * i + 1];
        uint32_t hi, lo;
        splitbf(a, bb, hi, lo);
        g_khp[t * 128 + h * 32 + i] = hi;
        g_klp[t * 128 + h * 32 + i] = lo;
    } else {
        int idx = (b - 2048) * 256 + threadIdx.x;
        float2 v = *(const float2*)&g_v[(size_t)idx * 2];
        uint32_t hi, lo;
        splitbf(v.x, v.y, hi, lo);
        g_vhp[idx] = hi;
        g_vlp[idx] = lo;
    }
}

// ---------------- cp.async pipelined tf32 GEMM ------------------------------
#define AS_ST 20
#define BS_ST 136
#define AS_STAGE (128 * AS_ST)
#define BS_STAGE (16 * BS_ST)
#define GEMM_SMEM ((4 * (AS_STAGE + BS_STAGE)) * 4)

template <int SILU, int ROUND, int TRANSC>
__device__ __forceinline__ void gemm_body(
    const float* __restrict__ A, const float* __restrict__ B,
    float* __restrict__ C, int N, int K, int rowBase, int colBase)
{
    extern __shared__ float smp[];
    float* As = smp;
    float* Bs = smp + 4 * AS_STAGE;

    int tid  = threadIdx.x;
    int lane = tid & 31;
    int warp = tid >> 5;
    int wm = (warp & 1) * 64;
    int wn = (warp >> 1) * 32;

    int ar  = tid >> 2;
    int ac  = (tid & 3) << 2;
    int bkr = tid >> 5;
    int bc  = (tid & 31) << 2;

    const float* Ag0 = A + (size_t)(rowBase + ar) * K + ac;
    const float* Ag1 = A + (size_t)(rowBase + 64 + ar) * K + ac;
    const float* Bg  = B + colBase + bc;

    int nk = K >> 4;

#pragma unroll
    for (int s = 0; s < 3; s++) {
        if (s < nk) {
            float* as = As + s * AS_STAGE;
            float* bs = Bs + s * BS_STAGE;
            int k0 = s << 4;
            cp16(as + ar * AS_ST + ac,        Ag0 + k0);
            cp16(as + (ar + 64) * AS_ST + ac, Ag1 + k0);
            cp16(bs + bkr * BS_ST + bc,       Bg + (size_t)(k0 + bkr) * N);
            cp16(bs + (bkr + 8) * BS_ST + bc, Bg + (size_t)(k0 + 8 + bkr) * N);
        }
        asm volatile("cp.async.commit_group;");
    }

    float acc[4][4][4];
#pragma unroll
    for (int i = 0; i < 4; i++)
#pragma unroll
        for (int j = 0; j < 4; j++)
#pragma unroll
            for (int q = 0; q < 4; q++) acc[i][j][q] = 0.0f;

    for (int kt = 0; kt < nk; kt++) {
        asm volatile("cp.async.wait_group 2;");
        __syncthreads();

        int nx = kt + 3;
        if (nx < nk) {
            int bufn = nx & 3;
            float* as = As + bufn * AS_STAGE;
            float* bs = Bs + bufn * BS_STAGE;
            int k0 = nx << 4;
            cp16(as + ar * AS_ST + ac,        Ag0 + k0);
            cp16(as + (ar + 64) * AS_ST + ac, Ag1 + k0);
            cp16(bs + bkr * BS_ST + bc,       Bg + (size_t)(k0 + bkr) * N);
            cp16(bs + (bkr + 8) * BS_ST + bc, Bg + (size_t)(k0 + 8 + bkr) * N);
        }
        asm volatile("cp.async.commit_group;");

        const float* as = As + (kt & 3) * AS_STAGE;
        const float* bs = Bs + (kt & 3) * BS_STAGE;
#pragma unroll
        for (int ks = 0; ks < 16; ks += 8) {
            uint32_t af[4][4], bf[4][2];
#pragma unroll
            for (int i = 0; i < 4; i++) {
                int r = wm + i * 16 + (lane >> 2);
                int c = ks + (lane & 3);
                af[i][0] = __float_as_uint(as[r * AS_ST + c]);
                af[i][1] = __float_as_uint(as[(r + 8) * AS_ST + c]);
                af[i][2] = __float_as_uint(as[r * AS_ST + c + 4]);
                af[i][3] = __float_as_uint(as[(r + 8) * AS_ST + c + 4]);
            }
#pragma unroll
            for (int j = 0; j < 4; j++) {
                int kk = ks + (lane & 3);
                int n  = wn + j * 8 + (lane >> 2);
                bf[j][0] = __float_as_uint(bs[kk * BS_ST + n]);
                bf[j][1] = __float_as_uint(bs[(kk + 4) * BS_ST + n]);
            }
#pragma unroll
            for (int i = 0; i < 4; i++)
#pragma unroll
                for (int j = 0; j < 4; j++)
                    mma_tf32(acc[i][j], af[i], bf[j], acc[i][j]);
        }
    }

#pragma unroll
    for (int i = 0; i < 4; i++) {
        int r0 = rowBase + wm + i * 16 + (lane >> 2);
#pragma unroll
        for (int j = 0; j < 4; j++) {
            int c0 = colBase + wn + j * 8 + (lane & 3) * 2;
            float2 v0, v1;
            v0.x = acc[i][j][0]; v0.y = acc[i][j][1];
            v1.x = acc[i][j][2]; v1.y = acc[i][j][3];
            if (SILU) {
                v0.x = v0.x / (1.0f + expf(-v0.x));
                v0.y = v0.y / (1.0f + expf(-v0.y));
                v1.x = v1.x / (1.0f + expf(-v1.x));
                v1.y = v1.y / (1.0f + expf(-v1.y));
            }
            if (ROUND) {
                v0.x = roundtf(v0.x); v0.y = roundtf(v0.y);
                v1.x = roundtf(v1.x); v1.y = roundtf(v1.y);
            }
            if (TRANSC) {
                C[(size_t)c0 * T_SEQ + r0]           = v0.x;
                C[(size_t)(c0 + 1) * T_SEQ + r0]     = v0.y;
                C[(size_t)c0 * T_SEQ + r0 + 8]       = v1.x;
                C[(size_t)(c0 + 1) * T_SEQ + r0 + 8] = v1.y;
            } else {
                *(float2*)&C[(size_t)r0 * N + c0]       = v0;
                *(float2*)&C[(size_t)(r0 + 8) * N + c0] = v1;
            }
        }
    }
}

template <int SILU, int ROUND>
__global__ void __launch_bounds__(256, 2) tgemm2_kernel(
    const float* __restrict__ A, const float* __restrict__ B,
    float* __restrict__ C, int N, int K)
{
    gemm_body<SILU, ROUND, 0>(A, B, C, N, K, blockIdx.y * 128, blockIdx.x * 128);
}

__global__ void __launch_bounds__(256, 2) qkv_kernel(
    const float* __restrict__ Xt,
    const float* __restrict__ Wqt, const float* __restrict__ Wkt,
    const float* __restrict__ Wvt,
    float* __restrict__ q, float* __restrict__ k, float* __restrict__ v)
{
    int bx = blockIdx.x;
    if (bx < 8) {
        gemm_body<0, 0, 0>(Xt, Wqt, q, D_MODEL, D_MODEL,
                           blockIdx.y * 128, bx * 128);
    } else if (bx < 10) {
        gemm_body<0, 0, 0>(Xt, Wkt, k, NKV * HD, D_MODEL,
                           blockIdx.y * 128, (bx - 8) * 128);
    } else {
        gemm_body<0, 0, 1>(Xt, Wvt, v, NKV * HD, D_MODEL,
                           blockIdx.y * 128, (bx - 10) * 128);
    }
}

// ---------------- bf16 MMA flash attention (BM=128, BN=128) ----------------
// Per stage: K 128 rows x 68 u32 (32 hi | 32 lo | pad),
//            V  64 rows x 132 u32 (64 hi | 64 lo | pad).
#define KR_K 68
#define KR_V 132
#define KARR (128 * KR_K)           // 8704 u32
#define VARR (64 * KR_V)            // 8448 u32
#define STAGE_U (KARR + VARR)       // 17152 u32
#define ATT_SMEM (2 * STAGE_U * 4)  // 137216 bytes

__global__ void __launch_bounds__(256) attn_bf16_kernel(
    const float* __restrict__ qp,
    const uint32_t* __restrict__ khp, const uint32_t* __restrict__ klp,
    const uint32_t* __restrict__ vhp, const uint32_t* __restrict__ vlp,
    float* __restrict__ op)
{
    extern __shared__ uint32_t smu[];
    float* Qs = (float*)smu;                  // Q staging, pre-loop only

    int qb   = gridDim.x - 1 - blockIdx.x;    // heavy blocks first
    int h    = blockIdx.y;
    int kvh  = h >> 2;
    int tid  = threadIdx.x;
    int lane = tid & 31;
    int warp = tid >> 5;
    int gid  = lane >> 2;
    int tig  = lane & 3;
    int tg2  = tig * 2;
    int fr   = warp * 16 + gid;

    // ---- stage Q tile ----
#pragma unroll
    for (int i = 0; i < 8; i++) {
        int e = tid + 256 * i;
        int r = e >> 4, c4 = (e & 15) << 2;
        *(float4*)&Qs[r * 64 + c4] =
            *(const float4*)&qp[(size_t)(qb * 128 + r) * D_MODEL + h * HD + c4];
    }
    __syncthreads();

    uint32_t qhi[4][4], qlo[4][4];
#pragma unroll
    for (int kt = 0; kt < 4; kt++) {
        float2 x0 = *(float2*)&Qs[fr * 64 + kt * 16 + tg2];
        float2 x1 = *(float2*)&Qs[(fr + 8) * 64 + kt * 16 + tg2];
        float2 x2 = *(float2*)&Qs[fr * 64 + kt * 16 + tg2 + 8];
        float2 x3 = *(float2*)&Qs[(fr + 8) * 64 + kt * 16 + tg2 + 8];
        splitbf(x0.x * 0.125f, x0.y * 0.125f, qhi[kt][0], qlo[kt][0]);
        splitbf(x1.x * 0.125f, x1.y * 0.125f, qhi[kt][1], qlo[kt][1]);
        splitbf(x2.x * 0.125f, x2.y * 0.125f, qhi[kt][2], qlo[kt][2]);
        splitbf(x3.x * 0.125f, x3.y * 0.125f, qhi[kt][3], qlo[kt][3]);
    }
    __syncthreads();   // Q reads done before cp.async overwrites stage 0

    // ldmatrix per-lane offsets (separate strides for K and V)
    uint32_t smem_b = (uint32_t)__cvta_generic_to_shared(smu);
    int loK = (lane & 7) * KR_K + ((lane >> 3) & 1) * 4 + (lane >> 4) * 32;
    int loV = (lane & 7) * KR_V + ((lane >> 3) & 1) * 4 + (lane >> 4) * 64;

    // load slots: K: row tid>>1 (0..127), 16-u32 half (tid&1)
    int rK = tid >> 1, hK = (tid & 1) * 16;
    // V: row tid>>2 (0..63), 16-u32 quarter (tid&3)
    int rV = tid >> 2, qV = (tid & 3) * 16;
    const uint32_t* khB = khp + kvh * 32;
    const uint32_t* klB = klp + kvh * 32;
    const uint32_t* vhB = vhp + (size_t)(kvh * HD + rV) * (T_SEQ / 2);
    const uint32_t* vlB = vlp + (size_t)(kvh * HD + rV) * (T_SEQ / 2);

    int kbmax = qb;

    // prefetch tile 0 into stage 0
    {
        uint32_t* Ks = smu;
        uint32_t* Vs = smu + KARR;
#pragma unroll
        for (int j = 0; j < 4; j++) {
            int c = hK + j * 4;
            cp16u(Ks + rK * KR_K + c,      khB + (size_t)rK * 128 + c);
            cp16u(Ks + rK * KR_K + 32 + c, klB + (size_t)rK * 128 + c);
        }
#pragma unroll
        for (int j = 0; j < 4; j++) {
            int c = qV + j * 4;
            cp16u(Vs + rV * KR_V + c,      vhB + c);
            cp16u(Vs + rV * KR_V + 64 + c, vlB + c);
        }
        asm volatile("cp.async.commit_group;");
    }

    float oacc[8][4];
#pragma unroll
    for (int nt = 0; nt < 8; nt++)
#pragma unroll
        for (int j = 0; j < 4; j++) oacc[nt][j] = 0.0f;
    float m0 = -1e30f, m1 = -1e30f, l0 = 0.0f, l1 = 0.0f;

    for (int kb = 0; kb <= kbmax; kb++) {
        asm volatile("cp.async.wait_group 0;");
        __syncthreads();

        // prefetch next tile
        if (kb < kbmax) {
            uint32_t* st = smu + ((kb + 1) & 1) * STAGE_U;
            uint32_t* Ks = st;
            uint32_t* Vs = st + KARR;
            int tk = (kb + 1) * 128;
            int tv = (kb + 1) * 64;
#pragma unroll
            for (int j = 0; j < 4; j++) {
                int c = hK + j * 4;
                cp16u(Ks + rK * KR_K + c,      khB + (size_t)(tk + rK) * 128 + c);
                cp16u(Ks + rK * KR_K + 32 + c, klB + (size_t)(tk + rK) * 128 + c);
            }
#pragma unroll
            for (int j = 0; j < 4; j++) {
                int c = qV + j * 4;
                cp16u(Vs + rV * KR_V + c,      vhB + tv + c);
                cp16u(Vs + rV * KR_V + 64 + c, vlB + tv + c);
            }
        }
        asm volatile("cp.async.commit_group;");

        uint32_t stK = smem_b + 4 * ((kb & 1) * STAGE_U + loK);
        uint32_t stV = smem_b + 4 * ((kb & 1) * STAGE_U + KARR + loV);

        // ---- S = (Q/8) @ K^T : 3-term bf16 ----
        float sacc[16][4];
#pragma unroll
        for (int nt = 0; nt < 16; nt++)
#pragma unroll
            for (int j = 0; j < 4; j++) sacc[nt][j] = 0.0f;

#pragma unroll
        for (int nt = 0; nt < 16; nt++) {
            uint32_t rowa = stK + nt * (8 * KR_K * 4);
#pragma unroll
            for (int ks = 0; ks < 4; ks++) {
                uint32_t bh0, bh1, bl0, bl1;
                ldsm_x4(bh0, bh1, bl0, bl1, rowa + ks * 32);
                uint32_t bh[2] = {bh0, bh1}, bl[2] = {bl0, bl1};
                mma_bf16(sacc[nt], qhi[ks], bh, sacc[nt]);
                mma_bf16(sacc[nt], qlo[ks], bh, sacc[nt]);
                mma_bf16(sacc[nt], qhi[ks], bl, sacc[nt]);
            }
        }

        // ---- causal mask (diagonal tile only) ----
        if (kb == qb) {
            int grow0 = qb * 128 + fr;
            int grow1 = grow0 + 8;
#pragma unroll
            for (int nt = 0; nt < 16; nt++) {
                int gc = kb * 128 + nt * 8 + tg2;
                if (gc     > grow0) sacc[nt][0] = -1e30f;
                if (gc + 1 > grow0) sacc[nt][1] = -1e30f;
                if (gc     > grow1) sacc[nt][2] = -1e30f;
                if (gc + 1 > grow1) sacc[nt][3] = -1e30f;
            }
        }

        // ---- online softmax ----
        float mx0 = -1e30f, mx1 = -1e30f;
#pragma unroll
        for (int nt = 0; nt < 16; nt++) {
            mx0 = fmaxf(mx0, fmaxf(sacc[nt][0], sacc[nt][1]));
            mx1 = fmaxf(mx1, fmaxf(sacc[nt][2], sacc[nt][3]));
        }
        mx0 = fmaxf(mx0, __shfl_xor_sync(0xffffffffu, mx0, 1));
        mx0 = fmaxf(mx0, __shfl_xor_sync(0xffffffffu, mx0, 2));
        mx1 = fmaxf(mx1, __shfl_xor_sync(0xffffffffu, mx1, 1));
        mx1 = fmaxf(mx1, __shfl_xor_sync(0xffffffffu, mx1, 2));

        float mn0 = fmaxf(m0, mx0), mn1 = fmaxf(m1, mx1);
        float c0 = __expf(m0 - mn0), c1 = __expf(m1 - mn1);
        float rs0 = 0.0f, rs1 = 0.0f;
#pragma unroll
        for (int nt = 0; nt < 16; nt++) {
            float p0 = __expf(sacc[nt][0] - mn0);
            float p1 = __expf(sacc[nt][1] - mn0);
            float p2 = __expf(sacc[nt][2] - mn1);
            float p3 = __expf(sacc[nt][3] - mn1);
            sacc[nt][0] = p0; sacc[nt][1] = p1;
            sacc[nt][2] = p2; sacc[nt][3] = p3;
            rs0 += p0 + p1;
            rs1 += p2 + p3;
        }
        rs0 += __shfl_xor_sync(0xffffffffu, rs0, 1);
        rs0 += __shfl_xor_sync(0xffffffffu, rs0, 2);
        rs1 += __shfl_xor_sync(0xffffffffu, rs1, 1);
        rs1 += __shfl_xor_sync(0xffffffffu, rs1, 2);
        l0 = l0 * c0 + rs0;  m0 = mn0;
        l1 = l1 * c1 + rs1;  m1 = mn1;
#pragma unroll
        for (int nt = 0; nt < 8; nt++) {
            oacc[nt][0] *= c0; oacc[nt][1] *= c0;
            oacc[nt][2] *= c1; oacc[nt][3] *= c1;
        }

        // ---- O += P @ V : A from sacc regs, B via ldmatrix ----
#pragma unroll
        for (int kt = 0; kt < 8; kt++) {
            uint32_t ahi[4], alo[4];
            splitbf(sacc[2*kt][0],     sacc[2*kt][1],     ahi[0], alo[0]);
            splitbf(sacc[2*kt][2],     sacc[2*kt][3],     ahi[1], alo[1]);
            splitbf(sacc[2*kt + 1][0], sacc[2*kt + 1][1], ahi[2], alo[2]);
            splitbf(sacc[2*kt + 1][2], sacc[2*kt + 1][3], ahi[3], alo[3]);
#pragma unroll
            for (int nt = 0; nt < 8; nt++) {
                uint32_t bh0, bh1, bl0, bl1;
                ldsm_x4(bh0, bh1, bl0, bl1,
                        stV + nt * (8 * KR_V * 4) + kt * 32);
                uint32_t bh[2] = {bh0, bh1}, bl[2] = {bl0, bl1};
                mma_bf16(oacc[nt], ahi, bh, oacc[nt]);
                mma_bf16(oacc[nt], alo, bh, oacc[nt]);
                mma_bf16(oacc[nt], ahi, bl, oacc[nt]);
            }
        }
    }

    // ---- finalize ----
    float inv0 = 1.0f / l0, inv1 = 1.0f / l1;
#pragma unroll
    for (int nt = 0; nt < 8; nt++) {
        int col = h * HD + nt * 8 + tg2;
        float2 w0, w1;
        w0.x = roundtf(oacc[nt][0] * inv0); w0.y = roundtf(oacc[nt][1] * inv0);
        w1.x = roundtf(oacc[nt][2] * inv1); w1.y = roundtf(oacc[nt][3] * inv1);
        *(float2*)&op[(size_t)(qb * 128 + fr) * D_MODEL + col]     = w0;
        *(float2*)&op[(size_t)(qb * 128 + fr + 8) * D_MODEL + col] = w1;
    }
}

// ---------------- launch ---------------------------------------------------
extern "C" void kernel_launch(void* const* d_in, const int* in_sizes, int n_in,
                              void* d_out, int out_size)
{
    const float* X  = (const float*)d_in[0];
    const float* Wq = (const float*)d_in[1];
    const float* Wk = (const float*)d_in[2];
    const float* Wv = (const float*)d_in[3];
    const float* W1 = (const float*)d_in[4];
    const float* W2 = (const float*)d_in[5];
    float* out = (float*)d_out;

    float *gq, *gk, *gv, *ga, *gh;
    float *gxt, *gwqt, *gwkt, *gwvt, *gw1t, *gw2t;
    uint32_t *gkh, *gkl, *gvh, *gvl;
    cudaGetSymbolAddress((void**)&gq, g_q);
    cudaGetSymbolAddress((void**)&gk, g_k);
    cudaGetSymbolAddress((void**)&gv, g_v);
    cudaGetSymbolAddress((void**)&ga, g_attn);
    cudaGetSymbolAddress((void**)&gh, g_h1);
    cudaGetSymbolAddress((void**)&gxt, g_xt);
    cudaGetSymbolAddress((void**)&gwqt, g_wqt);
    cudaGetSymbolAddress((void**)&gwkt, g_wkt);
    cudaGetSymbolAddress((void**)&gwvt, g_wvt);
    cudaGetSymbolAddress((void**)&gw1t, g_w1t);
    cudaGetSymbolAddress((void**)&gw2t, g_w2t);
    cudaGetSymbolAddress((void**)&gkh, g_khp);
    cudaGetSymbolAddress((void**)&gkl, g_klp);
    cudaGetSymbolAddress((void**)&gvh, g_vhp);
    cudaGetSymbolAddress((void**)&gvl, g_vlp);

    cudaFuncSetAttribute(attn_bf16_kernel,
                         cudaFuncAttributeMaxDynamicSharedMemorySize, ATT_SMEM);
    cudaFuncSetAttribute(qkv_kernel,
                         cudaFuncAttributeMaxDynamicSharedMemorySize, GEMM_SMEM);
    cudaFuncSetAttribute(tgemm2_kernel<1, 1>,
                         cudaFuncAttributeMaxDynamicSharedMemorySize, GEMM_SMEM);
    cudaFuncSetAttribute(tgemm2_kernel<0, 0>,
                         cudaFuncAttributeMaxDynamicSharedMemorySize, GEMM_SMEM);

    // launch 0: merged tf32 pre-round (13824 segment blocks)
    round_all_kernel<<<13824, 256>>>(X, Wq, Wk, Wv, W1, W2);
    // launch 1
    rope_table_kernel<<<T_SEQ, 32>>>();
    // launch 2: fused QKV projection (V written transposed)
    qkv_kernel<<<dim3(12, T_SEQ / 128), 256, GEMM_SMEM>>>(
        gxt, gwqt, gwkt, gwvt, gq, gk, gv);
    // launch 3: RoPE Q in-place
    rope_apply_kernel<<<T_SEQ, NH * 32>>>(gq, NH);
    // launch 4: fused K rope+split and V split
    prep_kv_kernel<<<4096, 256>>>();
    // launch 5: attention (profiled by ncu -s 5)
    attn_bf16_kernel<<<dim3(T_SEQ / 128, NH), 256, ATT_SMEM>>>(
        gq, gkh, gkl, gvh, gvl, ga);
    // launches 6-7: MLP
    tgemm2_kernel<1, 1><<<dim3(D_FF / 128, T_SEQ / 128), 256, GEMM_SMEM>>>(
        ga, gw1t, gh, D_FF, D_MODEL);
    tgemm2_kernel<0, 0><<<dim3(D_MODEL / 128, T_SEQ / 128), 256, GEMM_SMEM>>>(
        gh, gw2t, out, D_MODEL, D_FF);
}

// round 10
// speedup vs baseline: 3.3101x; 1.0120x over previous
#include <cuda_runtime.h>
#include <cuda_bf16.h>
#include <math.h>
#include <stdint.h>

// Problem constants
#define T_SEQ  4096
#define D_MODEL 1024
#define NH     16
#define NKV    4
#define HD     64
#define D_FF   4096

// ---------------- scratch (device globals; no allocation allowed) ----------
__device__ float g_q[T_SEQ * D_MODEL];
__device__ float g_k[T_SEQ * NKV * HD];         // [token][256] (pre-rope)
__device__ float g_v[NKV * HD * T_SEQ];         // TRANSPOSED [256][4096]
__device__ float g_attn[T_SEQ * D_MODEL];       // tf32-rounded
__device__ float g_h1[(size_t)T_SEQ * D_FF];    // tf32-rounded
__device__ float g_cos[T_SEQ * 32];
__device__ float g_sin[T_SEQ * 32];
__device__ float g_xt[T_SEQ * D_MODEL];
__device__ float g_wqt[D_MODEL * D_MODEL];
__device__ float g_wkt[D_MODEL * NKV * HD];
__device__ float g_wvt[D_MODEL * NKV * HD];
__device__ float g_w1t[D_MODEL * D_FF];
__device__ float g_w2t[D_FF * D_MODEL];
__device__ uint32_t g_khp[T_SEQ * 128];         // [token][kvh*32 + d2] bf16x2 hi
__device__ uint32_t g_klp[T_SEQ * 128];
__device__ uint32_t g_vhp[NKV * HD * (T_SEQ / 2)];  // [dim][token-pair]
__device__ uint32_t g_vlp[NKV * HD * (T_SEQ / 2)];

// ---------------- helpers ---------------------------------------------------
__device__ __forceinline__ uint32_t f2tf32(float x) {
    uint32_t r;
    asm("cvt.rna.tf32.f32 %0, %1;" : "=r"(r) : "f"(x));
    return r;
}
__device__ __forceinline__ float roundtf(float x) {
    return __uint_as_float(f2tf32(x));
}

__device__ __forceinline__ void mma_tf32(float* d, const uint32_t* a,
                                         const uint32_t* b, const float* c) {
    asm volatile(
        "mma.sync.aligned.m16n8k8.row.col.f32.tf32.tf32.f32 "
        "{%0,%1,%2,%3}, {%4,%5,%6,%7}, {%8,%9}, {%10,%11,%12,%13};"
        : "=f"(d[0]), "=f"(d[1]), "=f"(d[2]), "=f"(d[3])
        : "r"(a[0]), "r"(a[1]), "r"(a[2]), "r"(a[3]),
          "r"(b[0]), "r"(b[1]),
          "f"(c[0]), "f"(c[1]), "f"(c[2]), "f"(c[3]));
}

__device__ __forceinline__ void mma_bf16(float* d, const uint32_t* a,
                                         const uint32_t* b, const float* c) {
    asm volatile(
        "mma.sync.aligned.m16n8k16.row.col.f32.bf16.bf16.f32 "
        "{%0,%1,%2,%3}, {%4,%5,%6,%7}, {%8,%9}, {%10,%11,%12,%13};"
        : "=f"(d[0]), "=f"(d[1]), "=f"(d[2]), "=f"(d[3])
        : "r"(a[0]), "r"(a[1]), "r"(a[2]), "r"(a[3]),
          "r"(b[0]), "r"(b[1]),
          "f"(c[0]), "f"(c[1]), "f"(c[2]), "f"(c[3]));
}

__device__ __forceinline__ void ldsm_x4(uint32_t& r0, uint32_t& r1,
                                        uint32_t& r2, uint32_t& r3,
                                        uint32_t saddr) {
    asm volatile(
        "ldmatrix.sync.aligned.m8n8.x4.shared.b16 {%0,%1,%2,%3}, [%4];"
        : "=r"(r0), "=r"(r1), "=r"(r2), "=r"(r3) : "r"(saddr));
}

__device__ __forceinline__ uint32_t packbf(float x, float y) {
    __nv_bfloat162 t = __floats2bfloat162_rn(x, y);
    return *(uint32_t*)&t;
}
__device__ __forceinline__ void splitbf(float x, float y,
                                        uint32_t& hi, uint32_t& lo) {
    __nv_bfloat16 hx = __float2bfloat16_rn(x);
    __nv_bfloat16 hy = __float2bfloat16_rn(y);
    hi = packbf(__bfloat162float(hx), __bfloat162float(hy));
    lo = packbf(x - __bfloat162float(hx), y - __bfloat162float(hy));
}

__device__ __forceinline__ void cp16(float* smem_dst, const float* g) {
    uint32_t a = (uint32_t)__cvta_generic_to_shared(smem_dst);
    asm volatile("cp.async.ca.shared.global [%0], [%1], 16;" :: "r"(a), "l"(g));
}
__device__ __forceinline__ void cp16u(uint32_t* smem_dst, const uint32_t* g) {
    uint32_t a = (uint32_t)__cvta_generic_to_shared(smem_dst);
    asm volatile("cp.async.ca.shared.global [%0], [%1], 16;" :: "r"(a), "l"(g));
}

// ---------------- merged pre-round pass (launch 0) --------------------------
// Segment sizes in float4-blocks-of-256:
//   X 4096 | Wq 1024 | Wk 256 | Wv 256 | W1 4096 | W2 4096  => 13824 blocks
__global__ void round_all_kernel(
    const float* __restrict__ X,  const float* __restrict__ Wq,
    const float* __restrict__ Wk, const float* __restrict__ Wv,
    const float* __restrict__ W1, const float* __restrict__ W2)
{
    int b = blockIdx.x;
    const float* src;
    float* dst;
    int base;
    if      (b < 4096) { src = X;  dst = g_xt;  base = 0;    }
    else if (b < 5120) { src = Wq; dst = g_wqt; base = 4096; }
    else if (b < 5376) { src = Wk; dst = g_wkt; base = 5120; }
    else if (b < 5632) { src = Wv; dst = g_wvt; base = 5376; }
    else if (b < 9728) { src = W1; dst = g_w1t; base = 5632; }
    else               { src = W2; dst = g_w2t; base = 9728; }
    int i = (b - base) * 256 + threadIdx.x;
    float4 v = ((const float4*)src)[i];
    v.x = roundtf(v.x); v.y = roundtf(v.y);
    v.z = roundtf(v.z); v.w = roundtf(v.w);
    ((float4*)dst)[i] = v;
}

// ---------------- RoPE ------------------------------------------------------
__global__ void rope_table_kernel() {
    int t = blockIdx.x, i = threadIdx.x;
    float inv = 1.0f / powf(10000.0f, (float)(2 * i) / 64.0f);
    float ang = (float)t * inv;
    g_cos[t * 32 + i] = cosf(ang);
    g_sin[t * 32 + i] = sinf(ang);
}

__global__ void rope_apply_kernel(float* __restrict__ x, int nh) {
    int t = blockIdx.x;
    int h = threadIdx.x >> 5;
    int i = threadIdx.x & 31;
    float c = g_cos[t * 32 + i];
    float s = g_sin[t * 32 + i];
    float* p = x + (size_t)t * nh * HD + h * HD;
    float x1 = p[i], x2 = p[i + 32];
    p[i]      = x1 * c - x2 * s;
    p[i + 32] = x2 * c + x1 * s;
}

// ---------------- fused KV prep ---------------------------------------------
// blocks [0,2048): rope+split K (2 tokens/block). [2048,4096): split V.
__global__ void prep_kv_kernel() {
    int b = blockIdx.x;
    if (b < 2048) {
        __shared__ float buf[2][NKV][64];
        int sub = threadIdx.x >> 7;
        int wt  = threadIdx.x & 127;
        int t = b * 2 + sub;
        int h = wt >> 5;
        int i = wt & 31;
        float c = g_cos[t * 32 + i];
        float s = g_sin[t * 32 + i];
        const float* p = g_k + (size_t)t * (NKV * HD) + h * HD;
        float x1 = p[i], x2 = p[i + 32];
        buf[sub][h][i]      = x1 * c - x2 * s;
        buf[sub][h][i + 32] = x2 * c + x1 * s;
        __syncthreads();
        float a = buf[sub][h][2 * i], bb = buf[sub][h][2 * i + 1];
        uint32_t hi, lo;
        splitbf(a, bb, hi, lo);
        g_khp[t * 128 + h * 32 + i] = hi;
        g_klp[t * 128 + h * 32 + i] = lo;
    } else {
        int idx = (b - 2048) * 256 + threadIdx.x;
        float2 v = *(const float2*)&g_v[(size_t)idx * 2];
        uint32_t hi, lo;
        splitbf(v.x, v.y, hi, lo);
        g_vhp[idx] = hi;
        g_vlp[idx] = lo;
    }
}

// ---------------- cp.async pipelined tf32 GEMM (A-frags via ldmatrix) -------
#define AS_ST 20
#define BS_ST 136
#define AS_STAGE (128 * AS_ST)
#define BS_STAGE (16 * BS_ST)
#define GEMM_SMEM ((4 * (AS_STAGE + BS_STAGE)) * 4)

template <int SILU, int ROUND, int TRANSC>
__device__ __forceinline__ void gemm_body(
    const float* __restrict__ A, const float* __restrict__ B,
    float* __restrict__ C, int N, int K, int rowBase, int colBase)
{
    extern __shared__ float smp[];
    float* As = smp;
    float* Bs = smp + 4 * AS_STAGE;

    int tid  = threadIdx.x;
    int lane = tid & 31;
    int warp = tid >> 5;
    int wm = (warp & 1) * 64;
    int wn = (warp >> 1) * 32;

    int ar  = tid >> 2;
    int ac  = (tid & 3) << 2;
    int bkr = tid >> 5;
    int bc  = (tid & 31) << 2;

    const float* Ag0 = A + (size_t)(rowBase + ar) * K + ac;
    const float* Ag1 = A + (size_t)(rowBase + 64 + ar) * K + ac;
    const float* Bg  = B + colBase + bc;

    // ldmatrix lane offset for tf32 A-fragments:
    // matrices: m0 rows 0-7 cols ks..ks+3, m1 rows 8-15 same cols,
    //           m2 rows 0-7 cols ks+4.., m3 rows 8-15 cols ks+4..
    uint32_t smem_b = (uint32_t)__cvta_generic_to_shared(smp);
    uint32_t loA = ((wm + (lane & 7) + ((lane >> 3) & 1) * 8) * AS_ST
                    + (lane >> 4) * 4) * 4;

    int nk = K >> 4;

#pragma unroll
    for (int s = 0; s < 3; s++) {
        if (s < nk) {
            float* as = As + s * AS_STAGE;
            float* bs = Bs + s * BS_STAGE;
            int k0 = s << 4;
            cp16(as + ar * AS_ST + ac,        Ag0 + k0);
            cp16(as + (ar + 64) * AS_ST + ac, Ag1 + k0);
            cp16(bs + bkr * BS_ST + bc,       Bg + (size_t)(k0 + bkr) * N);
            cp16(bs + (bkr + 8) * BS_ST + bc, Bg + (size_t)(k0 + 8 + bkr) * N);
        }
        asm volatile("cp.async.commit_group;");
    }

    float acc[4][4][4];
#pragma unroll
    for (int i = 0; i < 4; i++)
#pragma unroll
        for (int j = 0; j < 4; j++)
#pragma unroll
            for (int q = 0; q < 4; q++) acc[i][j][q] = 0.0f;

    for (int kt = 0; kt < nk; kt++) {
        asm volatile("cp.async.wait_group 2;");
        __syncthreads();

        int nx = kt + 3;
        if (nx < nk) {
            int bufn = nx & 3;
            float* as = As + bufn * AS_STAGE;
            float* bs = Bs + bufn * BS_STAGE;
            int k0 = nx << 4;
            cp16(as + ar * AS_ST + ac,        Ag0 + k0);
            cp16(as + (ar + 64) * AS_ST + ac, Ag1 + k0);
            cp16(bs + bkr * BS_ST + bc,       Bg + (size_t)(k0 + bkr) * N);
            cp16(bs + (bkr + 8) * BS_ST + bc, Bg + (size_t)(k0 + 8 + bkr) * N);
        }
        asm volatile("cp.async.commit_group;");

        uint32_t asb = smem_b + ((kt & 3) * AS_STAGE) * 4 + loA;
        const float* bs = Bs + (kt & 3) * BS_STAGE;
#pragma unroll
        for (int ks = 0; ks < 16; ks += 8) {
            uint32_t af[4][4], bf[4][2];
#pragma unroll
            for (int i = 0; i < 4; i++) {
                ldsm_x4(af[i][0], af[i][1], af[i][2], af[i][3],
                        asb + (i * 16 * AS_ST + ks) * 4);
            }
#pragma unroll
            for (int j = 0; j < 4; j++) {
                int kk = ks + (lane & 3);
                int n  = wn + j * 8 + (lane >> 2);
                bf[j][0] = __float_as_uint(bs[kk * BS_ST + n]);
                bf[j][1] = __float_as_uint(bs[(kk + 4) * BS_ST + n]);
            }
#pragma unroll
            for (int i = 0; i < 4; i++)
#pragma unroll
                for (int j = 0; j < 4; j++)
                    mma_tf32(acc[i][j], af[i], bf[j], acc[i][j]);
        }
    }

#pragma unroll
    for (int i = 0; i < 4; i++) {
        int r0 = rowBase + wm + i * 16 + (lane >> 2);
#pragma unroll
        for (int j = 0; j < 4; j++) {
            int c0 = colBase + wn + j * 8 + (lane & 3) * 2;
            float2 v0, v1;
            v0.x = acc[i][j][0]; v0.y = acc[i][j][1];
            v1.x = acc[i][j][2]; v1.y = acc[i][j][3];
            if (SILU) {
                v0.x = v0.x / (1.0f + expf(-v0.x));
                v0.y = v0.y / (1.0f + expf(-v0.y));
                v1.x = v1.x / (1.0f + expf(-v1.x));
                v1.y = v1.y / (1.0f + expf(-v1.y));
            }
            if (ROUND) {
                v0.x = roundtf(v0.x); v0.y = roundtf(v0.y);
                v1.x = roundtf(v1.x); v1.y = roundtf(v1.y);
            }
            if (TRANSC) {
                C[(size_t)c0 * T_SEQ + r0]           = v0.x;
                C[(size_t)(c0 + 1) * T_SEQ + r0]     = v0.y;
                C[(size_t)c0 * T_SEQ + r0 + 8]       = v1.x;
                C[(size_t)(c0 + 1) * T_SEQ + r0 + 8] = v1.y;
            } else {
                *(float2*)&C[(size_t)r0 * N + c0]       = v0;
                *(float2*)&C[(size_t)(r0 + 8) * N + c0] = v1;
            }
        }
    }
}

template <int SILU, int ROUND>
__global__ void __launch_bounds__(256, 2) tgemm2_kernel(
    const float* __restrict__ A, const float* __restrict__ B,
    float* __restrict__ C, int N, int K)
{
    gemm_body<SILU, ROUND, 0>(A, B, C, N, K, blockIdx.y * 128, blockIdx.x * 128);
}

__global__ void __launch_bounds__(256, 2) qkv_kernel(
    const float* __restrict__ Xt,
    const float* __restrict__ Wqt, const float* __restrict__ Wkt,
    const float* __restrict__ Wvt,
    float* __restrict__ q, float* __restrict__ k, float* __restrict__ v)
{
    int bx = blockIdx.x;
    if (bx < 8) {
        gemm_body<0, 0, 0>(Xt, Wqt, q, D_MODEL, D_MODEL,
                           blockIdx.y * 128, bx * 128);
    } else if (bx < 10) {
        gemm_body<0, 0, 0>(Xt, Wkt, k, NKV * HD, D_MODEL,
                           blockIdx.y * 128, (bx - 8) * 128);
    } else {
        gemm_body<0, 0, 1>(Xt, Wvt, v, NKV * HD, D_MODEL,
                           blockIdx.y * 128, (bx - 10) * 128);
    }
}

// ---------------- bf16 MMA flash attention (BM=128, BN=128) ----------------
#define KR_K 68
#define KR_V 132
#define KARR (128 * KR_K)           // 8704 u32
#define VARR (64 * KR_V)            // 8448 u32
#define STAGE_U (KARR + VARR)       // 17152 u32
#define ATT_SMEM (2 * STAGE_U * 4)  // 137216 bytes

__global__ void __launch_bounds__(256) attn_bf16_kernel(
    const float* __restrict__ qp,
    const uint32_t* __restrict__ khp, const uint32_t* __restrict__ klp,
    const uint32_t* __restrict__ vhp, const uint32_t* __restrict__ vlp,
    float* __restrict__ op)
{
    extern __shared__ uint32_t smu[];
    float* Qs = (float*)smu;

    int qb   = gridDim.x - 1 - blockIdx.x;
    int h    = blockIdx.y;
    int kvh  = h >> 2;
    int tid  = threadIdx.x;
    int lane = tid & 31;
    int warp = tid >> 5;
    int gid  = lane >> 2;
    int tig  = lane & 3;
    int tg2  = tig * 2;
    int fr   = warp * 16 + gid;

#pragma unroll
    for (int i = 0; i < 8; i++) {
        int e = tid + 256 * i;
        int r = e >> 4, c4 = (e & 15) << 2;
        *(float4*)&Qs[r * 64 + c4] =
            *(const float4*)&qp[(size_t)(qb * 128 + r) * D_MODEL + h * HD + c4];
    }
    __syncthreads();

    uint32_t qhi[4][4], qlo[4][4];
#pragma unroll
    for (int kt = 0; kt < 4; kt++) {
        float2 x0 = *(float2*)&Qs[fr * 64 + kt * 16 + tg2];
        float2 x1 = *(float2*)&Qs[(fr + 8) * 64 + kt * 16 + tg2];
        float2 x2 = *(float2*)&Qs[fr * 64 + kt * 16 + tg2 + 8];
        float2 x3 = *(float2*)&Qs[(fr + 8) * 64 + kt * 16 + tg2 + 8];
        splitbf(x0.x * 0.125f, x0.y * 0.125f, qhi[kt][0], qlo[kt][0]);
        splitbf(x1.x * 0.125f, x1.y * 0.125f, qhi[kt][1], qlo[kt][1]);
        splitbf(x2.x * 0.125f, x2.y * 0.125f, qhi[kt][2], qlo[kt][2]);
        splitbf(x3.x * 0.125f, x3.y * 0.125f, qhi[kt][3], qlo[kt][3]);
    }
    __syncthreads();

    uint32_t smem_b = (uint32_t)__cvta_generic_to_shared(smu);
    int loK = (lane & 7) * KR_K + ((lane >> 3) & 1) * 4 + (lane >> 4) * 32;
    int loV = (lane & 7) * KR_V + ((lane >> 3) & 1) * 4 + (lane >> 4) * 64;

    int rK = tid >> 1, hK = (tid & 1) * 16;
    int rV = tid >> 2, qV = (tid & 3) * 16;
    const uint32_t* khB = khp + kvh * 32;
    const uint32_t* klB = klp + kvh * 32;
    const uint32_t* vhB = vhp + (size_t)(kvh * HD + rV) * (T_SEQ / 2);
    const uint32_t* vlB = vlp + (size_t)(kvh * HD + rV) * (T_SEQ / 2);

    int kbmax = qb;

    {
        uint32_t* Ks = smu;
        uint32_t* Vs = smu + KARR;
#pragma unroll
        for (int j = 0; j < 4; j++) {
            int c = hK + j * 4;
            cp16u(Ks + rK * KR_K + c,      khB + (size_t)rK * 128 + c);
            cp16u(Ks + rK * KR_K + 32 + c, klB + (size_t)rK * 128 + c);
        }
#pragma unroll
        for (int j = 0; j < 4; j++) {
            int c = qV + j * 4;
            cp16u(Vs + rV * KR_V + c,      vhB + c);
            cp16u(Vs + rV * KR_V + 64 + c, vlB + c);
        }
        asm volatile("cp.async.commit_group;");
    }

    float oacc[8][4];
#pragma unroll
    for (int nt = 0; nt < 8; nt++)
#pragma unroll
        for (int j = 0; j < 4; j++) oacc[nt][j] = 0.0f;
    float m0 = -1e30f, m1 = -1e30f, l0 = 0.0f, l1 = 0.0f;

    for (int kb = 0; kb <= kbmax; kb++) {
        asm volatile("cp.async.wait_group 0;");
        __syncthreads();

        if (kb < kbmax) {
            uint32_t* st = smu + ((kb + 1) & 1) * STAGE_U;
            uint32_t* Ks = st;
            uint32_t* Vs = st + KARR;
            int tk = (kb + 1) * 128;
            int tv = (kb + 1) * 64;
#pragma unroll
            for (int j = 0; j < 4; j++) {
                int c = hK + j * 4;
                cp16u(Ks + rK * KR_K + c,      khB + (size_t)(tk + rK) * 128 + c);
                cp16u(Ks + rK * KR_K + 32 + c, klB + (size_t)(tk + rK) * 128 + c);
            }
#pragma unroll
            for (int j = 0; j < 4; j++) {
                int c = qV + j * 4;
                cp16u(Vs + rV * KR_V + c,      vhB + tv + c);
                cp16u(Vs + rV * KR_V + 64 + c, vlB + tv + c);
            }
        }
        asm volatile("cp.async.commit_group;");

        uint32_t stK = smem_b + 4 * ((kb & 1) * STAGE_U + loK);
        uint32_t stV = smem_b + 4 * ((kb & 1) * STAGE_U + KARR + loV);

        float sacc[16][4];
#pragma unroll
        for (int nt = 0; nt < 16; nt++)
#pragma unroll
            for (int j = 0; j < 4; j++) sacc[nt][j] = 0.0f;

#pragma unroll
        for (int nt = 0; nt < 16; nt++) {
            uint32_t rowa = stK + nt * (8 * KR_K * 4);
#pragma unroll
            for (int ks = 0; ks < 4; ks++) {
                uint32_t bh0, bh1, bl0, bl1;
                ldsm_x4(bh0, bh1, bl0, bl1, rowa + ks * 32);
                uint32_t bh[2] = {bh0, bh1}, bl[2] = {bl0, bl1};
                mma_bf16(sacc[nt], qhi[ks], bh, sacc[nt]);
                mma_bf16(sacc[nt], qlo[ks], bh, sacc[nt]);
                mma_bf16(sacc[nt], qhi[ks], bl, sacc[nt]);
            }
        }

        if (kb == qb) {
            int grow0 = qb * 128 + fr;
            int grow1 = grow0 + 8;
#pragma unroll
            for (int nt = 0; nt < 16; nt++) {
                int gc = kb * 128 + nt * 8 + tg2;
                if (gc     > grow0) sacc[nt][0] = -1e30f;
                if (gc + 1 > grow0) sacc[nt][1] = -1e30f;
                if (gc     > grow1) sacc[nt][2] = -1e30f;
                if (gc + 1 > grow1) sacc[nt][3] = -1e30f;
            }
        }

        float mx0 = -1e30f, mx1 = -1e30f;
#pragma unroll
        for (int nt = 0; nt < 16; nt++) {
            mx0 = fmaxf(mx0, fmaxf(sacc[nt][0], sacc[nt][1]));
            mx1 = fmaxf(mx1, fmaxf(sacc[nt][2], sacc[nt][3]));
        }
        mx0 = fmaxf(mx0, __shfl_xor_sync(0xffffffffu, mx0, 1));
        mx0 = fmaxf(mx0, __shfl_xor_sync(0xffffffffu, mx0, 2));
        mx1 = fmaxf(mx1, __shfl_xor_sync(0xffffffffu, mx1, 1));
        mx1 = fmaxf(mx1, __shfl_xor_sync(0xffffffffu, mx1, 2));

        float mn0 = fmaxf(m0, mx0), mn1 = fmaxf(m1, mx1);
        float c0 = __expf(m0 - mn0), c1 = __expf(m1 - mn1);
        float rs0 = 0.0f, rs1 = 0.0f;
#pragma unroll
        for (int nt = 0; nt < 16; nt++) {
            float p0 = __expf(sacc[nt][0] - mn0);
            float p1 = __expf(sacc[nt][1] - mn0);
            float p2 = __expf(sacc[nt][2] - mn1);
            float p3 = __expf(sacc[nt][3] - mn1);
            sacc[nt][0] = p0; sacc[nt][1] = p1;
            sacc[nt][2] = p2; sacc[nt][3] = p3;
            rs0 += p0 + p1;
            rs1 += p2 + p3;
        }
        rs0 += __shfl_xor_sync(0xffffffffu, rs0, 1);
        rs0 += __shfl_xor_sync(0xffffffffu, rs0, 2);
        rs1 += __shfl_xor_sync(0xffffffffu, rs1, 1);
        rs1 += __shfl_xor_sync(0xffffffffu, rs1, 2);
        l0 = l0 * c0 + rs0;  m0 = mn0;
        l1 = l1 * c1 + rs1;  m1 = mn1;
#pragma unroll
        for (int nt = 0; nt < 8; nt++) {
            oacc[nt][0] *= c0; oacc[nt][1] *= c0;
            oacc[nt][2] *= c1; oacc[nt][3] *= c1;
        }

#pragma unroll
        for (int kt = 0; kt < 8; kt++) {
            uint32_t ahi[4], alo[4];
            splitbf(sacc[2*kt][0],     sacc[2*kt][1],     ahi[0], alo[0]);
            splitbf(sacc[2*kt][2],     sacc[2*kt][3],     ahi[1], alo[1]);
            splitbf(sacc[2*kt + 1][0], sacc[2*kt + 1][1], ahi[2], alo[2]);
            splitbf(sacc[2*kt + 1][2], sacc[2*kt + 1][3], ahi[3], alo[3]);
#pragma unroll
            for (int nt = 0; nt < 8; nt++) {
                uint32_t bh0, bh1, bl0, bl1;
                ldsm_x4(bh0, bh1, bl0, bl1,
                        stV + nt * (8 * KR_V * 4) + kt * 32);
                uint32_t bh[2] = {bh0, bh1}, bl[2] = {bl0, bl1};
                mma_bf16(oacc[nt], ahi, bh, oacc[nt]);
                mma_bf16(oacc[nt], alo, bh, oacc[nt]);
                mma_bf16(oacc[nt], ahi, bl, oacc[nt]);
            }
        }
    }

    float inv0 = 1.0f / l0, inv1 = 1.0f / l1;
#pragma unroll
    for (int nt = 0; nt < 8; nt++) {
        int col = h * HD + nt * 8 + tg2;
        float2 w0, w1;
        w0.x = roundtf(oacc[nt][0] * inv0); w0.y = roundtf(oacc[nt][1] * inv0);
        w1.x = roundtf(oacc[nt][2] * inv1); w1.y = roundtf(oacc[nt][3] * inv1);
        *(float2*)&op[(size_t)(qb * 128 + fr) * D_MODEL + col]     = w0;
        *(float2*)&op[(size_t)(qb * 128 + fr + 8) * D_MODEL + col] = w1;
    }
}

// ---------------- launch ---------------------------------------------------
extern "C" void kernel_launch(void* const* d_in, const int* in_sizes, int n_in,
                              void* d_out, int out_size)
{
    const float* X  = (const float*)d_in[0];
    const float* Wq = (const float*)d_in[1];
    const float* Wk = (const float*)d_in[2];
    const float* Wv = (const float*)d_in[3];
    const float* W1 = (const float*)d_in[4];
    const float* W2 = (const float*)d_in[5];
    float* out = (float*)d_out;

    float *gq, *gk, *gv, *ga, *gh;
    float *gxt, *gwqt, *gwkt, *gwvt, *gw1t, *gw2t;
    uint32_t *gkh, *gkl, *gvh, *gvl;
    cudaGetSymbolAddress((void**)&gq, g_q);
    cudaGetSymbolAddress((void**)&gk, g_k);
    cudaGetSymbolAddress((void**)&gv, g_v);
    cudaGetSymbolAddress((void**)&ga, g_attn);
    cudaGetSymbolAddress((void**)&gh, g_h1);
    cudaGetSymbolAddress((void**)&gxt, g_xt);
    cudaGetSymbolAddress((void**)&gwqt, g_wqt);
    cudaGetSymbolAddress((void**)&gwkt, g_wkt);
    cudaGetSymbolAddress((void**)&gwvt, g_wvt);
    cudaGetSymbolAddress((void**)&gw1t, g_w1t);
    cudaGetSymbolAddress((void**)&gw2t, g_w2t);
    cudaGetSymbolAddress((void**)&gkh, g_khp);
    cudaGetSymbolAddress((void**)&gkl, g_klp);
    cudaGetSymbolAddress((void**)&gvh, g_vhp);
    cudaGetSymbolAddress((void**)&gvl, g_vlp);

    cudaFuncSetAttribute(attn_bf16_kernel,
                         cudaFuncAttributeMaxDynamicSharedMemorySize, ATT_SMEM);
    cudaFuncSetAttribute(qkv_kernel,
                         cudaFuncAttributeMaxDynamicSharedMemorySize, GEMM_SMEM);
    cudaFuncSetAttribute(tgemm2_kernel<1, 1>,
                         cudaFuncAttributeMaxDynamicSharedMemorySize, GEMM_SMEM);
    cudaFuncSetAttribute(tgemm2_kernel<0, 0>,
                         cudaFuncAttributeMaxDynamicSharedMemorySize, GEMM_SMEM);

    round_all_kernel<<<13824, 256>>>(X, Wq, Wk, Wv, W1, W2);
    rope_table_kernel<<<T_SEQ, 32>>>();
    qkv_kernel<<<dim3(12, T_SEQ / 128), 256, GEMM_SMEM>>>(
        gxt, gwqt, gwkt, gwvt, gq, gk, gv);
    rope_apply_kernel<<<T_SEQ, NH * 32>>>(gq, NH);
    prep_kv_kernel<<<4096, 256>>>();
    attn_bf16_kernel<<<dim3(T_SEQ / 128, NH), 256, ATT_SMEM>>>(
        gq, gkh, gkl, gvh, gvl, ga);
    tgemm2_kernel<1, 1><<<dim3(D_FF / 128, T_SEQ / 128), 256, GEMM_SMEM>>>(
        ga, gw1t, gh, D_FF, D_MODEL);
    tgemm2_kernel<0, 0><<<dim3(D_MODEL / 128, T_SEQ / 128), 256, GEMM_SMEM>>>(
        gh, gw2t, out, D_MODEL, D_FF);
}